// round 1
// baseline (speedup 1.0000x reference)
#include <cuda_runtime.h>
#include <cstdint>

// Problem constants
#define T_DIM 1024
#define B_DIM 2
#define S_DIM 1024
#define G_DIM 4
#define D_DIM 1024
#define H_DIM 16
#define HD_DIM 64
#define BH_DIM 32
#define SCALING 0.125f  // 64^-0.5

// ---------------- scratch (no allocation allowed) ----------------
__device__ float g_qproj[2048 * 1024];                 // (t*B+b, D), already *SCALING
__device__ float g_kproj[2048 * 1024];                 // (s*B+b, D)
__device__ float g_vproj[2048 * 1024];                 // (s*B+b, D)
__device__ float g_qk[(size_t)BH_DIM * 1024 * 1024];   // (bh, t, s)
__device__ float g_attO[(size_t)4 * 1024 * 2 * 1024];  // ((g*T+t)*B+b, D)

// =====================================================================
// K1/K4: C[M,1024] = (A[M,1024] @ W[1024,1024]^T + bias) * scale
// 128x128 tile, BK=16, 256 threads, 8x8 per thread
// =====================================================================
__global__ __launch_bounds__(256) void sgemm_bias(
    const float* __restrict__ A, const float* __restrict__ W,
    const float* __restrict__ bias, float* __restrict__ C,
    int M, float scale)
{
    __shared__ __align__(16) float As[16][128];
    __shared__ __align__(16) float Ws[16][128];

    const int bm = blockIdx.y * 128;
    const int bn = blockIdx.x * 128;
    const int tid = threadIdx.x;
    const int tr = tid >> 4;          // 0..15
    const int tc = tid & 15;          // 0..15

    float acc[8][8];
#pragma unroll
    for (int i = 0; i < 8; i++)
#pragma unroll
        for (int j = 0; j < 8; j++) acc[i][j] = 0.f;

    for (int k0 = 0; k0 < 1024; k0 += 16) {
#pragma unroll
        for (int i = 0; i < 2; i++) {
            int r  = (tid >> 2) + i * 64;
            int c4 = (tid & 3) << 2;
            float4 a = *(const float4*)(A + (size_t)(bm + r) * 1024 + k0 + c4);
            As[c4 + 0][r] = a.x; As[c4 + 1][r] = a.y;
            As[c4 + 2][r] = a.z; As[c4 + 3][r] = a.w;
            float4 w = *(const float4*)(W + (size_t)(bn + r) * 1024 + k0 + c4);
            Ws[c4 + 0][r] = w.x; Ws[c4 + 1][r] = w.y;
            Ws[c4 + 2][r] = w.z; Ws[c4 + 3][r] = w.w;
        }
        __syncthreads();
#pragma unroll
        for (int kk = 0; kk < 16; kk++) {
            float4 a0 = *(const float4*)&As[kk][tr * 8];
            float4 a1 = *(const float4*)&As[kk][tr * 8 + 4];
            float4 w0 = *(const float4*)&Ws[kk][tc * 8];
            float4 w1 = *(const float4*)&Ws[kk][tc * 8 + 4];
            float ar[8] = {a0.x, a0.y, a0.z, a0.w, a1.x, a1.y, a1.z, a1.w};
            float wr[8] = {w0.x, w0.y, w0.z, w0.w, w1.x, w1.y, w1.z, w1.w};
#pragma unroll
            for (int i = 0; i < 8; i++)
#pragma unroll
                for (int j = 0; j < 8; j++) acc[i][j] += ar[i] * wr[j];
        }
        __syncthreads();
    }

#pragma unroll
    for (int i = 0; i < 8; i++) {
        size_t m = (size_t)(bm + tr * 8 + i);
#pragma unroll
        for (int j4 = 0; j4 < 8; j4 += 4) {
            int n = bn + tc * 8 + j4;
            float4 o;
            o.x = (acc[i][j4 + 0] + bias[n + 0]) * scale;
            o.y = (acc[i][j4 + 1] + bias[n + 1]) * scale;
            o.z = (acc[i][j4 + 2] + bias[n + 2]) * scale;
            o.w = (acc[i][j4 + 3] + bias[n + 3]) * scale;
            *(float4*)(C + m * 1024 + n) = o;
        }
    }
}

// =====================================================================
// K2: qk[bh,t,s] = sum_d q[bh,t,d] * k[bh,s,d]
// grid (S/64, T/64, BH), 256 threads, 4x4 per thread, K=64 in one shot
// =====================================================================
__global__ __launch_bounds__(256) void qk_kernel(
    const float* __restrict__ qp, const float* __restrict__ kp,
    float* __restrict__ qk)
{
    __shared__ __align__(16) float Qs[64][64];  // [k][t_row]
    __shared__ __align__(16) float Ks[64][64];  // [k][s_row]

    const int bh = blockIdx.z;
    const int b = bh >> 4, h = bh & 15;
    const int t0 = blockIdx.y * 64;
    const int s0 = blockIdx.x * 64;
    const int tid = threadIdx.x;

#pragma unroll
    for (int it = 0; it < 4; it++) {
        int vi = tid + it * 256;            // 0..1023 float4 slots
        int r  = vi >> 4;                   // 0..63
        int c4 = (vi & 15) << 2;            // 0..60
        float4 q = *(const float4*)(qp + (size_t)((t0 + r) * 2 + b) * 1024 + h * 64 + c4);
        Qs[c4 + 0][r] = q.x; Qs[c4 + 1][r] = q.y;
        Qs[c4 + 2][r] = q.z; Qs[c4 + 3][r] = q.w;
        float4 k = *(const float4*)(kp + (size_t)((s0 + r) * 2 + b) * 1024 + h * 64 + c4);
        Ks[c4 + 0][r] = k.x; Ks[c4 + 1][r] = k.y;
        Ks[c4 + 2][r] = k.z; Ks[c4 + 3][r] = k.w;
    }
    __syncthreads();

    const int tr = tid >> 4, tc = tid & 15;
    float acc[4][4];
#pragma unroll
    for (int i = 0; i < 4; i++)
#pragma unroll
        for (int j = 0; j < 4; j++) acc[i][j] = 0.f;

#pragma unroll 8
    for (int k = 0; k < 64; k++) {
        float4 a = *(const float4*)&Qs[k][tr * 4];
        float4 bb = *(const float4*)&Ks[k][tc * 4];
        float ar[4] = {a.x, a.y, a.z, a.w};
        float br[4] = {bb.x, bb.y, bb.z, bb.w};
#pragma unroll
        for (int i = 0; i < 4; i++)
#pragma unroll
            for (int j = 0; j < 4; j++) acc[i][j] += ar[i] * br[j];
    }

    const size_t base = ((size_t)bh << 20);
#pragma unroll
    for (int i = 0; i < 4; i++) {
        size_t o = base + (size_t)(t0 + tr * 4 + i) * 1024 + s0 + tc * 4;
        *(float4*)(qk + o) = make_float4(acc[i][0], acc[i][1], acc[i][2], acc[i][3]);
    }
}

// =====================================================================
// K3: fused softmax (4 groups) + prob write + PV
// grid (T/16, BH), 256 threads
// smem: Es[16][1024] + emsT[1024][4] + Vs[64][64] + rmax[16] + rZ[4][16]
// =====================================================================
#define K3_SMEM ((16 * 1024 + 1024 * 4 + 64 * 64 + 16 + 64) * 4)

__global__ __launch_bounds__(256) void softmax_pv_kernel(
    const float* __restrict__ qk, const float* __restrict__ vp,
    const float* __restrict__ gmask, const unsigned char* __restrict__ kpm,
    float* __restrict__ prob_out, float* __restrict__ attO)
{
    extern __shared__ __align__(16) float sm[];
    float* Es   = sm;                      // 16*1024
    float* emsT = Es + 16 * 1024;          // [s][g] 1024*4
    float* Vs   = emsT + 1024 * 4;         // 64*64
    float* rmax = Vs + 64 * 64;            // 16
    float* rZ   = rmax + 16;               // [g][row] 4*16

    const int tid = threadIdx.x;
    const int bh = blockIdx.y;
    const int b = bh >> 4, h = bh & 15;
    const int t0 = blockIdx.x * 16;

    // exp(group mask), zeroed where key is padded
    for (int idx = tid; idx < 4096; idx += 256) {
        int s = idx >> 2, g = idx & 3;
        float m = gmask[(size_t)((b * 4 + g) << 10) + s];
        float e = __expf(m);
        if (kpm[(b << 10) + s]) e = 0.f;
        emsT[s * 4 + g] = e;
    }

    // load qk tile (raw logits)
    const float* qkb = qk + ((size_t)bh << 20) + (size_t)t0 * 1024;
#pragma unroll
    for (int it = 0; it < 16; it++) {
        int idx = tid + it * 256;           // float4 index, 4096 total
        int r = idx >> 8, c = (idx & 255) << 2;
        *(float4*)(Es + r * 1024 + c) = *(const float4*)(qkb + (size_t)r * 1024 + c);
    }
    __syncthreads();

    const int rrow = tid >> 4, lane = tid & 15;

    // row max over s (groups shift only by exp(mask) factor, safe since E<=1)
    {
        float mx = -1e30f;
        const float* Er = Es + rrow * 1024 + lane * 64;
#pragma unroll 8
        for (int i = 0; i < 64; i++) mx = fmaxf(mx, Er[i]);
#pragma unroll
        for (int o = 8; o; o >>= 1) mx = fmaxf(mx, __shfl_xor_sync(0xffffffffu, mx, o));
        if (lane == 0) rmax[rrow] = mx;
    }
    __syncthreads();

    // E = exp(qk - rowmax)
    {
        float mx = rmax[rrow];
        float* Er = Es + rrow * 1024 + lane * 64;
#pragma unroll 8
        for (int i = 0; i < 64; i++) Er[i] = __expf(Er[i] - mx);
    }
    __syncthreads();

    // Z per group (4 at once via float4 over g)
    {
        const float* Er = Es + rrow * 1024 + lane * 64;
        float zx = 0.f, zy = 0.f, zz = 0.f, zw = 0.f;
#pragma unroll 8
        for (int i = 0; i < 64; i++) {
            float e = Er[i];
            float4 m = *(const float4*)(emsT + (lane * 64 + i) * 4);
            zx += e * m.x; zy += e * m.y; zz += e * m.z; zw += e * m.w;
        }
#pragma unroll
        for (int o = 8; o; o >>= 1) {
            zx += __shfl_xor_sync(0xffffffffu, zx, o);
            zy += __shfl_xor_sync(0xffffffffu, zy, o);
            zz += __shfl_xor_sync(0xffffffffu, zz, o);
            zw += __shfl_xor_sync(0xffffffffu, zw, o);
        }
        if (lane == 0) {
            rZ[0 * 16 + rrow] = 1.f / zx;
            rZ[1 * 16 + rrow] = 1.f / zy;
            rZ[2 * 16 + rrow] = 1.f / zz;
            rZ[3 * 16 + rrow] = 1.f / zw;
        }
    }
    __syncthreads();

    // write normalized probs to d_out:  ((bh*4+g)*1024 + t)*1024 + s
#pragma unroll
    for (int g = 0; g < 4; g++) {
        float* pout = prob_out + (((size_t)(bh * 4 + g) << 10) + t0) * 1024;
#pragma unroll
        for (int it = 0; it < 16; it++) {
            int idx = tid + it * 256;
            int r = idx >> 8, c = (idx & 255) << 2;
            float rz = rZ[g * 16 + r];
            const float* Er = Es + r * 1024 + c;
            float4 o;
            o.x = Er[0] * emsT[(c + 0) * 4 + g] * rz;
            o.y = Er[1] * emsT[(c + 1) * 4 + g] * rz;
            o.z = Er[2] * emsT[(c + 2) * 4 + g] * rz;
            o.w = Er[3] * emsT[(c + 3) * 4 + g] * rz;
            *(float4*)(pout + (size_t)r * 1024 + c) = o;
        }
    }

    // PV: acc[g][4] per thread (thread = (t row, 4-wide d group)), V in 64-row chunks
    const int dq = lane;  // d group
    float acc[4][4];
#pragma unroll
    for (int g = 0; g < 4; g++)
#pragma unroll
        for (int j = 0; j < 4; j++) acc[g][j] = 0.f;

    for (int sc = 0; sc < 16; sc++) {
        __syncthreads();
#pragma unroll
        for (int it = 0; it < 4; it++) {
            int vi = tid + it * 256;        // 1024 float4 slots
            int vr = vi >> 4;               // 0..63
            int c4 = (vi & 15) << 2;
            int s = sc * 64 + vr;
            *(float4*)(Vs + vr * 64 + c4) =
                *(const float4*)(vp + (size_t)(s * 2 + b) * 1024 + h * 64 + c4);
        }
        __syncthreads();
        const float* Erow = Es + rrow * 1024 + sc * 64;
        const float* emB = emsT + sc * 64 * 4;
#pragma unroll 4
        for (int s = 0; s < 64; s++) {
            float e = Erow[s];
            float4 m = *(const float4*)(emB + s * 4);
            float4 v = *(const float4*)(Vs + s * 64 + dq * 4);
            float p0 = e * m.x, p1 = e * m.y, p2 = e * m.z, p3 = e * m.w;
            acc[0][0] += p0 * v.x; acc[0][1] += p0 * v.y; acc[0][2] += p0 * v.z; acc[0][3] += p0 * v.w;
            acc[1][0] += p1 * v.x; acc[1][1] += p1 * v.y; acc[1][2] += p1 * v.z; acc[1][3] += p1 * v.w;
            acc[2][0] += p2 * v.x; acc[2][1] += p2 * v.y; acc[2][2] += p2 * v.z; acc[2][3] += p2 * v.w;
            acc[3][0] += p3 * v.x; acc[3][1] += p3 * v.y; acc[3][2] += p3 * v.z; acc[3][3] += p3 * v.w;
        }
    }

    // attO[((g*T + t)*B + b)*D + h*64 + d]
#pragma unroll
    for (int g = 0; g < 4; g++) {
        float rz = rZ[g * 16 + rrow];
        size_t row = ((size_t)g * 1024 + t0 + rrow) * 2 + b;
        float4 o = make_float4(acc[g][0] * rz, acc[g][1] * rz, acc[g][2] * rz, acc[g][3] * rz);
        *(float4*)(attO + (row << 10) + h * 64 + dq * 4) = o;
    }
}

// =====================================================================
extern "C" void kernel_launch(void* const* d_in, const int* in_sizes, int n_in,
                              void* d_out, int out_size)
{
    const float* query = (const float*)d_in[0];
    const float* key   = (const float*)d_in[1];
    const unsigned char* kpm = (const unsigned char*)d_in[2];
    const float* gmask = (const float*)d_in[3];
    const float* Wq = (const float*)d_in[4];
    const float* bq = (const float*)d_in[5];
    const float* Wk = (const float*)d_in[6];
    const float* bk = (const float*)d_in[7];
    const float* Wv = (const float*)d_in[8];
    const float* bv = (const float*)d_in[9];
    const float* Wo = (const float*)d_in[10];
    const float* bo = (const float*)d_in[11];

    float* out_proj = (float*)d_out;                              // (G,T,B,D) = 8388608
    float* prob_out = (float*)d_out + (size_t)4 * 1024 * 2 * 1024; // attn_prob

    float *qp, *kp, *vp, *qk, *attO;
    cudaGetSymbolAddress((void**)&qp,  g_qproj);
    cudaGetSymbolAddress((void**)&kp,  g_kproj);
    cudaGetSymbolAddress((void**)&vp,  g_vproj);
    cudaGetSymbolAddress((void**)&qk,  g_qk);
    cudaGetSymbolAddress((void**)&attO, g_attO);

    cudaFuncSetAttribute(softmax_pv_kernel,
                         cudaFuncAttributeMaxDynamicSharedMemorySize, K3_SMEM);

    // projections
    sgemm_bias<<<dim3(8, 16), 256>>>(query, Wq, bq, qp, 2048, SCALING);
    sgemm_bias<<<dim3(8, 16), 256>>>(key,   Wk, bk, kp, 2048, 1.0f);
    sgemm_bias<<<dim3(8, 16), 256>>>(key,   Wv, bv, vp, 2048, 1.0f);

    // logits
    qk_kernel<<<dim3(16, 16, 32), 256>>>(qp, kp, qk);

    // softmax + prob write + PV
    softmax_pv_kernel<<<dim3(64, 32), 256, K3_SMEM>>>(qk, vp, gmask, kpm,
                                                      prob_out, attO);

    // output projection
    sgemm_bias<<<dim3(8, 64), 256>>>(attO, Wo, bo, out_proj, 8192, 1.0f);
}

// round 3
// speedup vs baseline: 2.0978x; 2.0978x over previous
#include <cuda_runtime.h>
#include <cuda_bf16.h>
#include <cstdint>

#define SCALING 0.125f

// ---------------------------------------------------------------------------
// helpers
// ---------------------------------------------------------------------------
__device__ __forceinline__ uint32_t s2u(const void* p) {
    uint32_t a;
    asm("{ .reg .u64 t; cvta.to.shared.u64 t, %1; cvt.u32.u64 %0, t; }"
        : "=r"(a) : "l"(p));
    return a;
}
__device__ __forceinline__ uint32_t pk2(float a, float b) {
    __nv_bfloat162 t = __floats2bfloat162_rn(a, b);
    return reinterpret_cast<uint32_t&>(t);
}
__device__ __forceinline__ float bhi(float x) {
    return __bfloat162float(__float2bfloat16(x));
}
__device__ __forceinline__ void ldsm4(uint32_t* r, uint32_t addr) {
    asm volatile("ldmatrix.sync.aligned.m8n8.x4.shared.b16 {%0,%1,%2,%3}, [%4];"
        : "=r"(r[0]), "=r"(r[1]), "=r"(r[2]), "=r"(r[3]) : "r"(addr));
}
__device__ __forceinline__ void mma_bf16(float* c, const uint32_t* a, const uint32_t* b) {
    asm volatile(
        "mma.sync.aligned.m16n8k16.row.col.f32.bf16.bf16.f32 "
        "{%0,%1,%2,%3}, {%4,%5,%6,%7}, {%8,%9}, {%0,%1,%2,%3};"
        : "+f"(c[0]), "+f"(c[1]), "+f"(c[2]), "+f"(c[3])
        : "r"(a[0]), "r"(a[1]), "r"(a[2]), "r"(a[3]), "r"(b[0]), "r"(b[1]));
}
#define SWZ(x) ((x) ^ (((x) >> 3) & 0x70))

// ---------------------------------------------------------------------------
// Device scratch
// ---------------------------------------------------------------------------
__device__ __align__(16) __nv_bfloat16 g_qin_h[2048 * 1024], g_qin_l[2048 * 1024];
__device__ __align__(16) __nv_bfloat16 g_kin_h[2048 * 1024], g_kin_l[2048 * 1024];
__device__ __align__(16) __nv_bfloat16 g_wq_h[1024 * 1024], g_wq_l[1024 * 1024];
__device__ __align__(16) __nv_bfloat16 g_wk_h[1024 * 1024], g_wk_l[1024 * 1024];
__device__ __align__(16) __nv_bfloat16 g_wv_h[1024 * 1024], g_wv_l[1024 * 1024];
__device__ __align__(16) __nv_bfloat16 g_wo_h[1024 * 1024], g_wo_l[1024 * 1024];
__device__ __align__(16) __nv_bfloat16 g_qp_h[2048 * 1024], g_qp_l[2048 * 1024];
__device__ __align__(16) __nv_bfloat16 g_kp_h[2048 * 1024], g_kp_l[2048 * 1024];
__device__ __align__(16) float g_vp[2048 * 1024];
__device__ __align__(16) float g_qk[(size_t)32 * 1024 * 1024];
__device__ __align__(16) __nv_bfloat16 g_E_h[(size_t)32 * 1024 * 1024];
__device__ __align__(16) __nv_bfloat16 g_E_l[(size_t)32 * 1024 * 1024];
__device__ __align__(16) float g_rZ[32 * 4 * 1024];
__device__ __align__(16) __nv_bfloat16 g_vgt_h[32 * 256 * 1024], g_vgt_l[32 * 256 * 1024];
__device__ __align__(16) __nv_bfloat16 g_aO_h[8192 * 1024], g_aO_l[8192 * 1024];

// ---------------------------------------------------------------------------
// K0: fp32 -> bf16 hi/lo split
// ---------------------------------------------------------------------------
__global__ __launch_bounds__(256) void split_kernel(
    const float* __restrict__ x, __nv_bfloat16* __restrict__ h,
    __nv_bfloat16* __restrict__ l, int n4)
{
    int i = blockIdx.x * 256 + threadIdx.x;
    if (i >= n4) return;
    float4 v = ((const float4*)x)[i];
    float h0 = bhi(v.x), h1 = bhi(v.y), h2 = bhi(v.z), h3 = bhi(v.w);
    ((uint2*)h)[i] = make_uint2(pk2(h0, h1), pk2(h2, h3));
    ((uint2*)l)[i] = make_uint2(pk2(v.x - h0, v.y - h1), pk2(v.z - h2, v.w - h3));
}

// ---------------------------------------------------------------------------
// bf16x3 GEMM via mma.sync: C[128x128] = A @ B^T (A [M,K], B [N,K], K-major)
// MODE: 0 proj->bf16 split, 1 proj->fp32, 2 qk, 3 pv, 4 oproj
// smem: Ah 16K | Al 16K | Bh 16K | Bl 16K  = 64KB, SW128 swizzled 128B rows
// ---------------------------------------------------------------------------
#define GEMM_SMEM 65536

template <int MODE>
__global__ __launch_bounds__(256, 2) void gemm_k(
    const __nv_bfloat16* __restrict__ Ah, const __nv_bfloat16* __restrict__ Al,
    const __nv_bfloat16* __restrict__ Bh, const __nv_bfloat16* __restrict__ Bl,
    const float* __restrict__ bias, const float* __restrict__ rZ,
    float* __restrict__ Cf, __nv_bfloat16* __restrict__ Ch,
    __nv_bfloat16* __restrict__ Cl, float scale, int Kchunks)
{
    extern __shared__ __align__(1024) char smem[];
    const uint32_t sbase = s2u(smem);
    const int tid = threadIdx.x;
    const int wid = tid >> 5, lane = tid & 31;
    const int m0 = blockIdx.y * 128, n0 = blockIdx.x * 128;
    const int z = blockIdx.z;
    const int zb = z >> 4, zh = z & 15;

    size_t a_base, b_base;
    int a_str, b_str;
    if (MODE == 2) {
        a_base = (size_t)m0 * 2048 + zb * 1024 + zh * 64; a_str = 2048;
        b_base = (size_t)n0 * 2048 + zb * 1024 + zh * 64; b_str = 2048;
    } else if (MODE == 3) {
        a_base = ((size_t)z << 20) + (size_t)m0 * 1024; a_str = 1024;
        b_base = (size_t)z * 262144 + (size_t)n0 * 1024; b_str = 1024;
    } else {
        a_base = (size_t)m0 * 1024; a_str = 1024;
        b_base = (size_t)n0 * 1024; b_str = 1024;
    }

    const int wm = (wid >> 2) * 64;      // warp m offset (2 rows of warps)
    const int wn = (wid & 3) * 32;       // warp n offset (4 cols of warps)

    float acc[4][4][4];
#pragma unroll
    for (int i = 0; i < 4; i++)
#pragma unroll
        for (int j = 0; j < 4; j++)
#pragma unroll
            for (int e = 0; e < 4; e++) acc[i][j][e] = 0.f;

    // ldmatrix lane address components
    const int a_r = lane & 15;                 // A: row within 16
    const int a_kb = (lane >> 4) * 16;         // A: k-half byte offset
    const int b_r = (lane & 7) + ((lane >> 4) & 1) * 8;  // B: n row within 16
    const int b_kb = ((lane >> 3) & 1) * 16;   // B: k-half byte offset

    for (int kc = 0; kc < Kchunks; kc++) {
        const int k0 = kc * 64;
        // ---- load 4 tiles: each 128 rows x 64 bf16 (128B/row), swizzled ----
#pragma unroll
        for (int mat = 0; mat < 4; mat++) {
            const __nv_bfloat16* src = (mat == 0) ? Ah : (mat == 1) ? Al
                                     : (mat == 2) ? Bh : Bl;
            const size_t base = ((mat < 2) ? a_base : b_base) + k0;
            const int str = (mat < 2) ? a_str : b_str;
            char* dst = smem + mat * 16384;
#pragma unroll
            for (int it = 0; it < 4; it++) {
                int j = it * 256 + tid;
                int r = j >> 3, cB = (j & 7) * 16;
                uint4 v = *(const uint4*)(src + base + (size_t)r * str + (cB >> 1));
                *(uint4*)(dst + SWZ(r * 128 + cB)) = v;
            }
        }
        __syncthreads();

        // ---- 4 k-steps of 16 ----
#pragma unroll
        for (int ks = 0; ks < 4; ks++) {
            const int kbb = ks * 32;
            uint32_t ah[4][4], bb[2][4];
            // A-hi frags
#pragma unroll
            for (int mi = 0; mi < 4; mi++)
                ldsm4(ah[mi], sbase + SWZ((wm + 16 * mi + a_r) * 128 + kbb + a_kb));
            // B-hi frags (two x4 cover 4 n8 frags)
#pragma unroll
            for (int jj = 0; jj < 2; jj++)
                ldsm4(bb[jj], sbase + 32768 + SWZ((wn + 16 * jj + b_r) * 128 + kbb + b_kb));
#pragma unroll
            for (int mi = 0; mi < 4; mi++)
#pragma unroll
                for (int nj = 0; nj < 4; nj++)
                    mma_bf16(acc[mi][nj], ah[mi], &bb[nj >> 1][(nj & 1) * 2]);
            // B-lo frags, Ah x Bl
            uint32_t bl2[2][4];
#pragma unroll
            for (int jj = 0; jj < 2; jj++)
                ldsm4(bl2[jj], sbase + 49152 + SWZ((wn + 16 * jj + b_r) * 128 + kbb + b_kb));
#pragma unroll
            for (int mi = 0; mi < 4; mi++)
#pragma unroll
                for (int nj = 0; nj < 4; nj++)
                    mma_bf16(acc[mi][nj], ah[mi], &bl2[nj >> 1][(nj & 1) * 2]);
            // A-lo frags, Al x Bh
#pragma unroll
            for (int mi = 0; mi < 4; mi++) {
                uint32_t al[4];
                ldsm4(al, sbase + 16384 + SWZ((wm + 16 * mi + a_r) * 128 + kbb + a_kb));
#pragma unroll
                for (int nj = 0; nj < 4; nj++)
                    mma_bf16(acc[mi][nj], al, &bb[nj >> 1][(nj & 1) * 2]);
            }
        }
        __syncthreads();
    }

    // ---- epilogue straight from registers ----
    const int tr = lane >> 2, tc2 = (lane & 3) * 2;
#pragma unroll
    for (int mi = 0; mi < 4; mi++) {
#pragma unroll
        for (int nj = 0; nj < 4; nj++) {
            int n = n0 + wn + 8 * nj + tc2;
#pragma unroll
            for (int hr = 0; hr < 2; hr++) {
                int m = m0 + wm + 16 * mi + tr + hr * 8;
                float v0 = acc[mi][nj][hr * 2 + 0];
                float v1 = acc[mi][nj][hr * 2 + 1];
                if (MODE == 0) {
                    float y0 = (v0 + bias[n]) * scale, y1 = (v1 + bias[n + 1]) * scale;
                    float h0 = bhi(y0), h1 = bhi(y1);
                    size_t o = ((size_t)m * 1024 + n) >> 1;
                    ((uint32_t*)Ch)[o] = pk2(h0, h1);
                    ((uint32_t*)Cl)[o] = pk2(y0 - h0, y1 - h1);
                } else if (MODE == 1 || MODE == 4) {
                    float2 y = make_float2(v0 + bias[n], v1 + bias[n + 1]);
                    *(float2*)(Cf + (size_t)m * 1024 + n) = y;
                } else if (MODE == 2) {
                    *(float2*)(Cf + ((size_t)z << 20) + (size_t)m * 1024 + n) =
                        make_float2(v0, v1);
                } else {  // MODE 3
                    int g = n >> 6, d = n & 63;
                    float rz = rZ[z * 4096 + g * 1024 + m];
                    float y0 = v0 * rz, y1 = v1 * rz;
                    float h0 = bhi(y0), h1 = bhi(y1);
                    size_t o = ((((size_t)g * 1024 + m) * 2 + zb) * 1024 + zh * 64 + d) >> 1;
                    ((uint32_t*)Ch)[o] = pk2(h0, h1);
                    ((uint32_t*)Cl)[o] = pk2(y0 - h0, y1 - h1);
                }
            }
        }
    }
}

// ---------------------------------------------------------------------------
// K3: softmax — reads qk, writes prob (fp32, d_out), E hi/lo (bf16), 1/Z
// ---------------------------------------------------------------------------
#define SM3_BYTES ((16 * 1024 + 1024 * 4 + 16 + 64) * 4)

__global__ __launch_bounds__(256) void softmax_kernel(
    const float* __restrict__ qk, const float* __restrict__ gmask,
    const unsigned char* __restrict__ kpm, float* __restrict__ prob_out,
    __nv_bfloat16* __restrict__ Eh, __nv_bfloat16* __restrict__ El,
    float* __restrict__ rZg)
{
    extern __shared__ __align__(16) float sm[];
    float* Es   = sm;
    float* emsT = Es + 16 * 1024;
    float* rmax = emsT + 1024 * 4;
    float* rZ   = rmax + 16;

    const int tid = threadIdx.x;
    const int bh = blockIdx.y;
    const int b = bh >> 4;
    const int t0 = blockIdx.x * 16;

    for (int idx = tid; idx < 4096; idx += 256) {
        int s = idx >> 2, g = idx & 3;
        float e = __expf(gmask[(size_t)((b * 4 + g) << 10) + s]);
        if (kpm[(b << 10) + s]) e = 0.f;
        emsT[s * 4 + g] = e;
    }

    const float* qkb = qk + ((size_t)bh << 20) + (size_t)t0 * 1024;
#pragma unroll
    for (int it = 0; it < 16; it++) {
        int idx = tid + it * 256;
        int r = idx >> 8, c = (idx & 255) << 2;
        *(float4*)(Es + r * 1024 + c) = *(const float4*)(qkb + (size_t)r * 1024 + c);
    }
    __syncthreads();

    const int rrow = tid >> 4, lane = tid & 15;
    {
        float mx = -1e30f;
        const float* Er = Es + rrow * 1024 + lane * 64;
#pragma unroll 8
        for (int i = 0; i < 64; i++) mx = fmaxf(mx, Er[i]);
#pragma unroll
        for (int o = 8; o; o >>= 1) mx = fmaxf(mx, __shfl_xor_sync(0xffffffffu, mx, o));
        if (lane == 0) rmax[rrow] = mx;
    }
    __syncthreads();
    {
        float mx = rmax[rrow];
        float* Er = Es + rrow * 1024 + lane * 64;
#pragma unroll 8
        for (int i = 0; i < 64; i++) Er[i] = __expf(Er[i] - mx);
    }
    __syncthreads();
    {
        const float* Er = Es + rrow * 1024 + lane * 64;
        float zx = 0.f, zy = 0.f, zz = 0.f, zw = 0.f;
#pragma unroll 8
        for (int i = 0; i < 64; i++) {
            float e = Er[i];
            float4 m = *(const float4*)(emsT + (lane * 64 + i) * 4);
            zx += e * m.x; zy += e * m.y; zz += e * m.z; zw += e * m.w;
        }
#pragma unroll
        for (int o = 8; o; o >>= 1) {
            zx += __shfl_xor_sync(0xffffffffu, zx, o);
            zy += __shfl_xor_sync(0xffffffffu, zy, o);
            zz += __shfl_xor_sync(0xffffffffu, zz, o);
            zw += __shfl_xor_sync(0xffffffffu, zw, o);
        }
        if (lane == 0) {
            rZ[0 * 16 + rrow] = 1.f / zx;
            rZ[1 * 16 + rrow] = 1.f / zy;
            rZ[2 * 16 + rrow] = 1.f / zz;
            rZ[3 * 16 + rrow] = 1.f / zw;
            rZg[bh * 4096 + 0 * 1024 + t0 + rrow] = 1.f / zx;
            rZg[bh * 4096 + 1 * 1024 + t0 + rrow] = 1.f / zy;
            rZg[bh * 4096 + 2 * 1024 + t0 + rrow] = 1.f / zz;
            rZg[bh * 4096 + 3 * 1024 + t0 + rrow] = 1.f / zw;
        }
    }
    __syncthreads();

    const size_t ebase = ((size_t)bh << 20) + (size_t)t0 * 1024;
#pragma unroll
    for (int it = 0; it < 16; it++) {
        int idx = tid + it * 256;
        int r = idx >> 8, c = (idx & 255) << 2;
        float4 e4 = *(const float4*)(Es + r * 1024 + c);
        float h0 = bhi(e4.x), h1 = bhi(e4.y), h2 = bhi(e4.z), h3 = bhi(e4.w);
        size_t o = (ebase + (size_t)r * 1024 + c) >> 2;
        ((uint2*)Eh)[o] = make_uint2(pk2(h0, h1), pk2(h2, h3));
        ((uint2*)El)[o] = make_uint2(pk2(e4.x - h0, e4.y - h1), pk2(e4.z - h2, e4.w - h3));
    }

#pragma unroll
    for (int g = 0; g < 4; g++) {
        float* pout = prob_out + (((size_t)(bh * 4 + g) << 10) + t0) * 1024;
#pragma unroll
        for (int it = 0; it < 16; it++) {
            int idx = tid + it * 256;
            int r = idx >> 8, c = (idx & 255) << 2;
            float rz = rZ[g * 16 + r];
            const float* Er = Es + r * 1024 + c;
            float4 o;
            o.x = Er[0] * emsT[(c + 0) * 4 + g] * rz;
            o.y = Er[1] * emsT[(c + 1) * 4 + g] * rz;
            o.z = Er[2] * emsT[(c + 2) * 4 + g] * rz;
            o.w = Er[3] * emsT[(c + 3) * 4 + g] * rz;
            *(float4*)(pout + (size_t)r * 1024 + c) = o;
        }
    }
}

// ---------------------------------------------------------------------------
// K3b: vgt[bh][(g*64+d)][s] = exp(mask[b,g,s]) * V[s,b,h,d]   (hi/lo bf16)
// ---------------------------------------------------------------------------
__global__ __launch_bounds__(256) void build_vg(
    const float* __restrict__ vp, const float* __restrict__ gmask,
    const unsigned char* __restrict__ kpm,
    __nv_bfloat16* __restrict__ vgh, __nv_bfloat16* __restrict__ vgl)
{
    __shared__ float vsm[64][65];
    __shared__ float em[4][64];
    const int bh = blockIdx.y, b = bh >> 4, h = bh & 15;
    const int s0 = blockIdx.x * 64;
    const int tid = threadIdx.x;

#pragma unroll
    for (int it = 0; it < 4; it++) {
        int j = it * 256 + tid;
        int r = j >> 4, c4 = (j & 15) * 4;
        float4 v = *(const float4*)(vp + (size_t)((s0 + r) * 2 + b) * 1024 + h * 64 + c4);
        vsm[r][c4] = v.x; vsm[r][c4 + 1] = v.y; vsm[r][c4 + 2] = v.z; vsm[r][c4 + 3] = v.w;
    }
    {
        int g = tid >> 6, si = tid & 63;
        float e = __expf(gmask[(size_t)((b * 4 + g) << 10) + s0 + si]);
        if (kpm[(b << 10) + s0 + si]) e = 0.f;
        em[g][si] = e;
    }
    __syncthreads();

    const int w = tid >> 5, lane = tid & 31;
#pragma unroll 4
    for (int rr = 0; rr < 32; rr++) {
        int gd = rr * 8 + w;
        int g = gd >> 6, d = gd & 63;
        float v0 = em[g][lane * 2] * vsm[lane * 2][d];
        float v1 = em[g][lane * 2 + 1] * vsm[lane * 2 + 1][d];
        float h0 = bhi(v0), h1 = bhi(v1);
        size_t o = ((size_t)bh * 262144 + (size_t)gd * 1024 + s0 + lane * 2) >> 1;
        ((uint32_t*)vgh)[o] = pk2(h0, h1);
        ((uint32_t*)vgl)[o] = pk2(v0 - h0, v1 - h1);
    }
}

// ---------------------------------------------------------------------------
extern "C" void kernel_launch(void* const* d_in, const int* in_sizes, int n_in,
                              void* d_out, int out_size)
{
    const float* query = (const float*)d_in[0];
    const float* key   = (const float*)d_in[1];
    const unsigned char* kpm = (const unsigned char*)d_in[2];
    const float* gmask = (const float*)d_in[3];
    const float* Wq = (const float*)d_in[4];
    const float* bq = (const float*)d_in[5];
    const float* Wk = (const float*)d_in[6];
    const float* bk = (const float*)d_in[7];
    const float* Wv = (const float*)d_in[8];
    const float* bv = (const float*)d_in[9];
    const float* Wo = (const float*)d_in[10];
    const float* bo = (const float*)d_in[11];

    float* out_proj = (float*)d_out;
    float* prob_out = (float*)d_out + (size_t)4 * 1024 * 2 * 1024;

    __nv_bfloat16 *qin_h, *qin_l, *kin_h, *kin_l;
    __nv_bfloat16 *wq_h, *wq_l, *wk_h, *wk_l, *wv_h, *wv_l, *wo_h, *wo_l;
    __nv_bfloat16 *qp_h, *qp_l, *kp_h, *kp_l, *E_h, *E_l, *vgt_h, *vgt_l, *aO_h, *aO_l;
    float *vp, *qkbuf, *rZ;
    cudaGetSymbolAddress((void**)&qin_h, g_qin_h); cudaGetSymbolAddress((void**)&qin_l, g_qin_l);
    cudaGetSymbolAddress((void**)&kin_h, g_kin_h); cudaGetSymbolAddress((void**)&kin_l, g_kin_l);
    cudaGetSymbolAddress((void**)&wq_h, g_wq_h); cudaGetSymbolAddress((void**)&wq_l, g_wq_l);
    cudaGetSymbolAddress((void**)&wk_h, g_wk_h); cudaGetSymbolAddress((void**)&wk_l, g_wk_l);
    cudaGetSymbolAddress((void**)&wv_h, g_wv_h); cudaGetSymbolAddress((void**)&wv_l, g_wv_l);
    cudaGetSymbolAddress((void**)&wo_h, g_wo_h); cudaGetSymbolAddress((void**)&wo_l, g_wo_l);
    cudaGetSymbolAddress((void**)&qp_h, g_qp_h); cudaGetSymbolAddress((void**)&qp_l, g_qp_l);
    cudaGetSymbolAddress((void**)&kp_h, g_kp_h); cudaGetSymbolAddress((void**)&kp_l, g_kp_l);
    cudaGetSymbolAddress((void**)&vp, g_vp);
    cudaGetSymbolAddress((void**)&qkbuf, g_qk);
    cudaGetSymbolAddress((void**)&E_h, g_E_h); cudaGetSymbolAddress((void**)&E_l, g_E_l);
    cudaGetSymbolAddress((void**)&rZ, g_rZ);
    cudaGetSymbolAddress((void**)&vgt_h, g_vgt_h); cudaGetSymbolAddress((void**)&vgt_l, g_vgt_l);
    cudaGetSymbolAddress((void**)&aO_h, g_aO_h); cudaGetSymbolAddress((void**)&aO_l, g_aO_l);

    cudaFuncSetAttribute(gemm_k<0>, cudaFuncAttributeMaxDynamicSharedMemorySize, GEMM_SMEM);
    cudaFuncSetAttribute(gemm_k<1>, cudaFuncAttributeMaxDynamicSharedMemorySize, GEMM_SMEM);
    cudaFuncSetAttribute(gemm_k<2>, cudaFuncAttributeMaxDynamicSharedMemorySize, GEMM_SMEM);
    cudaFuncSetAttribute(gemm_k<3>, cudaFuncAttributeMaxDynamicSharedMemorySize, GEMM_SMEM);
    cudaFuncSetAttribute(gemm_k<4>, cudaFuncAttributeMaxDynamicSharedMemorySize, GEMM_SMEM);
    cudaFuncSetAttribute(softmax_kernel, cudaFuncAttributeMaxDynamicSharedMemorySize, SM3_BYTES);

    split_kernel<<<2048, 256>>>(query, qin_h, qin_l, 2048 * 1024 / 4);
    split_kernel<<<2048, 256>>>(key,   kin_h, kin_l, 2048 * 1024 / 4);
    split_kernel<<<1024, 256>>>(Wq, wq_h, wq_l, 1024 * 1024 / 4);
    split_kernel<<<1024, 256>>>(Wk, wk_h, wk_l, 1024 * 1024 / 4);
    split_kernel<<<1024, 256>>>(Wv, wv_h, wv_l, 1024 * 1024 / 4);
    split_kernel<<<1024, 256>>>(Wo, wo_h, wo_l, 1024 * 1024 / 4);

    gemm_k<0><<<dim3(8, 16, 1), 256, GEMM_SMEM>>>(qin_h, qin_l, wq_h, wq_l, bq,
        nullptr, nullptr, qp_h, qp_l, SCALING, 16);
    gemm_k<0><<<dim3(8, 16, 1), 256, GEMM_SMEM>>>(kin_h, kin_l, wk_h, wk_l, bk,
        nullptr, nullptr, kp_h, kp_l, 1.0f, 16);
    gemm_k<1><<<dim3(8, 16, 1), 256, GEMM_SMEM>>>(kin_h, kin_l, wv_h, wv_l, bv,
        nullptr, vp, nullptr, nullptr, 1.0f, 16);

    gemm_k<2><<<dim3(8, 8, 32), 256, GEMM_SMEM>>>(qp_h, qp_l, kp_h, kp_l, nullptr,
        nullptr, qkbuf, nullptr, nullptr, 1.0f, 1);

    softmax_kernel<<<dim3(64, 32), 256, SM3_BYTES>>>(qkbuf, gmask, kpm, prob_out,
                                                     E_h, E_l, rZ);
    build_vg<<<dim3(16, 32), 256>>>(vp, gmask, kpm, vgt_h, vgt_l);

    gemm_k<3><<<dim3(2, 8, 32), 256, GEMM_SMEM>>>(E_h, E_l, vgt_h, vgt_l, nullptr,
        rZ, nullptr, aO_h, aO_l, 1.0f, 16);

    gemm_k<4><<<dim3(8, 64, 1), 256, GEMM_SMEM>>>(aO_h, aO_l, wo_h, wo_l, bo,
        nullptr, out_proj, nullptr, nullptr, 1.0f, 16);
}

// round 4
// speedup vs baseline: 2.3223x; 1.1070x over previous
#include <cuda_runtime.h>
#include <cuda_bf16.h>
#include <cstdint>

#define SCALING 0.125f

// ---------------------------------------------------------------------------
// helpers
// ---------------------------------------------------------------------------
__device__ __forceinline__ uint32_t s2u(const void* p) {
    uint32_t a;
    asm("{ .reg .u64 t; cvta.to.shared.u64 t, %1; cvt.u32.u64 %0, t; }"
        : "=r"(a) : "l"(p));
    return a;
}
__device__ __forceinline__ uint32_t pk2(float a, float b) {
    __nv_bfloat162 t = __floats2bfloat162_rn(a, b);
    return reinterpret_cast<uint32_t&>(t);
}
__device__ __forceinline__ float bhi(float x) {
    return __bfloat162float(__float2bfloat16(x));
}
__device__ __forceinline__ void ldsm4(uint32_t* r, uint32_t addr) {
    asm volatile("ldmatrix.sync.aligned.m8n8.x4.shared.b16 {%0,%1,%2,%3}, [%4];"
        : "=r"(r[0]), "=r"(r[1]), "=r"(r[2]), "=r"(r[3]) : "r"(addr));
}
__device__ __forceinline__ void mma_bf16(float* c, const uint32_t* a, const uint32_t* b) {
    asm volatile(
        "mma.sync.aligned.m16n8k16.row.col.f32.bf16.bf16.f32 "
        "{%0,%1,%2,%3}, {%4,%5,%6,%7}, {%8,%9}, {%0,%1,%2,%3};"
        : "+f"(c[0]), "+f"(c[1]), "+f"(c[2]), "+f"(c[3])
        : "r"(a[0]), "r"(a[1]), "r"(a[2]), "r"(a[3]), "r"(b[0]), "r"(b[1]));
}
#define SWZ(x) ((x) ^ (((x) >> 3) & 0x70))

#define CP_ASYNC16(dst, src) \
    asm volatile("cp.async.cg.shared.global [%0], [%1], 16;" :: "r"(dst), "l"(src))
#define CP_COMMIT() asm volatile("cp.async.commit_group;")
#define CP_WAIT0()  asm volatile("cp.async.wait_group 0;")
#define CP_WAIT1()  asm volatile("cp.async.wait_group 1;")

// ---------------------------------------------------------------------------
// Device scratch
// ---------------------------------------------------------------------------
__device__ __align__(16) __nv_bfloat16 g_qin_h[2048 * 1024], g_qin_l[2048 * 1024];
__device__ __align__(16) __nv_bfloat16 g_kin_h[2048 * 1024], g_kin_l[2048 * 1024];
__device__ __align__(16) __nv_bfloat16 g_wq_h[1024 * 1024], g_wq_l[1024 * 1024];
__device__ __align__(16) __nv_bfloat16 g_wk_h[1024 * 1024], g_wk_l[1024 * 1024];
__device__ __align__(16) __nv_bfloat16 g_wv_h[1024 * 1024], g_wv_l[1024 * 1024];
__device__ __align__(16) __nv_bfloat16 g_wo_h[1024 * 1024], g_wo_l[1024 * 1024];
__device__ __align__(16) __nv_bfloat16 g_qp_h[2048 * 1024], g_qp_l[2048 * 1024];
__device__ __align__(16) __nv_bfloat16 g_kp_h[2048 * 1024], g_kp_l[2048 * 1024];
__device__ __align__(16) float g_vp[2048 * 1024];
__device__ __align__(16) float g_qk[(size_t)32 * 1024 * 1024];
__device__ __align__(16) __nv_bfloat16 g_E_h[(size_t)32 * 1024 * 1024];
__device__ __align__(16) __nv_bfloat16 g_E_l[(size_t)32 * 1024 * 1024];
__device__ __align__(16) float g_rZ[32 * 4 * 1024];
__device__ __align__(16) __nv_bfloat16 g_vgt_h[32 * 256 * 1024], g_vgt_l[32 * 256 * 1024];
__device__ __align__(16) __nv_bfloat16 g_aO_h[8192 * 1024], g_aO_l[8192 * 1024];

// ---------------------------------------------------------------------------
// K0: fused fp32 -> bf16 hi/lo split over all 6 tensors in one launch
// ---------------------------------------------------------------------------
struct SplitArgs {
    const float* src[6];
    __nv_bfloat16* h[6];
    __nv_bfloat16* l[6];
    int end[6];     // cumulative float4 counts
};

__global__ __launch_bounds__(256) void split_all_kernel(SplitArgs args)
{
    int i = blockIdx.x * 256 + threadIdx.x;
    int reg = 0;
#pragma unroll
    for (int r = 0; r < 5; r++) reg += (i >= args.end[r]) ? 1 : 0;
    int base = (reg == 0) ? 0 : args.end[reg - 1];
    int j = i - base;
    float4 v = ((const float4*)args.src[reg])[j];
    float h0 = bhi(v.x), h1 = bhi(v.y), h2 = bhi(v.z), h3 = bhi(v.w);
    ((uint2*)args.h[reg])[j] = make_uint2(pk2(h0, h1), pk2(h2, h3));
    ((uint2*)args.l[reg])[j] =
        make_uint2(pk2(v.x - h0, v.y - h1), pk2(v.z - h2, v.w - h3));
}

// ---------------------------------------------------------------------------
// bf16x3 GEMM via mma.sync, cp.async double-buffered
// C[128x128] = A @ B^T (A [M,K], B [N,K], K-major)
// MODE: 0 proj->bf16 split, 1 proj->fp32, 2 qk, 3 pv, 4 oproj
// smem: 2 stages x (Ah|Al|Bh|Bl 16K each) = 128KB
// ---------------------------------------------------------------------------
#define GEMM_SMEM (2 * 65536)

template <int MODE>
__global__ __launch_bounds__(256, 1) void gemm_k(
    const __nv_bfloat16* __restrict__ Ah, const __nv_bfloat16* __restrict__ Al,
    const __nv_bfloat16* __restrict__ Bh, const __nv_bfloat16* __restrict__ Bl,
    const float* __restrict__ bias, const float* __restrict__ rZ,
    float* __restrict__ Cf, __nv_bfloat16* __restrict__ Ch,
    __nv_bfloat16* __restrict__ Cl, float scale, int Kchunks)
{
    extern __shared__ __align__(1024) char smem[];
    const uint32_t sbase = s2u(smem);
    const int tid = threadIdx.x;
    const int wid = tid >> 5, lane = tid & 31;
    const int m0 = blockIdx.y * 128, n0 = blockIdx.x * 128;
    const int z = blockIdx.z;
    const int zb = z >> 4, zh = z & 15;

    size_t a_base, b_base;
    int a_str, b_str;
    if (MODE == 2) {
        a_base = (size_t)m0 * 2048 + zb * 1024 + zh * 64; a_str = 2048;
        b_base = (size_t)n0 * 2048 + zb * 1024 + zh * 64; b_str = 2048;
    } else if (MODE == 3) {
        a_base = ((size_t)z << 20) + (size_t)m0 * 1024; a_str = 1024;
        b_base = (size_t)z * 262144 + (size_t)n0 * 1024; b_str = 1024;
    } else {
        a_base = (size_t)m0 * 1024; a_str = 1024;
        b_base = (size_t)n0 * 1024; b_str = 1024;
    }

    const int wm = (wid >> 2) * 64;
    const int wn = (wid & 3) * 32;

    float acc[4][4][4];
#pragma unroll
    for (int i = 0; i < 4; i++)
#pragma unroll
        for (int j = 0; j < 4; j++)
#pragma unroll
            for (int e = 0; e < 4; e++) acc[i][j][e] = 0.f;

    const int a_r = lane & 15;
    const int a_kb = (lane >> 4) * 16;
    const int b_r = (lane & 7) + ((lane >> 4) & 1) * 8;
    const int b_kb = ((lane >> 3) & 1) * 16;

    // per-thread load coordinates (4 x cp.async 16B per tile)
    const int ld_r0 = tid >> 3;            // row 0..31 (+32*it)
    const int ld_cB = (tid & 7) * 16;      // byte col 0..112

    // issue async loads of chunk kc into stage st
    auto issue = [&](int kc, int st) {
        const int k0 = kc * 64;
#pragma unroll
        for (int mat = 0; mat < 4; mat++) {
            const __nv_bfloat16* src = (mat == 0) ? Ah : (mat == 1) ? Al
                                     : (mat == 2) ? Bh : Bl;
            const size_t base = ((mat < 2) ? a_base : b_base) + k0;
            const int str = (mat < 2) ? a_str : b_str;
            const uint32_t dstb = sbase + st * 65536 + mat * 16384;
#pragma unroll
            for (int it = 0; it < 4; it++) {
                int r = ld_r0 + it * 32;
                uint32_t d = dstb + SWZ(r * 128 + ld_cB);
                const __nv_bfloat16* s = src + base + (size_t)r * str + (ld_cB >> 1);
                CP_ASYNC16(d, s);
            }
        }
        CP_COMMIT();
    };

    issue(0, 0);

    for (int kc = 0; kc < Kchunks; kc++) {
        const int st = kc & 1;
        if (kc + 1 < Kchunks) {
            issue(kc + 1, st ^ 1);
            CP_WAIT1();
        } else {
            CP_WAIT0();
        }
        __syncthreads();

        const uint32_t sA  = sbase + st * 65536;
        const uint32_t sAl = sA + 16384;
        const uint32_t sB  = sA + 32768;
        const uint32_t sBl = sA + 49152;

#pragma unroll
        for (int ks = 0; ks < 4; ks++) {
            const int kbb = ks * 32;
            uint32_t ah[4][4], bb[2][4];
#pragma unroll
            for (int mi = 0; mi < 4; mi++)
                ldsm4(ah[mi], sA + SWZ((wm + 16 * mi + a_r) * 128 + kbb + a_kb));
#pragma unroll
            for (int jj = 0; jj < 2; jj++)
                ldsm4(bb[jj], sB + SWZ((wn + 16 * jj + b_r) * 128 + kbb + b_kb));
#pragma unroll
            for (int mi = 0; mi < 4; mi++)
#pragma unroll
                for (int nj = 0; nj < 4; nj++)
                    mma_bf16(acc[mi][nj], ah[mi], &bb[nj >> 1][(nj & 1) * 2]);
            uint32_t bl2[2][4];
#pragma unroll
            for (int jj = 0; jj < 2; jj++)
                ldsm4(bl2[jj], sBl + SWZ((wn + 16 * jj + b_r) * 128 + kbb + b_kb));
#pragma unroll
            for (int mi = 0; mi < 4; mi++)
#pragma unroll
                for (int nj = 0; nj < 4; nj++)
                    mma_bf16(acc[mi][nj], ah[mi], &bl2[nj >> 1][(nj & 1) * 2]);
#pragma unroll
            for (int mi = 0; mi < 4; mi++) {
                uint32_t al[4];
                ldsm4(al, sAl + SWZ((wm + 16 * mi + a_r) * 128 + kbb + a_kb));
#pragma unroll
                for (int nj = 0; nj < 4; nj++)
                    mma_bf16(acc[mi][nj], al, &bb[nj >> 1][(nj & 1) * 2]);
            }
        }
        __syncthreads();
    }

    // ---- epilogue straight from registers ----
    const int tr = lane >> 2, tc2 = (lane & 3) * 2;
#pragma unroll
    for (int mi = 0; mi < 4; mi++) {
#pragma unroll
        for (int nj = 0; nj < 4; nj++) {
            int n = n0 + wn + 8 * nj + tc2;
#pragma unroll
            for (int hr = 0; hr < 2; hr++) {
                int m = m0 + wm + 16 * mi + tr + hr * 8;
                float v0 = acc[mi][nj][hr * 2 + 0];
                float v1 = acc[mi][nj][hr * 2 + 1];
                if (MODE == 0) {
                    float y0 = (v0 + bias[n]) * scale, y1 = (v1 + bias[n + 1]) * scale;
                    float h0 = bhi(y0), h1 = bhi(y1);
                    size_t o = ((size_t)m * 1024 + n) >> 1;
                    ((uint32_t*)Ch)[o] = pk2(h0, h1);
                    ((uint32_t*)Cl)[o] = pk2(y0 - h0, y1 - h1);
                } else if (MODE == 1 || MODE == 4) {
                    float2 y = make_float2(v0 + bias[n], v1 + bias[n + 1]);
                    *(float2*)(Cf + (size_t)m * 1024 + n) = y;
                } else if (MODE == 2) {
                    *(float2*)(Cf + ((size_t)z << 20) + (size_t)m * 1024 + n) =
                        make_float2(v0, v1);
                } else {  // MODE 3
                    int g = n >> 6, d = n & 63;
                    float rz = rZ[z * 4096 + g * 1024 + m];
                    float y0 = v0 * rz, y1 = v1 * rz;
                    float h0 = bhi(y0), h1 = bhi(y1);
                    size_t o = ((((size_t)g * 1024 + m) * 2 + zb) * 1024 + zh * 64 + d) >> 1;
                    ((uint32_t*)Ch)[o] = pk2(h0, h1);
                    ((uint32_t*)Cl)[o] = pk2(y0 - h0, y1 - h1);
                }
            }
        }
    }
}

// ---------------------------------------------------------------------------
// K3: softmax — reads qk, writes prob (fp32, d_out), E hi/lo (bf16), 1/Z
// ---------------------------------------------------------------------------
#define SM3_BYTES ((16 * 1024 + 1024 * 4 + 16 + 64) * 4)

__global__ __launch_bounds__(256) void softmax_kernel(
    const float* __restrict__ qk, const float* __restrict__ gmask,
    const unsigned char* __restrict__ kpm, float* __restrict__ prob_out,
    __nv_bfloat16* __restrict__ Eh, __nv_bfloat16* __restrict__ El,
    float* __restrict__ rZg)
{
    extern __shared__ __align__(16) float sm[];
    float* Es   = sm;
    float* emsT = Es + 16 * 1024;
    float* rmax = emsT + 1024 * 4;
    float* rZ   = rmax + 16;

    const int tid = threadIdx.x;
    const int bh = blockIdx.y;
    const int b = bh >> 4;
    const int t0 = blockIdx.x * 16;

    for (int idx = tid; idx < 4096; idx += 256) {
        int s = idx >> 2, g = idx & 3;
        float e = __expf(gmask[(size_t)((b * 4 + g) << 10) + s]);
        if (kpm[(b << 10) + s]) e = 0.f;
        emsT[s * 4 + g] = e;
    }

    const float* qkb = qk + ((size_t)bh << 20) + (size_t)t0 * 1024;
#pragma unroll
    for (int it = 0; it < 16; it++) {
        int idx = tid + it * 256;
        int r = idx >> 8, c = (idx & 255) << 2;
        *(float4*)(Es + r * 1024 + c) = *(const float4*)(qkb + (size_t)r * 1024 + c);
    }
    __syncthreads();

    const int rrow = tid >> 4, lane = tid & 15;
    {
        float mx = -1e30f;
        const float* Er = Es + rrow * 1024 + lane * 64;
#pragma unroll 8
        for (int i = 0; i < 64; i++) mx = fmaxf(mx, Er[i]);
#pragma unroll
        for (int o = 8; o; o >>= 1) mx = fmaxf(mx, __shfl_xor_sync(0xffffffffu, mx, o));
        if (lane == 0) rmax[rrow] = mx;
    }
    __syncthreads();
    {
        float mx = rmax[rrow];
        float* Er = Es + rrow * 1024 + lane * 64;
#pragma unroll 8
        for (int i = 0; i < 64; i++) Er[i] = __expf(Er[i] - mx);
    }
    __syncthreads();
    {
        const float* Er = Es + rrow * 1024 + lane * 64;
        float zx = 0.f, zy = 0.f, zz = 0.f, zw = 0.f;
#pragma unroll 8
        for (int i = 0; i < 64; i++) {
            float e = Er[i];
            float4 m = *(const float4*)(emsT + (lane * 64 + i) * 4);
            zx += e * m.x; zy += e * m.y; zz += e * m.z; zw += e * m.w;
        }
#pragma unroll
        for (int o = 8; o; o >>= 1) {
            zx += __shfl_xor_sync(0xffffffffu, zx, o);
            zy += __shfl_xor_sync(0xffffffffu, zy, o);
            zz += __shfl_xor_sync(0xffffffffu, zz, o);
            zw += __shfl_xor_sync(0xffffffffu, zw, o);
        }
        if (lane == 0) {
            rZ[0 * 16 + rrow] = 1.f / zx;
            rZ[1 * 16 + rrow] = 1.f / zy;
            rZ[2 * 16 + rrow] = 1.f / zz;
            rZ[3 * 16 + rrow] = 1.f / zw;
            rZg[bh * 4096 + 0 * 1024 + t0 + rrow] = 1.f / zx;
            rZg[bh * 4096 + 1 * 1024 + t0 + rrow] = 1.f / zy;
            rZg[bh * 4096 + 2 * 1024 + t0 + rrow] = 1.f / zz;
            rZg[bh * 4096 + 3 * 1024 + t0 + rrow] = 1.f / zw;
        }
    }
    __syncthreads();

    const size_t ebase = ((size_t)bh << 20) + (size_t)t0 * 1024;
#pragma unroll
    for (int it = 0; it < 16; it++) {
        int idx = tid + it * 256;
        int r = idx >> 8, c = (idx & 255) << 2;
        float4 e4 = *(const float4*)(Es + r * 1024 + c);
        float h0 = bhi(e4.x), h1 = bhi(e4.y), h2 = bhi(e4.z), h3 = bhi(e4.w);
        size_t o = (ebase + (size_t)r * 1024 + c) >> 2;
        ((uint2*)Eh)[o] = make_uint2(pk2(h0, h1), pk2(h2, h3));
        ((uint2*)El)[o] = make_uint2(pk2(e4.x - h0, e4.y - h1), pk2(e4.z - h2, e4.w - h3));
    }

#pragma unroll
    for (int g = 0; g < 4; g++) {
        float* pout = prob_out + (((size_t)(bh * 4 + g) << 10) + t0) * 1024;
#pragma unroll
        for (int it = 0; it < 16; it++) {
            int idx = tid + it * 256;
            int r = idx >> 8, c = (idx & 255) << 2;
            float rz = rZ[g * 16 + r];
            const float* Er = Es + r * 1024 + c;
            float4 o;
            o.x = Er[0] * emsT[(c + 0) * 4 + g] * rz;
            o.y = Er[1] * emsT[(c + 1) * 4 + g] * rz;
            o.z = Er[2] * emsT[(c + 2) * 4 + g] * rz;
            o.w = Er[3] * emsT[(c + 3) * 4 + g] * rz;
            *(float4*)(pout + (size_t)r * 1024 + c) = o;
        }
    }
}

// ---------------------------------------------------------------------------
// K3b: vgt[bh][(g*64+d)][s] = exp(mask[b,g,s]) * V[s,b,h,d]   (hi/lo bf16)
// ---------------------------------------------------------------------------
__global__ __launch_bounds__(256) void build_vg(
    const float* __restrict__ vp, const float* __restrict__ gmask,
    const unsigned char* __restrict__ kpm,
    __nv_bfloat16* __restrict__ vgh, __nv_bfloat16* __restrict__ vgl)
{
    __shared__ float vsm[64][65];
    __shared__ float em[4][64];
    const int bh = blockIdx.y, b = bh >> 4, h = bh & 15;
    const int s0 = blockIdx.x * 64;
    const int tid = threadIdx.x;

#pragma unroll
    for (int it = 0; it < 4; it++) {
        int j = it * 256 + tid;
        int r = j >> 4, c4 = (j & 15) * 4;
        float4 v = *(const float4*)(vp + (size_t)((s0 + r) * 2 + b) * 1024 + h * 64 + c4);
        vsm[r][c4] = v.x; vsm[r][c4 + 1] = v.y; vsm[r][c4 + 2] = v.z; vsm[r][c4 + 3] = v.w;
    }
    {
        int g = tid >> 6, si = tid & 63;
        float e = __expf(gmask[(size_t)((b * 4 + g) << 10) + s0 + si]);
        if (kpm[(b << 10) + s0 + si]) e = 0.f;
        em[g][si] = e;
    }
    __syncthreads();

    const int w = tid >> 5, lane = tid & 31;
#pragma unroll 4
    for (int rr = 0; rr < 32; rr++) {
        int gd = rr * 8 + w;
        int g = gd >> 6, d = gd & 63;
        float v0 = em[g][lane * 2] * vsm[lane * 2][d];
        float v1 = em[g][lane * 2 + 1] * vsm[lane * 2 + 1][d];
        float h0 = bhi(v0), h1 = bhi(v1);
        size_t o = ((size_t)bh * 262144 + (size_t)gd * 1024 + s0 + lane * 2) >> 1;
        ((uint32_t*)vgh)[o] = pk2(h0, h1);
        ((uint32_t*)vgl)[o] = pk2(v0 - h0, v1 - h1);
    }
}

// ---------------------------------------------------------------------------
extern "C" void kernel_launch(void* const* d_in, const int* in_sizes, int n_in,
                              void* d_out, int out_size)
{
    const float* query = (const float*)d_in[0];
    const float* key   = (const float*)d_in[1];
    const unsigned char* kpm = (const unsigned char*)d_in[2];
    const float* gmask = (const float*)d_in[3];
    const float* Wq = (const float*)d_in[4];
    const float* bq = (const float*)d_in[5];
    const float* Wk = (const float*)d_in[6];
    const float* bk = (const float*)d_in[7];
    const float* Wv = (const float*)d_in[8];
    const float* bv = (const float*)d_in[9];
    const float* Wo = (const float*)d_in[10];
    const float* bo = (const float*)d_in[11];

    float* out_proj = (float*)d_out;
    float* prob_out = (float*)d_out + (size_t)4 * 1024 * 2 * 1024;

    __nv_bfloat16 *qin_h, *qin_l, *kin_h, *kin_l;
    __nv_bfloat16 *wq_h, *wq_l, *wk_h, *wk_l, *wv_h, *wv_l, *wo_h, *wo_l;
    __nv_bfloat16 *qp_h, *qp_l, *kp_h, *kp_l, *E_h, *E_l, *vgt_h, *vgt_l, *aO_h, *aO_l;
    float *vp, *qkbuf, *rZ;
    cudaGetSymbolAddress((void**)&qin_h, g_qin_h); cudaGetSymbolAddress((void**)&qin_l, g_qin_l);
    cudaGetSymbolAddress((void**)&kin_h, g_kin_h); cudaGetSymbolAddress((void**)&kin_l, g_kin_l);
    cudaGetSymbolAddress((void**)&wq_h, g_wq_h); cudaGetSymbolAddress((void**)&wq_l, g_wq_l);
    cudaGetSymbolAddress((void**)&wk_h, g_wk_h); cudaGetSymbolAddress((void**)&wk_l, g_wk_l);
    cudaGetSymbolAddress((void**)&wv_h, g_wv_h); cudaGetSymbolAddress((void**)&wv_l, g_wv_l);
    cudaGetSymbolAddress((void**)&wo_h, g_wo_h); cudaGetSymbolAddress((void**)&wo_l, g_wo_l);
    cudaGetSymbolAddress((void**)&qp_h, g_qp_h); cudaGetSymbolAddress((void**)&qp_l, g_qp_l);
    cudaGetSymbolAddress((void**)&kp_h, g_kp_h); cudaGetSymbolAddress((void**)&kp_l, g_kp_l);
    cudaGetSymbolAddress((void**)&vp, g_vp);
    cudaGetSymbolAddress((void**)&qkbuf, g_qk);
    cudaGetSymbolAddress((void**)&E_h, g_E_h); cudaGetSymbolAddress((void**)&E_l, g_E_l);
    cudaGetSymbolAddress((void**)&rZ, g_rZ);
    cudaGetSymbolAddress((void**)&vgt_h, g_vgt_h); cudaGetSymbolAddress((void**)&vgt_l, g_vgt_l);
    cudaGetSymbolAddress((void**)&aO_h, g_aO_h); cudaGetSymbolAddress((void**)&aO_l, g_aO_l);

    cudaFuncSetAttribute(gemm_k<0>, cudaFuncAttributeMaxDynamicSharedMemorySize, GEMM_SMEM);
    cudaFuncSetAttribute(gemm_k<1>, cudaFuncAttributeMaxDynamicSharedMemorySize, GEMM_SMEM);
    cudaFuncSetAttribute(gemm_k<2>, cudaFuncAttributeMaxDynamicSharedMemorySize, GEMM_SMEM);
    cudaFuncSetAttribute(gemm_k<3>, cudaFuncAttributeMaxDynamicSharedMemorySize, GEMM_SMEM);
    cudaFuncSetAttribute(gemm_k<4>, cudaFuncAttributeMaxDynamicSharedMemorySize, GEMM_SMEM);
    cudaFuncSetAttribute(softmax_kernel, cudaFuncAttributeMaxDynamicSharedMemorySize, SM3_BYTES);

    // fused splits: query(524288) key(524288) Wq..Wo(262144 each) float4s
    SplitArgs sa;
    sa.src[0] = query; sa.h[0] = qin_h; sa.l[0] = qin_l;
    sa.src[1] = key;   sa.h[1] = kin_h; sa.l[1] = kin_l;
    sa.src[2] = Wq;    sa.h[2] = wq_h;  sa.l[2] = wq_l;
    sa.src[3] = Wk;    sa.h[3] = wk_h;  sa.l[3] = wk_l;
    sa.src[4] = Wv;    sa.h[4] = wv_h;  sa.l[4] = wv_l;
    sa.src[5] = Wo;    sa.h[5] = wo_h;  sa.l[5] = wo_l;
    sa.end[0] = 524288; sa.end[1] = 1048576;
    sa.end[2] = 1310720; sa.end[3] = 1572864;
    sa.end[4] = 1835008; sa.end[5] = 2097152;
    split_all_kernel<<<2097152 / 256, 256>>>(sa);

    gemm_k<0><<<dim3(8, 16, 1), 256, GEMM_SMEM>>>(qin_h, qin_l, wq_h, wq_l, bq,
        nullptr, nullptr, qp_h, qp_l, SCALING, 16);
    gemm_k<0><<<dim3(8, 16, 1), 256, GEMM_SMEM>>>(kin_h, kin_l, wk_h, wk_l, bk,
        nullptr, nullptr, kp_h, kp_l, 1.0f, 16);
    gemm_k<1><<<dim3(8, 16, 1), 256, GEMM_SMEM>>>(kin_h, kin_l, wv_h, wv_l, bv,
        nullptr, vp, nullptr, nullptr, 1.0f, 16);

    gemm_k<2><<<dim3(8, 8, 32), 256, GEMM_SMEM>>>(qp_h, qp_l, kp_h, kp_l, nullptr,
        nullptr, qkbuf, nullptr, nullptr, 1.0f, 1);

    softmax_kernel<<<dim3(64, 32), 256, SM3_BYTES>>>(qkbuf, gmask, kpm, prob_out,
                                                     E_h, E_l, rZ);
    build_vg<<<dim3(16, 32), 256>>>(vp, gmask, kpm, vgt_h, vgt_l);

    gemm_k<3><<<dim3(2, 8, 32), 256, GEMM_SMEM>>>(E_h, E_l, vgt_h, vgt_l, nullptr,
        rZ, nullptr, aO_h, aO_l, 1.0f, 16);

    gemm_k<4><<<dim3(8, 64, 1), 256, GEMM_SMEM>>>(aO_h, aO_l, wo_h, wo_l, bo,
        nullptr, out_proj, nullptr, nullptr, 1.0f, 16);
}

// round 5
// speedup vs baseline: 2.3232x; 1.0004x over previous
#include <cuda_runtime.h>
#include <cuda_bf16.h>
#include <cstdint>

#define SCALING 0.125f

// ---------------------------------------------------------------------------
// helpers
// ---------------------------------------------------------------------------
__device__ __forceinline__ uint32_t s2u(const void* p) {
    uint32_t a;
    asm("{ .reg .u64 t; cvta.to.shared.u64 t, %1; cvt.u32.u64 %0, t; }"
        : "=r"(a) : "l"(p));
    return a;
}
__device__ __forceinline__ uint32_t pk2(float a, float b) {
    __nv_bfloat162 t = __floats2bfloat162_rn(a, b);
    return reinterpret_cast<uint32_t&>(t);
}
__device__ __forceinline__ float bhi(float x) {
    return __bfloat162float(__float2bfloat16(x));
}
__device__ __forceinline__ void ldsm4(uint32_t* r, uint32_t addr) {
    asm volatile("ldmatrix.sync.aligned.m8n8.x4.shared.b16 {%0,%1,%2,%3}, [%4];"
        : "=r"(r[0]), "=r"(r[1]), "=r"(r[2]), "=r"(r[3]) : "r"(addr));
}
__device__ __forceinline__ void mma_bf16(float* c, const uint32_t* a, const uint32_t* b) {
    asm volatile(
        "mma.sync.aligned.m16n8k16.row.col.f32.bf16.bf16.f32 "
        "{%0,%1,%2,%3}, {%4,%5,%6,%7}, {%8,%9}, {%0,%1,%2,%3};"
        : "+f"(c[0]), "+f"(c[1]), "+f"(c[2]), "+f"(c[3])
        : "r"(a[0]), "r"(a[1]), "r"(a[2]), "r"(a[3]), "r"(b[0]), "r"(b[1]));
}
#define SWZ(x) ((x) ^ (((x) >> 3) & 0x70))

#define CP_ASYNC16(dst, src) \
    asm volatile("cp.async.cg.shared.global [%0], [%1], 16;" :: "r"(dst), "l"(src))
#define CP_COMMIT() asm volatile("cp.async.commit_group;")
#define CP_WAIT0()  asm volatile("cp.async.wait_group 0;")
#define CP_WAIT1()  asm volatile("cp.async.wait_group 1;")

// ---------------------------------------------------------------------------
// Device scratch
// ---------------------------------------------------------------------------
__device__ __align__(16) __nv_bfloat16 g_qin_h[2048 * 1024], g_qin_l[2048 * 1024];
__device__ __align__(16) __nv_bfloat16 g_kin_h[2048 * 1024], g_kin_l[2048 * 1024];
__device__ __align__(16) __nv_bfloat16 g_wq_h[1024 * 1024], g_wq_l[1024 * 1024];
__device__ __align__(16) __nv_bfloat16 g_wk_h[1024 * 1024], g_wk_l[1024 * 1024];
__device__ __align__(16) __nv_bfloat16 g_wv_h[1024 * 1024], g_wv_l[1024 * 1024];
__device__ __align__(16) __nv_bfloat16 g_wo_h[1024 * 1024], g_wo_l[1024 * 1024];
__device__ __align__(16) __nv_bfloat16 g_qp_h[2048 * 1024], g_qp_l[2048 * 1024];
__device__ __align__(16) __nv_bfloat16 g_kp_h[2048 * 1024], g_kp_l[2048 * 1024];
__device__ __align__(16) float g_vp[2048 * 1024];
__device__ __align__(16) float g_qk[(size_t)32 * 1024 * 1024];
__device__ __align__(16) __nv_bfloat16 g_E_h[(size_t)32 * 1024 * 1024];
__device__ __align__(16) __nv_bfloat16 g_E_l[(size_t)32 * 1024 * 1024];
__device__ __align__(16) float g_rZ[32 * 4 * 1024];
__device__ __align__(16) __nv_bfloat16 g_vgt_h[32 * 256 * 1024], g_vgt_l[32 * 256 * 1024];
__device__ __align__(16) __nv_bfloat16 g_aO_h[8192 * 1024], g_aO_l[8192 * 1024];

// ---------------------------------------------------------------------------
// K0: fused fp32 -> bf16 hi/lo split over all 6 tensors in one launch
// ---------------------------------------------------------------------------
struct SplitArgs {
    const float* src[6];
    __nv_bfloat16* h[6];
    __nv_bfloat16* l[6];
    int end[6];
};

__global__ __launch_bounds__(256) void split_all_kernel(SplitArgs args)
{
    int i = blockIdx.x * 256 + threadIdx.x;
    int reg = 0;
#pragma unroll
    for (int r = 0; r < 5; r++) reg += (i >= args.end[r]) ? 1 : 0;
    int base = (reg == 0) ? 0 : args.end[reg - 1];
    int j = i - base;
    float4 v = ((const float4*)args.src[reg])[j];
    float h0 = bhi(v.x), h1 = bhi(v.y), h2 = bhi(v.z), h3 = bhi(v.w);
    ((uint2*)args.h[reg])[j] = make_uint2(pk2(h0, h1), pk2(h2, h3));
    ((uint2*)args.l[reg])[j] =
        make_uint2(pk2(v.x - h0, v.y - h1), pk2(v.z - h2, v.w - h3));
}

// ---------------------------------------------------------------------------
// GEMM core: bf16x3 mma.sync, cp.async double-buffered, BK=32
// smem stage (32KB): buf A = 128 rows x 128B [Ah(64B)|Al(64B)], buf B likewise
// 2 stages = 64KB -> 2 CTAs/SM
// ---------------------------------------------------------------------------
#define GEMM_SMEM 65536

__device__ __forceinline__ void gemm_core(
    const __nv_bfloat16* __restrict__ Ah, const __nv_bfloat16* __restrict__ Al,
    const __nv_bfloat16* __restrict__ Bh, const __nv_bfloat16* __restrict__ Bl,
    size_t a_base, int a_str, size_t b_base, int b_str,
    int Kchunks, uint32_t sbase, int tid, int wm, int wn,
    float acc[4][4][4])
{
    const int lane = tid & 31;
    const int a_r  = lane & 15;
    const int a_kb = (lane >> 4) * 16;
    const int b_r  = (lane & 7) + ((lane >> 4) & 1) * 8;
    const int b_kb = ((lane >> 3) & 1) * 16;

    // per-thread transfer coords: 8 x cp.async 16B per chunk
    const int jbuf = tid >> 2;           // unused placeholder (kept simple below)
    (void)jbuf;

#define ISSUE(kc, st) do {                                                     \
    const int _k0 = (kc) * 32;                                                 \
    _Pragma("unroll")                                                          \
    for (int it = 0; it < 8; it++) {                                           \
        int j = it * 256 + tid;                                                \
        int buf = j >> 10;                                                     \
        int r = (j >> 3) & 127;                                                \
        int ch = j & 7;                                                        \
        const __nv_bfloat16* src = buf ? (ch < 4 ? Bh : Bl)                    \
                                       : (ch < 4 ? Ah : Al);                   \
        size_t bs = buf ? b_base : a_base;                                     \
        int strd = buf ? b_str : a_str;                                        \
        uint32_t d = sbase + (st) * 32768 + buf * 16384 + SWZ(r * 128 + ch * 16);\
        CP_ASYNC16(d, src + bs + _k0 + (size_t)r * strd + (ch & 3) * 8);       \
    }                                                                          \
    CP_COMMIT();                                                               \
} while (0)

    ISSUE(0, 0);

    for (int kc = 0; kc < Kchunks; kc++) {
        const int st = kc & 1;
        if (kc + 1 < Kchunks) {
            ISSUE(kc + 1, st ^ 1);
            CP_WAIT1();
        } else {
            CP_WAIT0();
        }
        __syncthreads();

        const uint32_t sA = sbase + st * 32768;
        const uint32_t sB = sA + 16384;

#pragma unroll
        for (int ks = 0; ks < 2; ks++) {
            const int kbb = ks * 32;
            uint32_t ah[4][4], bb[2][4];
#pragma unroll
            for (int mi = 0; mi < 4; mi++)
                ldsm4(ah[mi], sA + SWZ((wm + 16 * mi + a_r) * 128 + kbb + a_kb));
#pragma unroll
            for (int jj = 0; jj < 2; jj++)
                ldsm4(bb[jj], sB + SWZ((wn + 16 * jj + b_r) * 128 + kbb + b_kb));
            // Ah x Bh
#pragma unroll
            for (int mi = 0; mi < 4; mi++)
#pragma unroll
                for (int nj = 0; nj < 4; nj++)
                    mma_bf16(acc[mi][nj], ah[mi], &bb[nj >> 1][(nj & 1) * 2]);
            // Al x Bh (al reused per mi)
#pragma unroll
            for (int mi = 0; mi < 4; mi++) {
                uint32_t al[4];
                ldsm4(al, sA + SWZ((wm + 16 * mi + a_r) * 128 + 64 + kbb + a_kb));
#pragma unroll
                for (int nj = 0; nj < 4; nj++)
                    mma_bf16(acc[mi][nj], al, &bb[nj >> 1][(nj & 1) * 2]);
            }
            // Bl overwrites bb, Ah x Bl
#pragma unroll
            for (int jj = 0; jj < 2; jj++)
                ldsm4(bb[jj], sB + SWZ((wn + 16 * jj + b_r) * 128 + 64 + kbb + b_kb));
#pragma unroll
            for (int mi = 0; mi < 4; mi++)
#pragma unroll
                for (int nj = 0; nj < 4; nj++)
                    mma_bf16(acc[mi][nj], ah[mi], &bb[nj >> 1][(nj & 1) * 2]);
        }
        __syncthreads();
    }
#undef ISSUE
}

// ---------------------------------------------------------------------------
// fused Q/K/V projection GEMM: z = 0:Q, 1:K, 2:V
// ---------------------------------------------------------------------------
struct QKVArgs {
    const __nv_bfloat16 *qh, *ql, *kh, *kl;
    const __nv_bfloat16 *wqh, *wql, *wkh, *wkl, *wvh, *wvl;
    const float *bq, *bk, *bv;
    __nv_bfloat16 *qph, *qpl, *kph, *kpl;
    float *vp;
};

__global__ __launch_bounds__(256, 2) void gemm_qkv(QKVArgs a)
{
    extern __shared__ __align__(1024) char smem[];
    const uint32_t sbase = s2u(smem);
    const int tid = threadIdx.x;
    const int wid = tid >> 5, lane = tid & 31;
    const int m0 = blockIdx.y * 128, n0 = blockIdx.x * 128;
    const int z = blockIdx.z;

    const __nv_bfloat16* Ah = (z == 0) ? a.qh : a.kh;
    const __nv_bfloat16* Al = (z == 0) ? a.ql : a.kl;
    const __nv_bfloat16* Bh = (z == 0) ? a.wqh : (z == 1) ? a.wkh : a.wvh;
    const __nv_bfloat16* Bl = (z == 0) ? a.wql : (z == 1) ? a.wkl : a.wvl;
    const float* bias = (z == 0) ? a.bq : (z == 1) ? a.bk : a.bv;
    const float scale = (z == 0) ? SCALING : 1.0f;

    const int wm = (wid >> 2) * 64, wn = (wid & 3) * 32;

    float acc[4][4][4];
#pragma unroll
    for (int i = 0; i < 4; i++)
#pragma unroll
        for (int j = 0; j < 4; j++)
#pragma unroll
            for (int e = 0; e < 4; e++) acc[i][j][e] = 0.f;

    gemm_core(Ah, Al, Bh, Bl, (size_t)m0 * 1024, 1024, (size_t)n0 * 1024, 1024,
              32, sbase, tid, wm, wn, acc);

    const int tr = lane >> 2, tc2 = (lane & 3) * 2;
#pragma unroll
    for (int mi = 0; mi < 4; mi++) {
#pragma unroll
        for (int nj = 0; nj < 4; nj++) {
            int n = n0 + wn + 8 * nj + tc2;
#pragma unroll
            for (int hr = 0; hr < 2; hr++) {
                int m = m0 + wm + 16 * mi + tr + hr * 8;
                float v0 = acc[mi][nj][hr * 2 + 0];
                float v1 = acc[mi][nj][hr * 2 + 1];
                if (z < 2) {
                    float y0 = (v0 + bias[n]) * scale, y1 = (v1 + bias[n + 1]) * scale;
                    float h0 = bhi(y0), h1 = bhi(y1);
                    size_t o = ((size_t)m * 1024 + n) >> 1;
                    __nv_bfloat16* Ch = (z == 0) ? a.qph : a.kph;
                    __nv_bfloat16* Cl = (z == 0) ? a.qpl : a.kpl;
                    ((uint32_t*)Ch)[o] = pk2(h0, h1);
                    ((uint32_t*)Cl)[o] = pk2(y0 - h0, y1 - h1);
                } else {
                    *(float2*)(a.vp + (size_t)m * 1024 + n) =
                        make_float2(v0 + bias[n], v1 + bias[n + 1]);
                }
            }
        }
    }
}

// ---------------------------------------------------------------------------
// generic GEMM: MODE 2 qk, 3 pv, 4 oproj
// ---------------------------------------------------------------------------
template <int MODE>
__global__ __launch_bounds__(256, 2) void gemm_k(
    const __nv_bfloat16* __restrict__ Ah, const __nv_bfloat16* __restrict__ Al,
    const __nv_bfloat16* __restrict__ Bh, const __nv_bfloat16* __restrict__ Bl,
    const float* __restrict__ bias, const float* __restrict__ rZ,
    float* __restrict__ Cf, __nv_bfloat16* __restrict__ Ch,
    __nv_bfloat16* __restrict__ Cl, int Kchunks)
{
    extern __shared__ __align__(1024) char smem[];
    const uint32_t sbase = s2u(smem);
    const int tid = threadIdx.x;
    const int wid = tid >> 5, lane = tid & 31;
    const int m0 = blockIdx.y * 128, n0 = blockIdx.x * 128;
    const int z = blockIdx.z;
    const int zb = z >> 4, zh = z & 15;

    size_t a_base, b_base;
    int a_str, b_str;
    if (MODE == 2) {
        a_base = (size_t)m0 * 2048 + zb * 1024 + zh * 64; a_str = 2048;
        b_base = (size_t)n0 * 2048 + zb * 1024 + zh * 64; b_str = 2048;
    } else if (MODE == 3) {
        a_base = ((size_t)z << 20) + (size_t)m0 * 1024; a_str = 1024;
        b_base = (size_t)z * 262144 + (size_t)n0 * 1024; b_str = 1024;
    } else {
        a_base = (size_t)m0 * 1024; a_str = 1024;
        b_base = (size_t)n0 * 1024; b_str = 1024;
    }

    const int wm = (wid >> 2) * 64, wn = (wid & 3) * 32;

    float acc[4][4][4];
#pragma unroll
    for (int i = 0; i < 4; i++)
#pragma unroll
        for (int j = 0; j < 4; j++)
#pragma unroll
            for (int e = 0; e < 4; e++) acc[i][j][e] = 0.f;

    gemm_core(Ah, Al, Bh, Bl, a_base, a_str, b_base, b_str,
              Kchunks, sbase, tid, wm, wn, acc);

    const int tr = lane >> 2, tc2 = (lane & 3) * 2;
#pragma unroll
    for (int mi = 0; mi < 4; mi++) {
#pragma unroll
        for (int nj = 0; nj < 4; nj++) {
            int n = n0 + wn + 8 * nj + tc2;
#pragma unroll
            for (int hr = 0; hr < 2; hr++) {
                int m = m0 + wm + 16 * mi + tr + hr * 8;
                float v0 = acc[mi][nj][hr * 2 + 0];
                float v1 = acc[mi][nj][hr * 2 + 1];
                if (MODE == 2) {
                    *(float2*)(Cf + ((size_t)z << 20) + (size_t)m * 1024 + n) =
                        make_float2(v0, v1);
                } else if (MODE == 3) {
                    int g = n >> 6, d = n & 63;
                    float rz = rZ[z * 4096 + g * 1024 + m];
                    float y0 = v0 * rz, y1 = v1 * rz;
                    float h0 = bhi(y0), h1 = bhi(y1);
                    size_t o = ((((size_t)g * 1024 + m) * 2 + zb) * 1024 + zh * 64 + d) >> 1;
                    ((uint32_t*)Ch)[o] = pk2(h0, h1);
                    ((uint32_t*)Cl)[o] = pk2(y0 - h0, y1 - h1);
                } else {
                    *(float2*)(Cf + (size_t)m * 1024 + n) =
                        make_float2(v0 + bias[n], v1 + bias[n + 1]);
                }
            }
        }
    }
}

// ---------------------------------------------------------------------------
// K3: softmax — reads qk, writes prob (fp32, d_out), E hi/lo (bf16), 1/Z
// ---------------------------------------------------------------------------
#define SM3_BYTES ((16 * 1024 + 1024 * 4 + 16 + 64) * 4)

__global__ __launch_bounds__(256) void softmax_kernel(
    const float* __restrict__ qk, const float* __restrict__ gmask,
    const unsigned char* __restrict__ kpm, float* __restrict__ prob_out,
    __nv_bfloat16* __restrict__ Eh, __nv_bfloat16* __restrict__ El,
    float* __restrict__ rZg)
{
    extern __shared__ __align__(16) float sm[];
    float* Es   = sm;
    float* emsT = Es + 16 * 1024;
    float* rmax = emsT + 1024 * 4;
    float* rZ   = rmax + 16;

    const int tid = threadIdx.x;
    const int bh = blockIdx.y;
    const int b = bh >> 4;
    const int t0 = blockIdx.x * 16;

    for (int idx = tid; idx < 4096; idx += 256) {
        int s = idx >> 2, g = idx & 3;
        float e = __expf(gmask[(size_t)((b * 4 + g) << 10) + s]);
        if (kpm[(b << 10) + s]) e = 0.f;
        emsT[s * 4 + g] = e;
    }

    const float* qkb = qk + ((size_t)bh << 20) + (size_t)t0 * 1024;
#pragma unroll
    for (int it = 0; it < 16; it++) {
        int idx = tid + it * 256;
        int r = idx >> 8, c = (idx & 255) << 2;
        *(float4*)(Es + r * 1024 + c) = *(const float4*)(qkb + (size_t)r * 1024 + c);
    }
    __syncthreads();

    const int rrow = tid >> 4, lane = tid & 15;
    {
        float mx = -1e30f;
        const float* Er = Es + rrow * 1024 + lane * 64;
#pragma unroll 8
        for (int i = 0; i < 64; i++) mx = fmaxf(mx, Er[i]);
#pragma unroll
        for (int o = 8; o; o >>= 1) mx = fmaxf(mx, __shfl_xor_sync(0xffffffffu, mx, o));
        if (lane == 0) rmax[rrow] = mx;
    }
    __syncthreads();
    {
        float mx = rmax[rrow];
        float* Er = Es + rrow * 1024 + lane * 64;
#pragma unroll 8
        for (int i = 0; i < 64; i++) Er[i] = __expf(Er[i] - mx);
    }
    __syncthreads();
    {
        const float* Er = Es + rrow * 1024 + lane * 64;
        float zx = 0.f, zy = 0.f, zz = 0.f, zw = 0.f;
#pragma unroll 8
        for (int i = 0; i < 64; i++) {
            float e = Er[i];
            float4 m = *(const float4*)(emsT + (lane * 64 + i) * 4);
            zx += e * m.x; zy += e * m.y; zz += e * m.z; zw += e * m.w;
        }
#pragma unroll
        for (int o = 8; o; o >>= 1) {
            zx += __shfl_xor_sync(0xffffffffu, zx, o);
            zy += __shfl_xor_sync(0xffffffffu, zy, o);
            zz += __shfl_xor_sync(0xffffffffu, zz, o);
            zw += __shfl_xor_sync(0xffffffffu, zw, o);
        }
        if (lane == 0) {
            rZ[0 * 16 + rrow] = 1.f / zx;
            rZ[1 * 16 + rrow] = 1.f / zy;
            rZ[2 * 16 + rrow] = 1.f / zz;
            rZ[3 * 16 + rrow] = 1.f / zw;
            rZg[bh * 4096 + 0 * 1024 + t0 + rrow] = 1.f / zx;
            rZg[bh * 4096 + 1 * 1024 + t0 + rrow] = 1.f / zy;
            rZg[bh * 4096 + 2 * 1024 + t0 + rrow] = 1.f / zz;
            rZg[bh * 4096 + 3 * 1024 + t0 + rrow] = 1.f / zw;
        }
    }
    __syncthreads();

    const size_t ebase = ((size_t)bh << 20) + (size_t)t0 * 1024;
#pragma unroll
    for (int it = 0; it < 16; it++) {
        int idx = tid + it * 256;
        int r = idx >> 8, c = (idx & 255) << 2;
        float4 e4 = *(const float4*)(Es + r * 1024 + c);
        float h0 = bhi(e4.x), h1 = bhi(e4.y), h2 = bhi(e4.z), h3 = bhi(e4.w);
        size_t o = (ebase + (size_t)r * 1024 + c) >> 2;
        ((uint2*)Eh)[o] = make_uint2(pk2(h0, h1), pk2(h2, h3));
        ((uint2*)El)[o] = make_uint2(pk2(e4.x - h0, e4.y - h1), pk2(e4.z - h2, e4.w - h3));
    }

#pragma unroll
    for (int g = 0; g < 4; g++) {
        float* pout = prob_out + (((size_t)(bh * 4 + g) << 10) + t0) * 1024;
#pragma unroll
        for (int it = 0; it < 16; it++) {
            int idx = tid + it * 256;
            int r = idx >> 8, c = (idx & 255) << 2;
            float rz = rZ[g * 16 + r];
            const float* Er = Es + r * 1024 + c;
            float4 o;
            o.x = Er[0] * emsT[(c + 0) * 4 + g] * rz;
            o.y = Er[1] * emsT[(c + 1) * 4 + g] * rz;
            o.z = Er[2] * emsT[(c + 2) * 4 + g] * rz;
            o.w = Er[3] * emsT[(c + 3) * 4 + g] * rz;
            *(float4*)(pout + (size_t)r * 1024 + c) = o;
        }
    }
}

// ---------------------------------------------------------------------------
// K3b: vgt[bh][(g*64+d)][s] = exp(mask[b,g,s]) * V[s,b,h,d]   (hi/lo bf16)
// ---------------------------------------------------------------------------
__global__ __launch_bounds__(256) void build_vg(
    const float* __restrict__ vp, const float* __restrict__ gmask,
    const unsigned char* __restrict__ kpm,
    __nv_bfloat16* __restrict__ vgh, __nv_bfloat16* __restrict__ vgl)
{
    __shared__ float vsm[64][65];
    __shared__ float em[4][64];
    const int bh = blockIdx.y, b = bh >> 4, h = bh & 15;
    const int s0 = blockIdx.x * 64;
    const int tid = threadIdx.x;

#pragma unroll
    for (int it = 0; it < 4; it++) {
        int j = it * 256 + tid;
        int r = j >> 4, c4 = (j & 15) * 4;
        float4 v = *(const float4*)(vp + (size_t)((s0 + r) * 2 + b) * 1024 + h * 64 + c4);
        vsm[r][c4] = v.x; vsm[r][c4 + 1] = v.y; vsm[r][c4 + 2] = v.z; vsm[r][c4 + 3] = v.w;
    }
    {
        int g = tid >> 6, si = tid & 63;
        float e = __expf(gmask[(size_t)((b * 4 + g) << 10) + s0 + si]);
        if (kpm[(b << 10) + s0 + si]) e = 0.f;
        em[g][si] = e;
    }
    __syncthreads();

    const int w = tid >> 5, lane = tid & 31;
#pragma unroll 4
    for (int rr = 0; rr < 32; rr++) {
        int gd = rr * 8 + w;
        int g = gd >> 6, d = gd & 63;
        float v0 = em[g][lane * 2] * vsm[lane * 2][d];
        float v1 = em[g][lane * 2 + 1] * vsm[lane * 2 + 1][d];
        float h0 = bhi(v0), h1 = bhi(v1);
        size_t o = ((size_t)bh * 262144 + (size_t)gd * 1024 + s0 + lane * 2) >> 1;
        ((uint32_t*)vgh)[o] = pk2(h0, h1);
        ((uint32_t*)vgl)[o] = pk2(v0 - h0, v1 - h1);
    }
}

// ---------------------------------------------------------------------------
extern "C" void kernel_launch(void* const* d_in, const int* in_sizes, int n_in,
                              void* d_out, int out_size)
{
    const float* query = (const float*)d_in[0];
    const float* key   = (const float*)d_in[1];
    const unsigned char* kpm = (const unsigned char*)d_in[2];
    const float* gmask = (const float*)d_in[3];
    const float* Wq = (const float*)d_in[4];
    const float* bq = (const float*)d_in[5];
    const float* Wk = (const float*)d_in[6];
    const float* bk = (const float*)d_in[7];
    const float* Wv = (const float*)d_in[8];
    const float* bv = (const float*)d_in[9];
    const float* Wo = (const float*)d_in[10];
    const float* bo = (const float*)d_in[11];

    float* out_proj = (float*)d_out;
    float* prob_out = (float*)d_out + (size_t)4 * 1024 * 2 * 1024;

    __nv_bfloat16 *qin_h, *qin_l, *kin_h, *kin_l;
    __nv_bfloat16 *wq_h, *wq_l, *wk_h, *wk_l, *wv_h, *wv_l, *wo_h, *wo_l;
    __nv_bfloat16 *qp_h, *qp_l, *kp_h, *kp_l, *E_h, *E_l, *vgt_h, *vgt_l, *aO_h, *aO_l;
    float *vp, *qkbuf, *rZ;
    cudaGetSymbolAddress((void**)&qin_h, g_qin_h); cudaGetSymbolAddress((void**)&qin_l, g_qin_l);
    cudaGetSymbolAddress((void**)&kin_h, g_kin_h); cudaGetSymbolAddress((void**)&kin_l, g_kin_l);
    cudaGetSymbolAddress((void**)&wq_h, g_wq_h); cudaGetSymbolAddress((void**)&wq_l, g_wq_l);
    cudaGetSymbolAddress((void**)&wk_h, g_wk_h); cudaGetSymbolAddress((void**)&wk_l, g_wk_l);
    cudaGetSymbolAddress((void**)&wv_h, g_wv_h); cudaGetSymbolAddress((void**)&wv_l, g_wv_l);
    cudaGetSymbolAddress((void**)&wo_h, g_wo_h); cudaGetSymbolAddress((void**)&wo_l, g_wo_l);
    cudaGetSymbolAddress((void**)&qp_h, g_qp_h); cudaGetSymbolAddress((void**)&qp_l, g_qp_l);
    cudaGetSymbolAddress((void**)&kp_h, g_kp_h); cudaGetSymbolAddress((void**)&kp_l, g_kp_l);
    cudaGetSymbolAddress((void**)&vp, g_vp);
    cudaGetSymbolAddress((void**)&qkbuf, g_qk);
    cudaGetSymbolAddress((void**)&E_h, g_E_h); cudaGetSymbolAddress((void**)&E_l, g_E_l);
    cudaGetSymbolAddress((void**)&rZ, g_rZ);
    cudaGetSymbolAddress((void**)&vgt_h, g_vgt_h); cudaGetSymbolAddress((void**)&vgt_l, g_vgt_l);
    cudaGetSymbolAddress((void**)&aO_h, g_aO_h); cudaGetSymbolAddress((void**)&aO_l, g_aO_l);

    cudaFuncSetAttribute(gemm_qkv, cudaFuncAttributeMaxDynamicSharedMemorySize, GEMM_SMEM);
    cudaFuncSetAttribute(gemm_k<2>, cudaFuncAttributeMaxDynamicSharedMemorySize, GEMM_SMEM);
    cudaFuncSetAttribute(gemm_k<3>, cudaFuncAttributeMaxDynamicSharedMemorySize, GEMM_SMEM);
    cudaFuncSetAttribute(gemm_k<4>, cudaFuncAttributeMaxDynamicSharedMemorySize, GEMM_SMEM);
    cudaFuncSetAttribute(softmax_kernel, cudaFuncAttributeMaxDynamicSharedMemorySize, SM3_BYTES);

    SplitArgs sa;
    sa.src[0] = query; sa.h[0] = qin_h; sa.l[0] = qin_l;
    sa.src[1] = key;   sa.h[1] = kin_h; sa.l[1] = kin_l;
    sa.src[2] = Wq;    sa.h[2] = wq_h;  sa.l[2] = wq_l;
    sa.src[3] = Wk;    sa.h[3] = wk_h;  sa.l[3] = wk_l;
    sa.src[4] = Wv;    sa.h[4] = wv_h;  sa.l[4] = wv_l;
    sa.src[5] = Wo;    sa.h[5] = wo_h;  sa.l[5] = wo_l;
    sa.end[0] = 524288; sa.end[1] = 1048576;
    sa.end[2] = 1310720; sa.end[3] = 1572864;
    sa.end[4] = 1835008; sa.end[5] = 2097152;
    split_all_kernel<<<2097152 / 256, 256>>>(sa);

    QKVArgs qa;
    qa.qh = qin_h; qa.ql = qin_l; qa.kh = kin_h; qa.kl = kin_l;
    qa.wqh = wq_h; qa.wql = wq_l; qa.wkh = wk_h; qa.wkl = wk_l;
    qa.wvh = wv_h; qa.wvl = wv_l;
    qa.bq = bq; qa.bk = bk; qa.bv = bv;
    qa.qph = qp_h; qa.qpl = qp_l; qa.kph = kp_h; qa.kpl = kp_l;
    qa.vp = vp;
    gemm_qkv<<<dim3(8, 16, 3), 256, GEMM_SMEM>>>(qa);

    gemm_k<2><<<dim3(8, 8, 32), 256, GEMM_SMEM>>>(qp_h, qp_l, kp_h, kp_l, nullptr,
        nullptr, qkbuf, nullptr, nullptr, 2);

    softmax_kernel<<<dim3(64, 32), 256, SM3_BYTES>>>(qkbuf, gmask, kpm, prob_out,
                                                     E_h, E_l, rZ);
    build_vg<<<dim3(16, 32), 256>>>(vp, gmask, kpm, vgt_h, vgt_l);

    gemm_k<3><<<dim3(2, 8, 32), 256, GEMM_SMEM>>>(E_h, E_l, vgt_h, vgt_l, nullptr,
        rZ, nullptr, aO_h, aO_l, 32);

    gemm_k<4><<<dim3(8, 64, 1), 256, GEMM_SMEM>>>(aO_h, aO_l, wo_h, wo_l, bo,
        nullptr, out_proj, nullptr, nullptr, 32);
}

// round 6
// speedup vs baseline: 3.0502x; 1.3129x over previous
#include <cuda_runtime.h>
#include <cuda_bf16.h>
#include <cstdint>

#define SCALING 0.125f

// ---------------------------------------------------------------------------
// helpers
// ---------------------------------------------------------------------------
__device__ __forceinline__ uint32_t s2u(const void* p) {
    uint32_t a;
    asm("{ .reg .u64 t; cvta.to.shared.u64 t, %1; cvt.u32.u64 %0, t; }"
        : "=r"(a) : "l"(p));
    return a;
}
__device__ __forceinline__ uint32_t pk2(float a, float b) {
    __nv_bfloat162 t = __floats2bfloat162_rn(a, b);
    return reinterpret_cast<uint32_t&>(t);
}
__device__ __forceinline__ float bhi(float x) {
    return __bfloat162float(__float2bfloat16(x));
}
__device__ __forceinline__ void ldsm4(uint32_t* r, uint32_t addr) {
    asm volatile("ldmatrix.sync.aligned.m8n8.x4.shared.b16 {%0,%1,%2,%3}, [%4];"
        : "=r"(r[0]), "=r"(r[1]), "=r"(r[2]), "=r"(r[3]) : "r"(addr));
}
__device__ __forceinline__ void mma_bf16(float* c, const uint32_t* a, const uint32_t* b) {
    asm volatile(
        "mma.sync.aligned.m16n8k16.row.col.f32.bf16.bf16.f32 "
        "{%0,%1,%2,%3}, {%4,%5,%6,%7}, {%8,%9}, {%0,%1,%2,%3};"
        : "+f"(c[0]), "+f"(c[1]), "+f"(c[2]), "+f"(c[3])
        : "r"(a[0]), "r"(a[1]), "r"(a[2]), "r"(a[3]), "r"(b[0]), "r"(b[1]));
}
#define SWZ(x) ((x) ^ (((x) >> 3) & 0x70))

#define CP_ASYNC16(dst, src) \
    asm volatile("cp.async.cg.shared.global [%0], [%1], 16;" :: "r"(dst), "l"(src))
#define CP_COMMIT() asm volatile("cp.async.commit_group;")
#define CP_WAIT0()  asm volatile("cp.async.wait_group 0;")
#define CP_WAIT1()  asm volatile("cp.async.wait_group 1;")
#define CP_WAIT2()  asm volatile("cp.async.wait_group 2;")

// ---------------------------------------------------------------------------
// Device scratch
// ---------------------------------------------------------------------------
__device__ __align__(16) __nv_bfloat16 g_qin_h[2048 * 1024], g_qin_l[2048 * 1024];
__device__ __align__(16) __nv_bfloat16 g_kin_h[2048 * 1024], g_kin_l[2048 * 1024];
__device__ __align__(16) __nv_bfloat16 g_wq_h[1024 * 1024], g_wq_l[1024 * 1024];
__device__ __align__(16) __nv_bfloat16 g_wk_h[1024 * 1024], g_wk_l[1024 * 1024];
__device__ __align__(16) __nv_bfloat16 g_wv_h[1024 * 1024], g_wv_l[1024 * 1024];
__device__ __align__(16) __nv_bfloat16 g_wo_h[1024 * 1024], g_wo_l[1024 * 1024];
__device__ __align__(16) __nv_bfloat16 g_qp_h[2048 * 1024], g_qp_l[2048 * 1024];
__device__ __align__(16) __nv_bfloat16 g_kp_h[2048 * 1024], g_kp_l[2048 * 1024];
__device__ __align__(16) float g_vp[2048 * 1024];
__device__ __align__(16) float g_qk[(size_t)32 * 1024 * 1024];
__device__ __align__(16) __nv_bfloat16 g_E_h[(size_t)32 * 1024 * 1024];
__device__ __align__(16) __nv_bfloat16 g_E_l[(size_t)32 * 1024 * 1024];
__device__ __align__(16) float g_rZ[32 * 4 * 1024];
__device__ __align__(16) float g_emg[2 * 4 * 1024];
__device__ __align__(16) __nv_bfloat16 g_vgt_h[32 * 256 * 1024], g_vgt_l[32 * 256 * 1024];
__device__ __align__(16) __nv_bfloat16 g_aO_h[8192 * 1024], g_aO_l[8192 * 1024];

// ---------------------------------------------------------------------------
// K0: fused fp32 -> bf16 hi/lo split over all 6 tensors in one launch
// ---------------------------------------------------------------------------
struct SplitArgs {
    const float* src[6];
    __nv_bfloat16* h[6];
    __nv_bfloat16* l[6];
    int end[6];
};

__global__ __launch_bounds__(256) void split_all_kernel(SplitArgs args)
{
    int i = blockIdx.x * 256 + threadIdx.x;
    int reg = 0;
#pragma unroll
    for (int r = 0; r < 5; r++) reg += (i >= args.end[r]) ? 1 : 0;
    int base = (reg == 0) ? 0 : args.end[reg - 1];
    int j = i - base;
    float4 v = ((const float4*)args.src[reg])[j];
    float h0 = bhi(v.x), h1 = bhi(v.y), h2 = bhi(v.z), h3 = bhi(v.w);
    ((uint2*)args.h[reg])[j] = make_uint2(pk2(h0, h1), pk2(h2, h3));
    ((uint2*)args.l[reg])[j] =
        make_uint2(pk2(v.x - h0, v.y - h1), pk2(v.z - h2, v.w - h3));
}

// ---------------------------------------------------------------------------
// prep: emg[b][g][s] = exp(gmask[b,g,s]) masked
// ---------------------------------------------------------------------------
__global__ __launch_bounds__(256) void prep_em(
    const float* __restrict__ gmask, const unsigned char* __restrict__ kpm,
    float* __restrict__ emg)
{
    int i = blockIdx.x * 256 + threadIdx.x;   // 8192 total
    int b = i >> 12, s = i & 1023;
    float e = __expf(gmask[i]);
    if (kpm[b * 1024 + s]) e = 0.f;
    emg[i] = e;
}

// ---------------------------------------------------------------------------
// GEMM core: bf16x3 mma.sync, cp.async 3-stage, BK=32
// stage (32KB): A = 128 rows x 128B [Ah|Al], B likewise; 3 stages = 96KB
// ---------------------------------------------------------------------------
#define GEMM_SMEM 98304

__device__ __forceinline__ void gemm_core(
    const __nv_bfloat16* __restrict__ Ah, const __nv_bfloat16* __restrict__ Al,
    const __nv_bfloat16* __restrict__ Bh, const __nv_bfloat16* __restrict__ Bl,
    size_t a_base, int a_str, size_t b_base, int b_str,
    int Kchunks, uint32_t sbase, int tid, int wm, int wn,
    float acc[4][4][4])
{
    const int lane = tid & 31;
    const int a_r  = lane & 15;
    const int a_kb = (lane >> 4) * 16;
    const int b_r  = (lane & 7) + ((lane >> 4) & 1) * 8;
    const int b_kb = ((lane >> 3) & 1) * 16;

#define ISSUE(kc, st) do {                                                     \
    const int _k0 = (kc) * 32;                                                 \
    _Pragma("unroll")                                                          \
    for (int it = 0; it < 8; it++) {                                           \
        int j = it * 256 + tid;                                                \
        int buf = j >> 10;                                                     \
        int r = (j >> 3) & 127;                                                \
        int ch = j & 7;                                                        \
        const __nv_bfloat16* src = buf ? (ch < 4 ? Bh : Bl)                    \
                                       : (ch < 4 ? Ah : Al);                   \
        size_t bs = buf ? b_base : a_base;                                     \
        int strd = buf ? b_str : a_str;                                        \
        uint32_t d = sbase + (st) * 32768 + buf * 16384 + SWZ(r * 128 + ch * 16);\
        CP_ASYNC16(d, src + bs + _k0 + (size_t)r * strd + (ch & 3) * 8);       \
    }                                                                          \
    CP_COMMIT();                                                               \
} while (0)

    ISSUE(0, 0);
    if (Kchunks > 1) ISSUE(1, 1);

    for (int kc = 0; kc < Kchunks; kc++) {
        const int st = kc % 3;
        if (kc + 2 < Kchunks) {
            ISSUE(kc + 2, (kc + 2) % 3);
            CP_WAIT2();
        } else if (kc + 1 < Kchunks) {
            CP_WAIT1();
        } else {
            CP_WAIT0();
        }
        __syncthreads();

        const uint32_t sA = sbase + st * 32768;
        const uint32_t sB = sA + 16384;

#pragma unroll
        for (int ks = 0; ks < 2; ks++) {
            const int kbb = ks * 32;
            uint32_t ah[4][4], bb[2][4];
#pragma unroll
            for (int mi = 0; mi < 4; mi++)
                ldsm4(ah[mi], sA + SWZ((wm + 16 * mi + a_r) * 128 + kbb + a_kb));
#pragma unroll
            for (int jj = 0; jj < 2; jj++)
                ldsm4(bb[jj], sB + SWZ((wn + 16 * jj + b_r) * 128 + kbb + b_kb));
#pragma unroll
            for (int mi = 0; mi < 4; mi++)
#pragma unroll
                for (int nj = 0; nj < 4; nj++)
                    mma_bf16(acc[mi][nj], ah[mi], &bb[nj >> 1][(nj & 1) * 2]);
#pragma unroll
            for (int mi = 0; mi < 4; mi++) {
                uint32_t al[4];
                ldsm4(al, sA + SWZ((wm + 16 * mi + a_r) * 128 + 64 + kbb + a_kb));
#pragma unroll
                for (int nj = 0; nj < 4; nj++)
                    mma_bf16(acc[mi][nj], al, &bb[nj >> 1][(nj & 1) * 2]);
            }
#pragma unroll
            for (int jj = 0; jj < 2; jj++)
                ldsm4(bb[jj], sB + SWZ((wn + 16 * jj + b_r) * 128 + 64 + kbb + b_kb));
#pragma unroll
            for (int mi = 0; mi < 4; mi++)
#pragma unroll
                for (int nj = 0; nj < 4; nj++)
                    mma_bf16(acc[mi][nj], ah[mi], &bb[nj >> 1][(nj & 1) * 2]);
        }
        __syncthreads();
    }
#undef ISSUE
}

// ---------------------------------------------------------------------------
// fused Q/K/V projection GEMM: z = 0:Q, 1:K, 2:V
// ---------------------------------------------------------------------------
struct QKVArgs {
    const __nv_bfloat16 *qh, *ql, *kh, *kl;
    const __nv_bfloat16 *wqh, *wql, *wkh, *wkl, *wvh, *wvl;
    const float *bq, *bk, *bv;
    __nv_bfloat16 *qph, *qpl, *kph, *kpl;
    float *vp;
};

__global__ __launch_bounds__(256, 2) void gemm_qkv(QKVArgs a)
{
    extern __shared__ __align__(1024) char smem[];
    const uint32_t sbase = s2u(smem);
    const int tid = threadIdx.x;
    const int wid = tid >> 5, lane = tid & 31;
    const int m0 = blockIdx.y * 128, n0 = blockIdx.x * 128;
    const int z = blockIdx.z;

    const __nv_bfloat16* Ah = (z == 0) ? a.qh : a.kh;
    const __nv_bfloat16* Al = (z == 0) ? a.ql : a.kl;
    const __nv_bfloat16* Bh = (z == 0) ? a.wqh : (z == 1) ? a.wkh : a.wvh;
    const __nv_bfloat16* Bl = (z == 0) ? a.wql : (z == 1) ? a.wkl : a.wvl;
    const float* bias = (z == 0) ? a.bq : (z == 1) ? a.bk : a.bv;
    const float scale = (z == 0) ? SCALING : 1.0f;

    const int wm = (wid >> 2) * 64, wn = (wid & 3) * 32;

    float acc[4][4][4];
#pragma unroll
    for (int i = 0; i < 4; i++)
#pragma unroll
        for (int j = 0; j < 4; j++)
#pragma unroll
            for (int e = 0; e < 4; e++) acc[i][j][e] = 0.f;

    gemm_core(Ah, Al, Bh, Bl, (size_t)m0 * 1024, 1024, (size_t)n0 * 1024, 1024,
              32, sbase, tid, wm, wn, acc);

    const int tr = lane >> 2, tc2 = (lane & 3) * 2;
#pragma unroll
    for (int mi = 0; mi < 4; mi++) {
#pragma unroll
        for (int nj = 0; nj < 4; nj++) {
            int n = n0 + wn + 8 * nj + tc2;
#pragma unroll
            for (int hr = 0; hr < 2; hr++) {
                int m = m0 + wm + 16 * mi + tr + hr * 8;
                float v0 = acc[mi][nj][hr * 2 + 0];
                float v1 = acc[mi][nj][hr * 2 + 1];
                if (z < 2) {
                    float y0 = (v0 + bias[n]) * scale, y1 = (v1 + bias[n + 1]) * scale;
                    float h0 = bhi(y0), h1 = bhi(y1);
                    size_t o = ((size_t)m * 1024 + n) >> 1;
                    __nv_bfloat16* Ch = (z == 0) ? a.qph : a.kph;
                    __nv_bfloat16* Cl = (z == 0) ? a.qpl : a.kpl;
                    ((uint32_t*)Ch)[o] = pk2(h0, h1);
                    ((uint32_t*)Cl)[o] = pk2(y0 - h0, y1 - h1);
                } else {
                    *(float2*)(a.vp + (size_t)m * 1024 + n) =
                        make_float2(v0 + bias[n], v1 + bias[n + 1]);
                }
            }
        }
    }
}

// ---------------------------------------------------------------------------
// generic GEMM: MODE 2 qk, 3 pv, 4 oproj
// ---------------------------------------------------------------------------
template <int MODE>
__global__ __launch_bounds__(256, 2) void gemm_k(
    const __nv_bfloat16* __restrict__ Ah, const __nv_bfloat16* __restrict__ Al,
    const __nv_bfloat16* __restrict__ Bh, const __nv_bfloat16* __restrict__ Bl,
    const float* __restrict__ bias, const float* __restrict__ rZ,
    float* __restrict__ Cf, __nv_bfloat16* __restrict__ Ch,
    __nv_bfloat16* __restrict__ Cl, int Kchunks)
{
    extern __shared__ __align__(1024) char smem[];
    const uint32_t sbase = s2u(smem);
    const int tid = threadIdx.x;
    const int wid = tid >> 5, lane = tid & 31;
    const int m0 = blockIdx.y * 128, n0 = blockIdx.x * 128;
    const int z = blockIdx.z;
    const int zb = z >> 4, zh = z & 15;

    size_t a_base, b_base;
    int a_str, b_str;
    if (MODE == 2) {
        a_base = (size_t)m0 * 2048 + zb * 1024 + zh * 64; a_str = 2048;
        b_base = (size_t)n0 * 2048 + zb * 1024 + zh * 64; b_str = 2048;
    } else if (MODE == 3) {
        a_base = ((size_t)z << 20) + (size_t)m0 * 1024; a_str = 1024;
        b_base = (size_t)z * 262144 + (size_t)n0 * 1024; b_str = 1024;
    } else {
        a_base = (size_t)m0 * 1024; a_str = 1024;
        b_base = (size_t)n0 * 1024; b_str = 1024;
    }

    const int wm = (wid >> 2) * 64, wn = (wid & 3) * 32;

    float acc[4][4][4];
#pragma unroll
    for (int i = 0; i < 4; i++)
#pragma unroll
        for (int j = 0; j < 4; j++)
#pragma unroll
            for (int e = 0; e < 4; e++) acc[i][j][e] = 0.f;

    gemm_core(Ah, Al, Bh, Bl, a_base, a_str, b_base, b_str,
              Kchunks, sbase, tid, wm, wn, acc);

    const int tr = lane >> 2, tc2 = (lane & 3) * 2;
#pragma unroll
    for (int mi = 0; mi < 4; mi++) {
#pragma unroll
        for (int nj = 0; nj < 4; nj++) {
            int n = n0 + wn + 8 * nj + tc2;
#pragma unroll
            for (int hr = 0; hr < 2; hr++) {
                int m = m0 + wm + 16 * mi + tr + hr * 8;
                float v0 = acc[mi][nj][hr * 2 + 0];
                float v1 = acc[mi][nj][hr * 2 + 1];
                if (MODE == 2) {
                    *(float2*)(Cf + ((size_t)z << 20) + (size_t)m * 1024 + n) =
                        make_float2(v0, v1);
                } else if (MODE == 3) {
                    int g = n >> 6, d = n & 63;
                    float rz = rZ[z * 4096 + g * 1024 + m];
                    float y0 = v0 * rz, y1 = v1 * rz;
                    float h0 = bhi(y0), h1 = bhi(y1);
                    size_t o = ((((size_t)g * 1024 + m) * 2 + zb) * 1024 + zh * 64 + d) >> 1;
                    ((uint32_t*)Ch)[o] = pk2(h0, h1);
                    ((uint32_t*)Cl)[o] = pk2(y0 - h0, y1 - h1);
                } else {
                    *(float2*)(Cf + (size_t)m * 1024 + n) =
                        make_float2(v0 + bias[n], v1 + bias[n + 1]);
                }
            }
        }
    }
}

// ---------------------------------------------------------------------------
// K3: softmax — warp-per-row, row in registers
// grid (128, 32), 256 threads (8 warps = 8 rows)
// ---------------------------------------------------------------------------
__global__ __launch_bounds__(256) void softmax_kernel(
    const float* __restrict__ qk, const float* __restrict__ emg,
    float* __restrict__ prob_out,
    __nv_bfloat16* __restrict__ Eh, __nv_bfloat16* __restrict__ El,
    float* __restrict__ rZg)
{
    __shared__ __align__(16) float em[4][1024];

    const int tid = threadIdx.x, wid = tid >> 5, lane = tid & 31;
    const int bh = blockIdx.y, b = bh >> 4;
    const int t = blockIdx.x * 8 + wid;

    // stage exp(mask) table (16KB) from L2
    for (int i = tid; i < 1024; i += 256)
        ((float4*)&em[0][0])[i] = ((const float4*)(emg + b * 4096))[i];
    __syncthreads();

    const float* row = qk + ((size_t)bh << 20) + (size_t)t * 1024;
    float e[32];
#pragma unroll
    for (int j = 0; j < 8; j++) {
        float4 v = *(const float4*)(row + j * 128 + lane * 4);
        e[4 * j] = v.x; e[4 * j + 1] = v.y; e[4 * j + 2] = v.z; e[4 * j + 3] = v.w;
    }

    float mx = -1e30f;
#pragma unroll
    for (int i = 0; i < 32; i++) mx = fmaxf(mx, e[i]);
#pragma unroll
    for (int o = 16; o; o >>= 1) mx = fmaxf(mx, __shfl_xor_sync(0xffffffffu, mx, o));

#pragma unroll
    for (int i = 0; i < 32; i++) e[i] = __expf(e[i] - mx);

    // Z per group
    float z[4] = {0.f, 0.f, 0.f, 0.f};
#pragma unroll
    for (int g = 0; g < 4; g++) {
#pragma unroll
        for (int j = 0; j < 8; j++) {
            float4 m = *(const float4*)&em[g][j * 128 + lane * 4];
            z[g] = fmaf(e[4 * j], m.x, z[g]);
            z[g] = fmaf(e[4 * j + 1], m.y, z[g]);
            z[g] = fmaf(e[4 * j + 2], m.z, z[g]);
            z[g] = fmaf(e[4 * j + 3], m.w, z[g]);
        }
    }
#pragma unroll
    for (int o = 16; o; o >>= 1) {
#pragma unroll
        for (int g = 0; g < 4; g++)
            z[g] += __shfl_xor_sync(0xffffffffu, z[g], o);
    }
    float rz[4];
#pragma unroll
    for (int g = 0; g < 4; g++) rz[g] = 1.f / z[g];
    if (lane < 4) rZg[bh * 4096 + lane * 1024 + t] = rz[lane];

    // E hi/lo bf16
    const size_t ebase = ((size_t)bh << 20) + (size_t)t * 1024;
#pragma unroll
    for (int j = 0; j < 8; j++) {
        float h0 = bhi(e[4 * j]), h1 = bhi(e[4 * j + 1]);
        float h2 = bhi(e[4 * j + 2]), h3 = bhi(e[4 * j + 3]);
        size_t o = (ebase + j * 128 + lane * 4) >> 2;
        ((uint2*)Eh)[o] = make_uint2(pk2(h0, h1), pk2(h2, h3));
        ((uint2*)El)[o] = make_uint2(pk2(e[4 * j] - h0, e[4 * j + 1] - h1),
                                     pk2(e[4 * j + 2] - h2, e[4 * j + 3] - h3));
    }

    // prob fp32
#pragma unroll
    for (int g = 0; g < 4; g++) {
        float* pout = prob_out + (((size_t)(bh * 4 + g) << 10) + t) * 1024;
        float rzg = rz[g];
#pragma unroll
        for (int j = 0; j < 8; j++) {
            float4 m = *(const float4*)&em[g][j * 128 + lane * 4];
            float4 o;
            o.x = e[4 * j] * m.x * rzg;
            o.y = e[4 * j + 1] * m.y * rzg;
            o.z = e[4 * j + 2] * m.z * rzg;
            o.w = e[4 * j + 3] * m.w * rzg;
            *(float4*)(pout + j * 128 + lane * 4) = o;
        }
    }
}

// ---------------------------------------------------------------------------
// K3b: vgt[bh][(g*64+d)][s] = emg[b,g,s] * V[s,b,h,d]   (hi/lo bf16)
// ---------------------------------------------------------------------------
__global__ __launch_bounds__(256) void build_vg(
    const float* __restrict__ vp, const float* __restrict__ emg,
    __nv_bfloat16* __restrict__ vgh, __nv_bfloat16* __restrict__ vgl)
{
    __shared__ float vsm[64][65];
    __shared__ float em[4][64];
    const int bh = blockIdx.y, b = bh >> 4, h = bh & 15;
    const int s0 = blockIdx.x * 64;
    const int tid = threadIdx.x;

#pragma unroll
    for (int it = 0; it < 4; it++) {
        int j = it * 256 + tid;
        int r = j >> 4, c4 = (j & 15) * 4;
        float4 v = *(const float4*)(vp + (size_t)((s0 + r) * 2 + b) * 1024 + h * 64 + c4);
        vsm[r][c4] = v.x; vsm[r][c4 + 1] = v.y; vsm[r][c4 + 2] = v.z; vsm[r][c4 + 3] = v.w;
    }
    {
        int g = tid >> 6, si = tid & 63;
        em[g][si] = emg[b * 4096 + g * 1024 + s0 + si];
    }
    __syncthreads();

    const int w = tid >> 5, lane = tid & 31;
#pragma unroll 4
    for (int rr = 0; rr < 32; rr++) {
        int gd = rr * 8 + w;
        int g = gd >> 6, d = gd & 63;
        float v0 = em[g][lane * 2] * vsm[lane * 2][d];
        float v1 = em[g][lane * 2 + 1] * vsm[lane * 2 + 1][d];
        float h0 = bhi(v0), h1 = bhi(v1);
        size_t o = ((size_t)bh * 262144 + (size_t)gd * 1024 + s0 + lane * 2) >> 1;
        ((uint32_t*)vgh)[o] = pk2(h0, h1);
        ((uint32_t*)vgl)[o] = pk2(v0 - h0, v1 - h1);
    }
}

// ---------------------------------------------------------------------------
extern "C" void kernel_launch(void* const* d_in, const int* in_sizes, int n_in,
                              void* d_out, int out_size)
{
    const float* query = (const float*)d_in[0];
    const float* key   = (const float*)d_in[1];
    const unsigned char* kpm = (const unsigned char*)d_in[2];
    const float* gmask = (const float*)d_in[3];
    const float* Wq = (const float*)d_in[4];
    const float* bq = (const float*)d_in[5];
    const float* Wk = (const float*)d_in[6];
    const float* bk = (const float*)d_in[7];
    const float* Wv = (const float*)d_in[8];
    const float* bv = (const float*)d_in[9];
    const float* Wo = (const float*)d_in[10];
    const float* bo = (const float*)d_in[11];

    float* out_proj = (float*)d_out;
    float* prob_out = (float*)d_out + (size_t)4 * 1024 * 2 * 1024;

    __nv_bfloat16 *qin_h, *qin_l, *kin_h, *kin_l;
    __nv_bfloat16 *wq_h, *wq_l, *wk_h, *wk_l, *wv_h, *wv_l, *wo_h, *wo_l;
    __nv_bfloat16 *qp_h, *qp_l, *kp_h, *kp_l, *E_h, *E_l, *vgt_h, *vgt_l, *aO_h, *aO_l;
    float *vp, *qkbuf, *rZ, *emg;
    cudaGetSymbolAddress((void**)&qin_h, g_qin_h); cudaGetSymbolAddress((void**)&qin_l, g_qin_l);
    cudaGetSymbolAddress((void**)&kin_h, g_kin_h); cudaGetSymbolAddress((void**)&kin_l, g_kin_l);
    cudaGetSymbolAddress((void**)&wq_h, g_wq_h); cudaGetSymbolAddress((void**)&wq_l, g_wq_l);
    cudaGetSymbolAddress((void**)&wk_h, g_wk_h); cudaGetSymbolAddress((void**)&wk_l, g_wk_l);
    cudaGetSymbolAddress((void**)&wv_h, g_wv_h); cudaGetSymbolAddress((void**)&wv_l, g_wv_l);
    cudaGetSymbolAddress((void**)&wo_h, g_wo_h); cudaGetSymbolAddress((void**)&wo_l, g_wo_l);
    cudaGetSymbolAddress((void**)&qp_h, g_qp_h); cudaGetSymbolAddress((void**)&qp_l, g_qp_l);
    cudaGetSymbolAddress((void**)&kp_h, g_kp_h); cudaGetSymbolAddress((void**)&kp_l, g_kp_l);
    cudaGetSymbolAddress((void**)&vp, g_vp);
    cudaGetSymbolAddress((void**)&qkbuf, g_qk);
    cudaGetSymbolAddress((void**)&E_h, g_E_h); cudaGetSymbolAddress((void**)&E_l, g_E_l);
    cudaGetSymbolAddress((void**)&rZ, g_rZ);
    cudaGetSymbolAddress((void**)&emg, g_emg);
    cudaGetSymbolAddress((void**)&vgt_h, g_vgt_h); cudaGetSymbolAddress((void**)&vgt_l, g_vgt_l);
    cudaGetSymbolAddress((void**)&aO_h, g_aO_h); cudaGetSymbolAddress((void**)&aO_l, g_aO_l);

    cudaFuncSetAttribute(gemm_qkv, cudaFuncAttributeMaxDynamicSharedMemorySize, GEMM_SMEM);
    cudaFuncSetAttribute(gemm_k<2>, cudaFuncAttributeMaxDynamicSharedMemorySize, GEMM_SMEM);
    cudaFuncSetAttribute(gemm_k<3>, cudaFuncAttributeMaxDynamicSharedMemorySize, GEMM_SMEM);
    cudaFuncSetAttribute(gemm_k<4>, cudaFuncAttributeMaxDynamicSharedMemorySize, GEMM_SMEM);

    SplitArgs sa;
    sa.src[0] = query; sa.h[0] = qin_h; sa.l[0] = qin_l;
    sa.src[1] = key;   sa.h[1] = kin_h; sa.l[1] = kin_l;
    sa.src[2] = Wq;    sa.h[2] = wq_h;  sa.l[2] = wq_l;
    sa.src[3] = Wk;    sa.h[3] = wk_h;  sa.l[3] = wk_l;
    sa.src[4] = Wv;    sa.h[4] = wv_h;  sa.l[4] = wv_l;
    sa.src[5] = Wo;    sa.h[5] = wo_h;  sa.l[5] = wo_l;
    sa.end[0] = 524288; sa.end[1] = 1048576;
    sa.end[2] = 1310720; sa.end[3] = 1572864;
    sa.end[4] = 1835008; sa.end[5] = 2097152;
    split_all_kernel<<<2097152 / 256, 256>>>(sa);
    prep_em<<<32, 256>>>(gmask, kpm, emg);

    QKVArgs qa;
    qa.qh = qin_h; qa.ql = qin_l; qa.kh = kin_h; qa.kl = kin_l;
    qa.wqh = wq_h; qa.wql = wq_l; qa.wkh = wk_h; qa.wkl = wk_l;
    qa.wvh = wv_h; qa.wvl = wv_l;
    qa.bq = bq; qa.bk = bk; qa.bv = bv;
    qa.qph = qp_h; qa.qpl = qp_l; qa.kph = kp_h; qa.kpl = kp_l;
    qa.vp = vp;
    gemm_qkv<<<dim3(8, 16, 3), 256, GEMM_SMEM>>>(qa);

    gemm_k<2><<<dim3(8, 8, 32), 256, GEMM_SMEM>>>(qp_h, qp_l, kp_h, kp_l, nullptr,
        nullptr, qkbuf, nullptr, nullptr, 2);

    softmax_kernel<<<dim3(128, 32), 256>>>(qkbuf, emg, prob_out, E_h, E_l, rZ);
    build_vg<<<dim3(16, 32), 256>>>(vp, emg, vgt_h, vgt_l);

    gemm_k<3><<<dim3(2, 8, 32), 256, GEMM_SMEM>>>(E_h, E_l, vgt_h, vgt_l, nullptr,
        rZ, nullptr, aO_h, aO_l, 32);

    gemm_k<4><<<dim3(8, 64, 1), 256, GEMM_SMEM>>>(aO_h, aO_l, wo_h, wo_l, bo,
        nullptr, out_proj, nullptr, nullptr, 32);
}

// round 7
// speedup vs baseline: 3.1179x; 1.0222x over previous
#include <cuda_runtime.h>
#include <cuda_bf16.h>
#include <cstdint>

#define SCALING 0.125f

// ---------------------------------------------------------------------------
// helpers
// ---------------------------------------------------------------------------
__device__ __forceinline__ uint32_t s2u(const void* p) {
    uint32_t a;
    asm("{ .reg .u64 t; cvta.to.shared.u64 t, %1; cvt.u32.u64 %0, t; }"
        : "=r"(a) : "l"(p));
    return a;
}
__device__ __forceinline__ uint32_t pk2(float a, float b) {
    __nv_bfloat162 t = __floats2bfloat162_rn(a, b);
    return reinterpret_cast<uint32_t&>(t);
}
__device__ __forceinline__ float bhi(float x) {
    return __bfloat162float(__float2bfloat16(x));
}
__device__ __forceinline__ void ldsm4(uint32_t* r, uint32_t addr) {
    asm volatile("ldmatrix.sync.aligned.m8n8.x4.shared.b16 {%0,%1,%2,%3}, [%4];"
        : "=r"(r[0]), "=r"(r[1]), "=r"(r[2]), "=r"(r[3]) : "r"(addr));
}
__device__ __forceinline__ void mma_bf16(float* c, const uint32_t* a, const uint32_t* b) {
    asm volatile(
        "mma.sync.aligned.m16n8k16.row.col.f32.bf16.bf16.f32 "
        "{%0,%1,%2,%3}, {%4,%5,%6,%7}, {%8,%9}, {%0,%1,%2,%3};"
        : "+f"(c[0]), "+f"(c[1]), "+f"(c[2]), "+f"(c[3])
        : "r"(a[0]), "r"(a[1]), "r"(a[2]), "r"(a[3]), "r"(b[0]), "r"(b[1]));
}
#define SWZ(x) ((x) ^ (((x) >> 3) & 0x70))

#define CP_ASYNC16(dst, src) \
    asm volatile("cp.async.cg.shared.global [%0], [%1], 16;" :: "r"(dst), "l"(src))
#define CP_COMMIT() asm volatile("cp.async.commit_group;")
#define CP_WAIT0()  asm volatile("cp.async.wait_group 0;")
#define CP_WAIT1()  asm volatile("cp.async.wait_group 1;")
#define CP_WAIT2()  asm volatile("cp.async.wait_group 2;")

// ---------------------------------------------------------------------------
// Device scratch
// ---------------------------------------------------------------------------
__device__ __align__(16) __nv_bfloat16 g_qin_h[2048 * 1024], g_qin_l[2048 * 1024];
__device__ __align__(16) __nv_bfloat16 g_kin_h[2048 * 1024], g_kin_l[2048 * 1024];
__device__ __align__(16) __nv_bfloat16 g_wq_h[1024 * 1024], g_wq_l[1024 * 1024];
__device__ __align__(16) __nv_bfloat16 g_wk_h[1024 * 1024], g_wk_l[1024 * 1024];
__device__ __align__(16) __nv_bfloat16 g_wv_h[1024 * 1024], g_wv_l[1024 * 1024];
__device__ __align__(16) __nv_bfloat16 g_wo_h[1024 * 1024], g_wo_l[1024 * 1024];
__device__ __align__(16) __nv_bfloat16 g_qp_h[2048 * 1024], g_qp_l[2048 * 1024];
__device__ __align__(16) __nv_bfloat16 g_kp_h[2048 * 1024], g_kp_l[2048 * 1024];
__device__ __align__(16) float g_vp[2048 * 1024];
__device__ __align__(16) float g_qk[(size_t)32 * 1024 * 1024];
__device__ __align__(16) __nv_bfloat16 g_E_h[(size_t)32 * 1024 * 1024];
__device__ __align__(16) __nv_bfloat16 g_E_l[(size_t)32 * 1024 * 1024];
__device__ __align__(16) float g_rZ[32 * 4 * 1024];
__device__ __align__(16) float g_emg[2 * 4 * 1024];
__device__ __align__(16) __nv_bfloat16 g_vgt_h[32 * 256 * 1024], g_vgt_l[32 * 256 * 1024];
__device__ __align__(16) __nv_bfloat16 g_aO_h[8192 * 1024], g_aO_l[8192 * 1024];

// ---------------------------------------------------------------------------
// K0: fused fp32 -> bf16 hi/lo split over all 6 tensors in one launch
// ---------------------------------------------------------------------------
struct SplitArgs {
    const float* src[6];
    __nv_bfloat16* h[6];
    __nv_bfloat16* l[6];
    int end[6];
};

__global__ __launch_bounds__(256) void split_all_kernel(SplitArgs args)
{
    int i = blockIdx.x * 256 + threadIdx.x;
    int reg = 0;
#pragma unroll
    for (int r = 0; r < 5; r++) reg += (i >= args.end[r]) ? 1 : 0;
    int base = (reg == 0) ? 0 : args.end[reg - 1];
    int j = i - base;
    float4 v = ((const float4*)args.src[reg])[j];
    float h0 = bhi(v.x), h1 = bhi(v.y), h2 = bhi(v.z), h3 = bhi(v.w);
    ((uint2*)args.h[reg])[j] = make_uint2(pk2(h0, h1), pk2(h2, h3));
    ((uint2*)args.l[reg])[j] =
        make_uint2(pk2(v.x - h0, v.y - h1), pk2(v.z - h2, v.w - h3));
}

// ---------------------------------------------------------------------------
// prep: emg[b][g][s] = exp(gmask[b,g,s]) masked
// ---------------------------------------------------------------------------
__global__ __launch_bounds__(256) void prep_em(
    const float* __restrict__ gmask, const unsigned char* __restrict__ kpm,
    float* __restrict__ emg)
{
    int i = blockIdx.x * 256 + threadIdx.x;   // 8192 total
    int b = i >> 12, s = i & 1023;
    float e = __expf(gmask[i]);
    if (kpm[b * 1024 + s]) e = 0.f;
    emg[i] = e;
}

// ---------------------------------------------------------------------------
// GEMM core: bf16x3 mma.sync, cp.async 3-stage, BK=32
// ---------------------------------------------------------------------------
#define GEMM_SMEM 98304

__device__ __forceinline__ void gemm_core(
    const __nv_bfloat16* __restrict__ Ah, const __nv_bfloat16* __restrict__ Al,
    const __nv_bfloat16* __restrict__ Bh, const __nv_bfloat16* __restrict__ Bl,
    size_t a_base, int a_str, size_t b_base, int b_str,
    int Kchunks, uint32_t sbase, int tid, int wm, int wn,
    float acc[4][4][4])
{
    const int lane = tid & 31;
    const int a_r  = lane & 15;
    const int a_kb = (lane >> 4) * 16;
    const int b_r  = (lane & 7) + ((lane >> 4) & 1) * 8;
    const int b_kb = ((lane >> 3) & 1) * 16;

#define ISSUE(kc, st) do {                                                     \
    const int _k0 = (kc) * 32;                                                 \
    _Pragma("unroll")                                                          \
    for (int it = 0; it < 8; it++) {                                           \
        int j = it * 256 + tid;                                                \
        int buf = j >> 10;                                                     \
        int r = (j >> 3) & 127;                                                \
        int ch = j & 7;                                                        \
        const __nv_bfloat16* src = buf ? (ch < 4 ? Bh : Bl)                    \
                                       : (ch < 4 ? Ah : Al);                   \
        size_t bs = buf ? b_base : a_base;                                     \
        int strd = buf ? b_str : a_str;                                        \
        uint32_t d = sbase + (st) * 32768 + buf * 16384 + SWZ(r * 128 + ch * 16);\
        CP_ASYNC16(d, src + bs + _k0 + (size_t)r * strd + (ch & 3) * 8);       \
    }                                                                          \
    CP_COMMIT();                                                               \
} while (0)

    ISSUE(0, 0);
    if (Kchunks > 1) ISSUE(1, 1);

    for (int kc = 0; kc < Kchunks; kc++) {
        const int st = kc % 3;
        if (kc + 2 < Kchunks) {
            ISSUE(kc + 2, (kc + 2) % 3);
            CP_WAIT2();
        } else if (kc + 1 < Kchunks) {
            CP_WAIT1();
        } else {
            CP_WAIT0();
        }
        __syncthreads();

        const uint32_t sA = sbase + st * 32768;
        const uint32_t sB = sA + 16384;

#pragma unroll
        for (int ks = 0; ks < 2; ks++) {
            const int kbb = ks * 32;
            uint32_t ah[4][4], bb[2][4];
#pragma unroll
            for (int mi = 0; mi < 4; mi++)
                ldsm4(ah[mi], sA + SWZ((wm + 16 * mi + a_r) * 128 + kbb + a_kb));
#pragma unroll
            for (int jj = 0; jj < 2; jj++)
                ldsm4(bb[jj], sB + SWZ((wn + 16 * jj + b_r) * 128 + kbb + b_kb));
#pragma unroll
            for (int mi = 0; mi < 4; mi++)
#pragma unroll
                for (int nj = 0; nj < 4; nj++)
                    mma_bf16(acc[mi][nj], ah[mi], &bb[nj >> 1][(nj & 1) * 2]);
#pragma unroll
            for (int mi = 0; mi < 4; mi++) {
                uint32_t al[4];
                ldsm4(al, sA + SWZ((wm + 16 * mi + a_r) * 128 + 64 + kbb + a_kb));
#pragma unroll
                for (int nj = 0; nj < 4; nj++)
                    mma_bf16(acc[mi][nj], al, &bb[nj >> 1][(nj & 1) * 2]);
            }
#pragma unroll
            for (int jj = 0; jj < 2; jj++)
                ldsm4(bb[jj], sB + SWZ((wn + 16 * jj + b_r) * 128 + 64 + kbb + b_kb));
#pragma unroll
            for (int mi = 0; mi < 4; mi++)
#pragma unroll
                for (int nj = 0; nj < 4; nj++)
                    mma_bf16(acc[mi][nj], ah[mi], &bb[nj >> 1][(nj & 1) * 2]);
        }
        __syncthreads();
    }
#undef ISSUE
}

// ---------------------------------------------------------------------------
// fused Q/K/V projection GEMM: z = 0:Q, 1:K, 2:V
// ---------------------------------------------------------------------------
struct QKVArgs {
    const __nv_bfloat16 *qh, *ql, *kh, *kl;
    const __nv_bfloat16 *wqh, *wql, *wkh, *wkl, *wvh, *wvl;
    const float *bq, *bk, *bv;
    __nv_bfloat16 *qph, *qpl, *kph, *kpl;
    float *vp;
};

__global__ __launch_bounds__(256, 2) void gemm_qkv(QKVArgs a)
{
    extern __shared__ __align__(1024) char smem[];
    const uint32_t sbase = s2u(smem);
    const int tid = threadIdx.x;
    const int wid = tid >> 5, lane = tid & 31;
    const int m0 = blockIdx.y * 128, n0 = blockIdx.x * 128;
    const int z = blockIdx.z;

    const __nv_bfloat16* Ah = (z == 0) ? a.qh : a.kh;
    const __nv_bfloat16* Al = (z == 0) ? a.ql : a.kl;
    const __nv_bfloat16* Bh = (z == 0) ? a.wqh : (z == 1) ? a.wkh : a.wvh;
    const __nv_bfloat16* Bl = (z == 0) ? a.wql : (z == 1) ? a.wkl : a.wvl;
    const float* bias = (z == 0) ? a.bq : (z == 1) ? a.bk : a.bv;
    const float scale = (z == 0) ? SCALING : 1.0f;

    const int wm = (wid >> 2) * 64, wn = (wid & 3) * 32;

    float acc[4][4][4];
#pragma unroll
    for (int i = 0; i < 4; i++)
#pragma unroll
        for (int j = 0; j < 4; j++)
#pragma unroll
            for (int e = 0; e < 4; e++) acc[i][j][e] = 0.f;

    gemm_core(Ah, Al, Bh, Bl, (size_t)m0 * 1024, 1024, (size_t)n0 * 1024, 1024,
              32, sbase, tid, wm, wn, acc);

    const int tr = lane >> 2, tc2 = (lane & 3) * 2;
#pragma unroll
    for (int mi = 0; mi < 4; mi++) {
#pragma unroll
        for (int nj = 0; nj < 4; nj++) {
            int n = n0 + wn + 8 * nj + tc2;
#pragma unroll
            for (int hr = 0; hr < 2; hr++) {
                int m = m0 + wm + 16 * mi + tr + hr * 8;
                float v0 = acc[mi][nj][hr * 2 + 0];
                float v1 = acc[mi][nj][hr * 2 + 1];
                if (z < 2) {
                    float y0 = (v0 + bias[n]) * scale, y1 = (v1 + bias[n + 1]) * scale;
                    float h0 = bhi(y0), h1 = bhi(y1);
                    size_t o = ((size_t)m * 1024 + n) >> 1;
                    __nv_bfloat16* Ch = (z == 0) ? a.qph : a.kph;
                    __nv_bfloat16* Cl = (z == 0) ? a.qpl : a.kpl;
                    ((uint32_t*)Ch)[o] = pk2(h0, h1);
                    ((uint32_t*)Cl)[o] = pk2(y0 - h0, y1 - h1);
                } else {
                    *(float2*)(a.vp + (size_t)m * 1024 + n) =
                        make_float2(v0 + bias[n], v1 + bias[n + 1]);
                }
            }
        }
    }
}

// ---------------------------------------------------------------------------
// generic GEMM: MODE 2 qk, 3 pv, 4 oproj ; zbase = bh offset for halves
// ---------------------------------------------------------------------------
template <int MODE>
__global__ __launch_bounds__(256, 2) void gemm_k(
    const __nv_bfloat16* __restrict__ Ah, const __nv_bfloat16* __restrict__ Al,
    const __nv_bfloat16* __restrict__ Bh, const __nv_bfloat16* __restrict__ Bl,
    const float* __restrict__ bias, const float* __restrict__ rZ,
    float* __restrict__ Cf, __nv_bfloat16* __restrict__ Ch,
    __nv_bfloat16* __restrict__ Cl, int Kchunks, int zbase)
{
    extern __shared__ __align__(1024) char smem[];
    const uint32_t sbase = s2u(smem);
    const int tid = threadIdx.x;
    const int wid = tid >> 5, lane = tid & 31;
    const int m0 = blockIdx.y * 128, n0 = blockIdx.x * 128;
    const int z = blockIdx.z + zbase;
    const int zb = z >> 4, zh = z & 15;

    size_t a_base, b_base;
    int a_str, b_str;
    if (MODE == 2) {
        a_base = (size_t)m0 * 2048 + zb * 1024 + zh * 64; a_str = 2048;
        b_base = (size_t)n0 * 2048 + zb * 1024 + zh * 64; b_str = 2048;
    } else if (MODE == 3) {
        a_base = ((size_t)z << 20) + (size_t)m0 * 1024; a_str = 1024;
        b_base = (size_t)z * 262144 + (size_t)n0 * 1024; b_str = 1024;
    } else {
        a_base = (size_t)m0 * 1024; a_str = 1024;
        b_base = (size_t)n0 * 1024; b_str = 1024;
    }

    const int wm = (wid >> 2) * 64, wn = (wid & 3) * 32;

    float acc[4][4][4];
#pragma unroll
    for (int i = 0; i < 4; i++)
#pragma unroll
        for (int j = 0; j < 4; j++)
#pragma unroll
            for (int e = 0; e < 4; e++) acc[i][j][e] = 0.f;

    gemm_core(Ah, Al, Bh, Bl, a_base, a_str, b_base, b_str,
              Kchunks, sbase, tid, wm, wn, acc);

    const int tr = lane >> 2, tc2 = (lane & 3) * 2;
#pragma unroll
    for (int mi = 0; mi < 4; mi++) {
#pragma unroll
        for (int nj = 0; nj < 4; nj++) {
            int n = n0 + wn + 8 * nj + tc2;
#pragma unroll
            for (int hr = 0; hr < 2; hr++) {
                int m = m0 + wm + 16 * mi + tr + hr * 8;
                float v0 = acc[mi][nj][hr * 2 + 0];
                float v1 = acc[mi][nj][hr * 2 + 1];
                if (MODE == 2) {
                    *(float2*)(Cf + ((size_t)z << 20) + (size_t)m * 1024 + n) =
                        make_float2(v0, v1);
                } else if (MODE == 3) {
                    int g = n >> 6, d = n & 63;
                    float rz = rZ[z * 4096 + g * 1024 + m];
                    float y0 = v0 * rz, y1 = v1 * rz;
                    float h0 = bhi(y0), h1 = bhi(y1);
                    size_t o = ((((size_t)g * 1024 + m) * 2 + zb) * 1024 + zh * 64 + d) >> 1;
                    ((uint32_t*)Ch)[o] = pk2(h0, h1);
                    ((uint32_t*)Cl)[o] = pk2(y0 - h0, y1 - h1);
                } else {
                    *(float2*)(Cf + (size_t)m * 1024 + n) =
                        make_float2(v0 + bias[n], v1 + bias[n + 1]);
                }
            }
        }
    }
}

// ---------------------------------------------------------------------------
// K3: softmax — warp-per-row, row in registers; streaming hints
// ---------------------------------------------------------------------------
__global__ __launch_bounds__(256) void softmax_kernel(
    const float* __restrict__ qk, const float* __restrict__ emg,
    float* __restrict__ prob_out,
    __nv_bfloat16* __restrict__ Eh, __nv_bfloat16* __restrict__ El,
    float* __restrict__ rZg, int bh_base)
{
    __shared__ __align__(16) float em[4][1024];

    const int tid = threadIdx.x, wid = tid >> 5, lane = tid & 31;
    const int bh = blockIdx.y + bh_base, b = bh >> 4;
    const int t = blockIdx.x * 8 + wid;

    for (int i = tid; i < 1024; i += 256)
        ((float4*)&em[0][0])[i] = ((const float4*)(emg + b * 4096))[i];
    __syncthreads();

    const float* row = qk + ((size_t)bh << 20) + (size_t)t * 1024;
    float e[32];
#pragma unroll
    for (int j = 0; j < 8; j++) {
        float4 v = __ldcs((const float4*)(row + j * 128 + lane * 4));
        e[4 * j] = v.x; e[4 * j + 1] = v.y; e[4 * j + 2] = v.z; e[4 * j + 3] = v.w;
    }

    float mx = -1e30f;
#pragma unroll
    for (int i = 0; i < 32; i++) mx = fmaxf(mx, e[i]);
#pragma unroll
    for (int o = 16; o; o >>= 1) mx = fmaxf(mx, __shfl_xor_sync(0xffffffffu, mx, o));

#pragma unroll
    for (int i = 0; i < 32; i++) e[i] = __expf(e[i] - mx);

    float z[4] = {0.f, 0.f, 0.f, 0.f};
#pragma unroll
    for (int g = 0; g < 4; g++) {
#pragma unroll
        for (int j = 0; j < 8; j++) {
            float4 m = *(const float4*)&em[g][j * 128 + lane * 4];
            z[g] = fmaf(e[4 * j], m.x, z[g]);
            z[g] = fmaf(e[4 * j + 1], m.y, z[g]);
            z[g] = fmaf(e[4 * j + 2], m.z, z[g]);
            z[g] = fmaf(e[4 * j + 3], m.w, z[g]);
        }
    }
#pragma unroll
    for (int o = 16; o; o >>= 1) {
#pragma unroll
        for (int g = 0; g < 4; g++)
            z[g] += __shfl_xor_sync(0xffffffffu, z[g], o);
    }
    float rz[4];
#pragma unroll
    for (int g = 0; g < 4; g++) rz[g] = 1.f / z[g];
    if (lane < 4) rZg[bh * 4096 + lane * 1024 + t] = rz[lane];

    const size_t ebase = ((size_t)bh << 20) + (size_t)t * 1024;
#pragma unroll
    for (int j = 0; j < 8; j++) {
        float h0 = bhi(e[4 * j]), h1 = bhi(e[4 * j + 1]);
        float h2 = bhi(e[4 * j + 2]), h3 = bhi(e[4 * j + 3]);
        size_t o = (ebase + j * 128 + lane * 4) >> 2;
        ((uint2*)Eh)[o] = make_uint2(pk2(h0, h1), pk2(h2, h3));
        ((uint2*)El)[o] = make_uint2(pk2(e[4 * j] - h0, e[4 * j + 1] - h1),
                                     pk2(e[4 * j + 2] - h2, e[4 * j + 3] - h3));
    }

#pragma unroll
    for (int g = 0; g < 4; g++) {
        float* pout = prob_out + (((size_t)(bh * 4 + g) << 10) + t) * 1024;
        float rzg = rz[g];
#pragma unroll
        for (int j = 0; j < 8; j++) {
            float4 m = *(const float4*)&em[g][j * 128 + lane * 4];
            float4 o;
            o.x = e[4 * j] * m.x * rzg;
            o.y = e[4 * j + 1] * m.y * rzg;
            o.z = e[4 * j + 2] * m.z * rzg;
            o.w = e[4 * j + 3] * m.w * rzg;
            __stcs((float4*)(pout + j * 128 + lane * 4), o);
        }
    }
}

// ---------------------------------------------------------------------------
// K3b: vgt[bh][(g*64+d)][s] = emg[b,g,s] * V[s,b,h,d]   (hi/lo bf16)
// ---------------------------------------------------------------------------
__global__ __launch_bounds__(256) void build_vg(
    const float* __restrict__ vp, const float* __restrict__ emg,
    __nv_bfloat16* __restrict__ vgh, __nv_bfloat16* __restrict__ vgl)
{
    __shared__ float vsm[64][65];
    __shared__ float em[4][64];
    const int bh = blockIdx.y, b = bh >> 4, h = bh & 15;
    const int s0 = blockIdx.x * 64;
    const int tid = threadIdx.x;

#pragma unroll
    for (int it = 0; it < 4; it++) {
        int j = it * 256 + tid;
        int r = j >> 4, c4 = (j & 15) * 4;
        float4 v = *(const float4*)(vp + (size_t)((s0 + r) * 2 + b) * 1024 + h * 64 + c4);
        vsm[r][c4] = v.x; vsm[r][c4 + 1] = v.y; vsm[r][c4 + 2] = v.z; vsm[r][c4 + 3] = v.w;
    }
    {
        int g = tid >> 6, si = tid & 63;
        em[g][si] = emg[b * 4096 + g * 1024 + s0 + si];
    }
    __syncthreads();

    const int w = tid >> 5, lane = tid & 31;
#pragma unroll 4
    for (int rr = 0; rr < 32; rr++) {
        int gd = rr * 8 + w;
        int g = gd >> 6, d = gd & 63;
        float v0 = em[g][lane * 2] * vsm[lane * 2][d];
        float v1 = em[g][lane * 2 + 1] * vsm[lane * 2 + 1][d];
        float h0 = bhi(v0), h1 = bhi(v1);
        size_t o = ((size_t)bh * 262144 + (size_t)gd * 1024 + s0 + lane * 2) >> 1;
        ((uint32_t*)vgh)[o] = pk2(h0, h1);
        ((uint32_t*)vgl)[o] = pk2(v0 - h0, v1 - h1);
    }
}

// ---------------------------------------------------------------------------
extern "C" void kernel_launch(void* const* d_in, const int* in_sizes, int n_in,
                              void* d_out, int out_size)
{
    const float* query = (const float*)d_in[0];
    const float* key   = (const float*)d_in[1];
    const unsigned char* kpm = (const unsigned char*)d_in[2];
    const float* gmask = (const float*)d_in[3];
    const float* Wq = (const float*)d_in[4];
    const float* bq = (const float*)d_in[5];
    const float* Wk = (const float*)d_in[6];
    const float* bk = (const float*)d_in[7];
    const float* Wv = (const float*)d_in[8];
    const float* bv = (const float*)d_in[9];
    const float* Wo = (const float*)d_in[10];
    const float* bo = (const float*)d_in[11];

    float* out_proj = (float*)d_out;
    float* prob_out = (float*)d_out + (size_t)4 * 1024 * 2 * 1024;

    __nv_bfloat16 *qin_h, *qin_l, *kin_h, *kin_l;
    __nv_bfloat16 *wq_h, *wq_l, *wk_h, *wk_l, *wv_h, *wv_l, *wo_h, *wo_l;
    __nv_bfloat16 *qp_h, *qp_l, *kp_h, *kp_l, *E_h, *E_l, *vgt_h, *vgt_l, *aO_h, *aO_l;
    float *vp, *qkbuf, *rZ, *emg;
    cudaGetSymbolAddress((void**)&qin_h, g_qin_h); cudaGetSymbolAddress((void**)&qin_l, g_qin_l);
    cudaGetSymbolAddress((void**)&kin_h, g_kin_h); cudaGetSymbolAddress((void**)&kin_l, g_kin_l);
    cudaGetSymbolAddress((void**)&wq_h, g_wq_h); cudaGetSymbolAddress((void**)&wq_l, g_wq_l);
    cudaGetSymbolAddress((void**)&wk_h, g_wk_h); cudaGetSymbolAddress((void**)&wk_l, g_wk_l);
    cudaGetSymbolAddress((void**)&wv_h, g_wv_h); cudaGetSymbolAddress((void**)&wv_l, g_wv_l);
    cudaGetSymbolAddress((void**)&wo_h, g_wo_h); cudaGetSymbolAddress((void**)&wo_l, g_wo_l);
    cudaGetSymbolAddress((void**)&qp_h, g_qp_h); cudaGetSymbolAddress((void**)&qp_l, g_qp_l);
    cudaGetSymbolAddress((void**)&kp_h, g_kp_h); cudaGetSymbolAddress((void**)&kp_l, g_kp_l);
    cudaGetSymbolAddress((void**)&vp, g_vp);
    cudaGetSymbolAddress((void**)&qkbuf, g_qk);
    cudaGetSymbolAddress((void**)&E_h, g_E_h); cudaGetSymbolAddress((void**)&E_l, g_E_l);
    cudaGetSymbolAddress((void**)&rZ, g_rZ);
    cudaGetSymbolAddress((void**)&emg, g_emg);
    cudaGetSymbolAddress((void**)&vgt_h, g_vgt_h); cudaGetSymbolAddress((void**)&vgt_l, g_vgt_l);
    cudaGetSymbolAddress((void**)&aO_h, g_aO_h); cudaGetSymbolAddress((void**)&aO_l, g_aO_l);

    cudaFuncSetAttribute(gemm_qkv, cudaFuncAttributeMaxDynamicSharedMemorySize, GEMM_SMEM);
    cudaFuncSetAttribute(gemm_k<2>, cudaFuncAttributeMaxDynamicSharedMemorySize, GEMM_SMEM);
    cudaFuncSetAttribute(gemm_k<3>, cudaFuncAttributeMaxDynamicSharedMemorySize, GEMM_SMEM);
    cudaFuncSetAttribute(gemm_k<4>, cudaFuncAttributeMaxDynamicSharedMemorySize, GEMM_SMEM);

    SplitArgs sa;
    sa.src[0] = query; sa.h[0] = qin_h; sa.l[0] = qin_l;
    sa.src[1] = key;   sa.h[1] = kin_h; sa.l[1] = kin_l;
    sa.src[2] = Wq;    sa.h[2] = wq_h;  sa.l[2] = wq_l;
    sa.src[3] = Wk;    sa.h[3] = wk_h;  sa.l[3] = wk_l;
    sa.src[4] = Wv;    sa.h[4] = wv_h;  sa.l[4] = wv_l;
    sa.src[5] = Wo;    sa.h[5] = wo_h;  sa.l[5] = wo_l;
    sa.end[0] = 524288; sa.end[1] = 1048576;
    sa.end[2] = 1310720; sa.end[3] = 1572864;
    sa.end[4] = 1835008; sa.end[5] = 2097152;
    split_all_kernel<<<2097152 / 256, 256>>>(sa);
    prep_em<<<32, 256>>>(gmask, kpm, emg);

    QKVArgs qa;
    qa.qh = qin_h; qa.ql = qin_l; qa.kh = kin_h; qa.kl = kin_l;
    qa.wqh = wq_h; qa.wql = wq_l; qa.wkh = wk_h; qa.wkl = wk_l;
    qa.wvh = wv_h; qa.wvl = wv_l;
    qa.bq = bq; qa.bk = bk; qa.bv = bv;
    qa.qph = qp_h; qa.qpl = qp_l; qa.kph = kp_h; qa.kpl = kp_l;
    qa.vp = vp;
    gemm_qkv<<<dim3(8, 16, 3), 256, GEMM_SMEM>>>(qa);

    // vg depends only on vp
    build_vg<<<dim3(16, 32), 256>>>(vp, emg, vgt_h, vgt_l);

    // L2-resident halves: qk(half) -> softmax(half) -> pv(half)
    for (int half = 0; half < 2; half++) {
        int zb = half * 16;
        gemm_k<2><<<dim3(8, 8, 16), 256, GEMM_SMEM>>>(qp_h, qp_l, kp_h, kp_l,
            nullptr, nullptr, qkbuf, nullptr, nullptr, 2, zb);
        softmax_kernel<<<dim3(128, 16), 256>>>(qkbuf, emg, prob_out, E_h, E_l,
                                               rZ, zb);
        gemm_k<3><<<dim3(2, 8, 16), 256, GEMM_SMEM>>>(E_h, E_l, vgt_h, vgt_l,
            nullptr, rZ, nullptr, aO_h, aO_l, 32, zb);
    }

    gemm_k<4><<<dim3(8, 64, 1), 256, GEMM_SMEM>>>(aO_h, aO_l, wo_h, wo_l, bo,
        nullptr, out_proj, nullptr, nullptr, 32, 0);
}

// round 8
// speedup vs baseline: 3.2417x; 1.0397x over previous
#include <cuda_runtime.h>
#include <cuda_bf16.h>
#include <cstdint>

#define SCALING 0.125f

// ---------------------------------------------------------------------------
// helpers
// ---------------------------------------------------------------------------
__device__ __forceinline__ uint32_t s2u(const void* p) {
    uint32_t a;
    asm("{ .reg .u64 t; cvta.to.shared.u64 t, %1; cvt.u32.u64 %0, t; }"
        : "=r"(a) : "l"(p));
    return a;
}
__device__ __forceinline__ uint32_t pk2(float a, float b) {
    __nv_bfloat162 t = __floats2bfloat162_rn(a, b);
    return reinterpret_cast<uint32_t&>(t);
}
__device__ __forceinline__ float bhi(float x) {
    return __bfloat162float(__float2bfloat16(x));
}
__device__ __forceinline__ void ldsm4(uint32_t* r, uint32_t addr) {
    asm volatile("ldmatrix.sync.aligned.m8n8.x4.shared.b16 {%0,%1,%2,%3}, [%4];"
        : "=r"(r[0]), "=r"(r[1]), "=r"(r[2]), "=r"(r[3]) : "r"(addr));
}
__device__ __forceinline__ void mma_bf16(float* c, const uint32_t* a, const uint32_t* b) {
    asm volatile(
        "mma.sync.aligned.m16n8k16.row.col.f32.bf16.bf16.f32 "
        "{%0,%1,%2,%3}, {%4,%5,%6,%7}, {%8,%9}, {%0,%1,%2,%3};"
        : "+f"(c[0]), "+f"(c[1]), "+f"(c[2]), "+f"(c[3])
        : "r"(a[0]), "r"(a[1]), "r"(a[2]), "r"(a[3]), "r"(b[0]), "r"(b[1]));
}
#define SWZ(x) ((x) ^ (((x) >> 3) & 0x70))

#define CP_ASYNC16(dst, src) \
    asm volatile("cp.async.cg.shared.global [%0], [%1], 16;" :: "r"(dst), "l"(src))
#define CP_COMMIT() asm volatile("cp.async.commit_group;")
#define CP_WAIT0()  asm volatile("cp.async.wait_group 0;")
#define CP_WAIT1()  asm volatile("cp.async.wait_group 1;")
#define CP_WAIT2()  asm volatile("cp.async.wait_group 2;")

// ---------------------------------------------------------------------------
// Device scratch
// ---------------------------------------------------------------------------
__device__ __align__(16) __nv_bfloat16 g_qin_h[2048 * 1024], g_qin_l[2048 * 1024];
__device__ __align__(16) __nv_bfloat16 g_kin_h[2048 * 1024], g_kin_l[2048 * 1024];
__device__ __align__(16) __nv_bfloat16 g_wq_h[1024 * 1024], g_wq_l[1024 * 1024];
__device__ __align__(16) __nv_bfloat16 g_wk_h[1024 * 1024], g_wk_l[1024 * 1024];
__device__ __align__(16) __nv_bfloat16 g_wv_h[1024 * 1024], g_wv_l[1024 * 1024];
__device__ __align__(16) __nv_bfloat16 g_wo_h[1024 * 1024], g_wo_l[1024 * 1024];
__device__ __align__(16) __nv_bfloat16 g_qp_h[2048 * 1024], g_qp_l[2048 * 1024];
__device__ __align__(16) __nv_bfloat16 g_kp_h[2048 * 1024], g_kp_l[2048 * 1024];
__device__ __align__(16) float g_vp[2048 * 1024];
__device__ __align__(16) float g_qk[(size_t)32 * 1024 * 1024];
__device__ __align__(16) __nv_bfloat16 g_E_h[(size_t)32 * 1024 * 1024];
__device__ __align__(16) __nv_bfloat16 g_E_l[(size_t)32 * 1024 * 1024];
__device__ __align__(16) float g_rZ[32 * 4 * 1024];
__device__ __align__(16) float g_emg[2 * 4 * 1024];
__device__ __align__(16) __nv_bfloat16 g_vgt_h[32 * 256 * 1024], g_vgt_l[32 * 256 * 1024];
__device__ __align__(16) __nv_bfloat16 g_aO_h[8192 * 1024], g_aO_l[8192 * 1024];

// ---------------------------------------------------------------------------
// K0: fused fp32 -> bf16 hi/lo split over all 6 tensors in one launch
// ---------------------------------------------------------------------------
struct SplitArgs {
    const float* src[6];
    __nv_bfloat16* h[6];
    __nv_bfloat16* l[6];
    int end[6];
};

__global__ __launch_bounds__(256) void split_all_kernel(SplitArgs args)
{
    int i = blockIdx.x * 256 + threadIdx.x;
    int reg = 0;
#pragma unroll
    for (int r = 0; r < 5; r++) reg += (i >= args.end[r]) ? 1 : 0;
    int base = (reg == 0) ? 0 : args.end[reg - 1];
    int j = i - base;
    float4 v = ((const float4*)args.src[reg])[j];
    float h0 = bhi(v.x), h1 = bhi(v.y), h2 = bhi(v.z), h3 = bhi(v.w);
    ((uint2*)args.h[reg])[j] = make_uint2(pk2(h0, h1), pk2(h2, h3));
    ((uint2*)args.l[reg])[j] =
        make_uint2(pk2(v.x - h0, v.y - h1), pk2(v.z - h2, v.w - h3));
}

// ---------------------------------------------------------------------------
// prep: emg[b][g][s] = exp(gmask[b,g,s]) masked
// ---------------------------------------------------------------------------
__global__ __launch_bounds__(256) void prep_em(
    const float* __restrict__ gmask, const unsigned char* __restrict__ kpm,
    float* __restrict__ emg)
{
    int i = blockIdx.x * 256 + threadIdx.x;
    int b = i >> 12, s = i & 1023;
    float e = __expf(gmask[i]);
    if (kpm[b * 1024 + s]) e = 0.f;
    emg[i] = e;
}

// ---------------------------------------------------------------------------
// GEMM core: bf16x3 mma.sync, cp.async 3-stage, BK=32
// ---------------------------------------------------------------------------
#define GEMM_SMEM 98304

__device__ __forceinline__ void gemm_core(
    const __nv_bfloat16* __restrict__ Ah, const __nv_bfloat16* __restrict__ Al,
    const __nv_bfloat16* __restrict__ Bh, const __nv_bfloat16* __restrict__ Bl,
    size_t a_base, int a_str, size_t b_base, int b_str,
    int Kchunks, uint32_t sbase, int tid, int wm, int wn,
    float acc[4][4][4])
{
    const int lane = tid & 31;
    const int a_r  = lane & 15;
    const int a_kb = (lane >> 4) * 16;
    const int b_r  = (lane & 7) + ((lane >> 4) & 1) * 8;
    const int b_kb = ((lane >> 3) & 1) * 16;

#define ISSUE(kc, st) do {                                                     \
    const int _k0 = (kc) * 32;                                                 \
    _Pragma("unroll")                                                          \
    for (int it = 0; it < 8; it++) {                                           \
        int j = it * 256 + tid;                                                \
        int buf = j >> 10;                                                     \
        int r = (j >> 3) & 127;                                                \
        int ch = j & 7;                                                        \
        const __nv_bfloat16* src = buf ? (ch < 4 ? Bh : Bl)                    \
                                       : (ch < 4 ? Ah : Al);                   \
        size_t bs = buf ? b_base : a_base;                                     \
        int strd = buf ? b_str : a_str;                                        \
        uint32_t d = sbase + (st) * 32768 + buf * 16384 + SWZ(r * 128 + ch * 16);\
        CP_ASYNC16(d, src + bs + _k0 + (size_t)r * strd + (ch & 3) * 8);       \
    }                                                                          \
    CP_COMMIT();                                                               \
} while (0)

    ISSUE(0, 0);
    if (Kchunks > 1) ISSUE(1, 1);

    for (int kc = 0; kc < Kchunks; kc++) {
        const int st = kc % 3;
        if (kc + 2 < Kchunks) {
            ISSUE(kc + 2, (kc + 2) % 3);
            CP_WAIT2();
        } else if (kc + 1 < Kchunks) {
            CP_WAIT1();
        } else {
            CP_WAIT0();
        }
        __syncthreads();

        const uint32_t sA = sbase + st * 32768;
        const uint32_t sB = sA + 16384;

#pragma unroll
        for (int ks = 0; ks < 2; ks++) {
            const int kbb = ks * 32;
            uint32_t ah[4][4], bb[2][4];
#pragma unroll
            for (int mi = 0; mi < 4; mi++)
                ldsm4(ah[mi], sA + SWZ((wm + 16 * mi + a_r) * 128 + kbb + a_kb));
#pragma unroll
            for (int jj = 0; jj < 2; jj++)
                ldsm4(bb[jj], sB + SWZ((wn + 16 * jj + b_r) * 128 + kbb + b_kb));
#pragma unroll
            for (int mi = 0; mi < 4; mi++)
#pragma unroll
                for (int nj = 0; nj < 4; nj++)
                    mma_bf16(acc[mi][nj], ah[mi], &bb[nj >> 1][(nj & 1) * 2]);
#pragma unroll
            for (int mi = 0; mi < 4; mi++) {
                uint32_t al[4];
                ldsm4(al, sA + SWZ((wm + 16 * mi + a_r) * 128 + 64 + kbb + a_kb));
#pragma unroll
                for (int nj = 0; nj < 4; nj++)
                    mma_bf16(acc[mi][nj], al, &bb[nj >> 1][(nj & 1) * 2]);
            }
#pragma unroll
            for (int jj = 0; jj < 2; jj++)
                ldsm4(bb[jj], sB + SWZ((wn + 16 * jj + b_r) * 128 + 64 + kbb + b_kb));
#pragma unroll
            for (int mi = 0; mi < 4; mi++)
#pragma unroll
                for (int nj = 0; nj < 4; nj++)
                    mma_bf16(acc[mi][nj], ah[mi], &bb[nj >> 1][(nj & 1) * 2]);
        }
        __syncthreads();
    }
#undef ISSUE
}

// ---------------------------------------------------------------------------
// fused Q/K/V projection GEMM: z = 0:Q, 1:K, 2:V
// ---------------------------------------------------------------------------
struct QKVArgs {
    const __nv_bfloat16 *qh, *ql, *kh, *kl;
    const __nv_bfloat16 *wqh, *wql, *wkh, *wkl, *wvh, *wvl;
    const float *bq, *bk, *bv;
    __nv_bfloat16 *qph, *qpl, *kph, *kpl;
    float *vp;
};

__global__ __launch_bounds__(256, 2) void gemm_qkv(QKVArgs a)
{
    extern __shared__ __align__(1024) char smem[];
    const uint32_t sbase = s2u(smem);
    const int tid = threadIdx.x;
    const int wid = tid >> 5, lane = tid & 31;
    const int m0 = blockIdx.y * 128, n0 = blockIdx.x * 128;
    const int z = blockIdx.z;

    const __nv_bfloat16* Ah = (z == 0) ? a.qh : a.kh;
    const __nv_bfloat16* Al = (z == 0) ? a.ql : a.kl;
    const __nv_bfloat16* Bh = (z == 0) ? a.wqh : (z == 1) ? a.wkh : a.wvh;
    const __nv_bfloat16* Bl = (z == 0) ? a.wql : (z == 1) ? a.wkl : a.wvl;
    const float* bias = (z == 0) ? a.bq : (z == 1) ? a.bk : a.bv;
    const float scale = (z == 0) ? SCALING : 1.0f;

    const int wm = (wid >> 2) * 64, wn = (wid & 3) * 32;

    float acc[4][4][4];
#pragma unroll
    for (int i = 0; i < 4; i++)
#pragma unroll
        for (int j = 0; j < 4; j++)
#pragma unroll
            for (int e = 0; e < 4; e++) acc[i][j][e] = 0.f;

    gemm_core(Ah, Al, Bh, Bl, (size_t)m0 * 1024, 1024, (size_t)n0 * 1024, 1024,
              32, sbase, tid, wm, wn, acc);

    const int tr = lane >> 2, tc2 = (lane & 3) * 2;
#pragma unroll
    for (int mi = 0; mi < 4; mi++) {
#pragma unroll
        for (int nj = 0; nj < 4; nj++) {
            int n = n0 + wn + 8 * nj + tc2;
#pragma unroll
            for (int hr = 0; hr < 2; hr++) {
                int m = m0 + wm + 16 * mi + tr + hr * 8;
                float v0 = acc[mi][nj][hr * 2 + 0];
                float v1 = acc[mi][nj][hr * 2 + 1];
                if (z < 2) {
                    float y0 = (v0 + bias[n]) * scale, y1 = (v1 + bias[n + 1]) * scale;
                    float h0 = bhi(y0), h1 = bhi(y1);
                    size_t o = ((size_t)m * 1024 + n) >> 1;
                    __nv_bfloat16* Ch = (z == 0) ? a.qph : a.kph;
                    __nv_bfloat16* Cl = (z == 0) ? a.qpl : a.kpl;
                    ((uint32_t*)Ch)[o] = pk2(h0, h1);
                    ((uint32_t*)Cl)[o] = pk2(y0 - h0, y1 - h1);
                } else {
                    *(float2*)(a.vp + (size_t)m * 1024 + n) =
                        make_float2(v0 + bias[n], v1 + bias[n + 1]);
                }
            }
        }
    }
}

// ---------------------------------------------------------------------------
// generic GEMM: MODE 2 qk, 3 pv, 4 oproj ; zbase = bh offset for halves
// ---------------------------------------------------------------------------
template <int MODE>
__global__ __launch_bounds__(256, 2) void gemm_k(
    const __nv_bfloat16* __restrict__ Ah, const __nv_bfloat16* __restrict__ Al,
    const __nv_bfloat16* __restrict__ Bh, const __nv_bfloat16* __restrict__ Bl,
    const float* __restrict__ bias, const float* __restrict__ rZ,
    float* __restrict__ Cf, __nv_bfloat16* __restrict__ Ch,
    __nv_bfloat16* __restrict__ Cl, int Kchunks, int zbase)
{
    extern __shared__ __align__(1024) char smem[];
    const uint32_t sbase = s2u(smem);
    const int tid = threadIdx.x;
    const int wid = tid >> 5, lane = tid & 31;
    const int m0 = blockIdx.y * 128, n0 = blockIdx.x * 128;
    const int z = blockIdx.z + zbase;
    const int zb = z >> 4, zh = z & 15;

    size_t a_base, b_base;
    int a_str, b_str;
    if (MODE == 2) {
        a_base = (size_t)m0 * 2048 + zb * 1024 + zh * 64; a_str = 2048;
        b_base = (size_t)n0 * 2048 + zb * 1024 + zh * 64; b_str = 2048;
    } else if (MODE == 3) {
        a_base = ((size_t)z << 20) + (size_t)m0 * 1024; a_str = 1024;
        b_base = (size_t)z * 262144 + (size_t)n0 * 1024; b_str = 1024;
    } else {
        a_base = (size_t)m0 * 1024; a_str = 1024;
        b_base = (size_t)n0 * 1024; b_str = 1024;
    }

    const int wm = (wid >> 2) * 64, wn = (wid & 3) * 32;

    float acc[4][4][4];
#pragma unroll
    for (int i = 0; i < 4; i++)
#pragma unroll
        for (int j = 0; j < 4; j++)
#pragma unroll
            for (int e = 0; e < 4; e++) acc[i][j][e] = 0.f;

    gemm_core(Ah, Al, Bh, Bl, a_base, a_str, b_base, b_str,
              Kchunks, sbase, tid, wm, wn, acc);

    const int tr = lane >> 2, tc2 = (lane & 3) * 2;
#pragma unroll
    for (int mi = 0; mi < 4; mi++) {
#pragma unroll
        for (int nj = 0; nj < 4; nj++) {
            int n = n0 + wn + 8 * nj + tc2;
#pragma unroll
            for (int hr = 0; hr < 2; hr++) {
                int m = m0 + wm + 16 * mi + tr + hr * 8;
                float v0 = acc[mi][nj][hr * 2 + 0];
                float v1 = acc[mi][nj][hr * 2 + 1];
                if (MODE == 2) {
                    *(float2*)(Cf + ((size_t)z << 20) + (size_t)m * 1024 + n) =
                        make_float2(v0, v1);
                } else if (MODE == 3) {
                    int g = n >> 6, d = n & 63;
                    float rz = rZ[z * 4096 + g * 1024 + m];
                    float y0 = v0 * rz, y1 = v1 * rz;
                    float h0 = bhi(y0), h1 = bhi(y1);
                    size_t o = ((((size_t)g * 1024 + m) * 2 + zb) * 1024 + zh * 64 + d) >> 1;
                    ((uint32_t*)Ch)[o] = pk2(h0, h1);
                    ((uint32_t*)Cl)[o] = pk2(y0 - h0, y1 - h1);
                } else {
                    __stcs((float2*)(Cf + (size_t)m * 1024 + n),
                           make_float2(v0 + bias[n], v1 + bias[n + 1]));
                }
            }
        }
    }
}

// ---------------------------------------------------------------------------
// K3: softmax — warp-per-row, row in registers; streaming hints
// ---------------------------------------------------------------------------
__global__ __launch_bounds__(256) void softmax_kernel(
    const float* __restrict__ qk, const float* __restrict__ emg,
    float* __restrict__ prob_out,
    __nv_bfloat16* __restrict__ Eh, __nv_bfloat16* __restrict__ El,
    float* __restrict__ rZg, int bh_base)
{
    __shared__ __align__(16) float em[4][1024];

    const int tid = threadIdx.x, wid = tid >> 5, lane = tid & 31;
    const int bh = blockIdx.y + bh_base, b = bh >> 4;
    const int t = blockIdx.x * 8 + wid;

    for (int i = tid; i < 1024; i += 256)
        ((float4*)&em[0][0])[i] = ((const float4*)(emg + b * 4096))[i];
    __syncthreads();

    const float* row = qk + ((size_t)bh << 20) + (size_t)t * 1024;
    float e[32];
#pragma unroll
    for (int j = 0; j < 8; j++) {
        float4 v = __ldcs((const float4*)(row + j * 128 + lane * 4));
        e[4 * j] = v.x; e[4 * j + 1] = v.y; e[4 * j + 2] = v.z; e[4 * j + 3] = v.w;
    }

    float mx = -1e30f;
#pragma unroll
    for (int i = 0; i < 32; i++) mx = fmaxf(mx, e[i]);
#pragma unroll
    for (int o = 16; o; o >>= 1) mx = fmaxf(mx, __shfl_xor_sync(0xffffffffu, mx, o));

#pragma unroll
    for (int i = 0; i < 32; i++) e[i] = __expf(e[i] - mx);

    float z[4] = {0.f, 0.f, 0.f, 0.f};
#pragma unroll
    for (int g = 0; g < 4; g++) {
#pragma unroll
        for (int j = 0; j < 8; j++) {
            float4 m = *(const float4*)&em[g][j * 128 + lane * 4];
            z[g] = fmaf(e[4 * j], m.x, z[g]);
            z[g] = fmaf(e[4 * j + 1], m.y, z[g]);
            z[g] = fmaf(e[4 * j + 2], m.z, z[g]);
            z[g] = fmaf(e[4 * j + 3], m.w, z[g]);
        }
    }
#pragma unroll
    for (int o = 16; o; o >>= 1) {
#pragma unroll
        for (int g = 0; g < 4; g++)
            z[g] += __shfl_xor_sync(0xffffffffu, z[g], o);
    }
    float rz[4];
#pragma unroll
    for (int g = 0; g < 4; g++) rz[g] = 1.f / z[g];
    if (lane < 4) rZg[bh * 4096 + lane * 1024 + t] = rz[lane];

    const size_t ebase = ((size_t)bh << 20) + (size_t)t * 1024;
#pragma unroll
    for (int j = 0; j < 8; j++) {
        float h0 = bhi(e[4 * j]), h1 = bhi(e[4 * j + 1]);
        float h2 = bhi(e[4 * j + 2]), h3 = bhi(e[4 * j + 3]);
        size_t o = (ebase + j * 128 + lane * 4) >> 2;
        ((uint2*)Eh)[o] = make_uint2(pk2(h0, h1), pk2(h2, h3));
        ((uint2*)El)[o] = make_uint2(pk2(e[4 * j] - h0, e[4 * j + 1] - h1),
                                     pk2(e[4 * j + 2] - h2, e[4 * j + 3] - h3));
    }

#pragma unroll
    for (int g = 0; g < 4; g++) {
        float* pout = prob_out + (((size_t)(bh * 4 + g) << 10) + t) * 1024;
        float rzg = rz[g];
#pragma unroll
        for (int j = 0; j < 8; j++) {
            float4 m = *(const float4*)&em[g][j * 128 + lane * 4];
            float4 o;
            o.x = e[4 * j] * m.x * rzg;
            o.y = e[4 * j + 1] * m.y * rzg;
            o.z = e[4 * j + 2] * m.z * rzg;
            o.w = e[4 * j + 3] * m.w * rzg;
            __stcs((float4*)(pout + j * 128 + lane * 4), o);
        }
    }
}

// ---------------------------------------------------------------------------
// K3b: vgt[bh][(g*64+d)][s] = emg[b,g,s] * V[s,b,h,d]   (hi/lo bf16)
// ---------------------------------------------------------------------------
__global__ __launch_bounds__(256) void build_vg(
    const float* __restrict__ vp, const float* __restrict__ emg,
    __nv_bfloat16* __restrict__ vgh, __nv_bfloat16* __restrict__ vgl)
{
    __shared__ float vsm[64][65];
    __shared__ float em[4][64];
    const int bh = blockIdx.y, b = bh >> 4, h = bh & 15;
    const int s0 = blockIdx.x * 64;
    const int tid = threadIdx.x;

#pragma unroll
    for (int it = 0; it < 4; it++) {
        int j = it * 256 + tid;
        int r = j >> 4, c4 = (j & 15) * 4;
        float4 v = *(const float4*)(vp + (size_t)((s0 + r) * 2 + b) * 1024 + h * 64 + c4);
        vsm[r][c4] = v.x; vsm[r][c4 + 1] = v.y; vsm[r][c4 + 2] = v.z; vsm[r][c4 + 3] = v.w;
    }
    {
        int g = tid >> 6, si = tid & 63;
        em[g][si] = emg[b * 4096 + g * 1024 + s0 + si];
    }
    __syncthreads();

    const int w = tid >> 5, lane = tid & 31;
#pragma unroll 4
    for (int rr = 0; rr < 32; rr++) {
        int gd = rr * 8 + w;
        int g = gd >> 6, d = gd & 63;
        float v0 = em[g][lane * 2] * vsm[lane * 2][d];
        float v1 = em[g][lane * 2 + 1] * vsm[lane * 2 + 1][d];
        float h0 = bhi(v0), h1 = bhi(v1);
        size_t o = ((size_t)bh * 262144 + (size_t)gd * 1024 + s0 + lane * 2) >> 1;
        ((uint32_t*)vgh)[o] = pk2(h0, h1);
        ((uint32_t*)vgl)[o] = pk2(v0 - h0, v1 - h1);
    }
}

// ---------------------------------------------------------------------------
extern "C" void kernel_launch(void* const* d_in, const int* in_sizes, int n_in,
                              void* d_out, int out_size)
{
    const float* query = (const float*)d_in[0];
    const float* key   = (const float*)d_in[1];
    const unsigned char* kpm = (const unsigned char*)d_in[2];
    const float* gmask = (const float*)d_in[3];
    const float* Wq = (const float*)d_in[4];
    const float* bq = (const float*)d_in[5];
    const float* Wk = (const float*)d_in[6];
    const float* bk = (const float*)d_in[7];
    const float* Wv = (const float*)d_in[8];
    const float* bv = (const float*)d_in[9];
    const float* Wo = (const float*)d_in[10];
    const float* bo = (const float*)d_in[11];

    float* out_proj = (float*)d_out;
    float* prob_out = (float*)d_out + (size_t)4 * 1024 * 2 * 1024;

    __nv_bfloat16 *qin_h, *qin_l, *kin_h, *kin_l;
    __nv_bfloat16 *wq_h, *wq_l, *wk_h, *wk_l, *wv_h, *wv_l, *wo_h, *wo_l;
    __nv_bfloat16 *qp_h, *qp_l, *kp_h, *kp_l, *E_h, *E_l, *vgt_h, *vgt_l, *aO_h, *aO_l;
    float *vp, *qkbuf, *rZ, *emg;
    cudaGetSymbolAddress((void**)&qin_h, g_qin_h); cudaGetSymbolAddress((void**)&qin_l, g_qin_l);
    cudaGetSymbolAddress((void**)&kin_h, g_kin_h); cudaGetSymbolAddress((void**)&kin_l, g_kin_l);
    cudaGetSymbolAddress((void**)&wq_h, g_wq_h); cudaGetSymbolAddress((void**)&wq_l, g_wq_l);
    cudaGetSymbolAddress((void**)&wk_h, g_wk_h); cudaGetSymbolAddress((void**)&wk_l, g_wk_l);
    cudaGetSymbolAddress((void**)&wv_h, g_wv_h); cudaGetSymbolAddress((void**)&wv_l, g_wv_l);
    cudaGetSymbolAddress((void**)&wo_h, g_wo_h); cudaGetSymbolAddress((void**)&wo_l, g_wo_l);
    cudaGetSymbolAddress((void**)&qp_h, g_qp_h); cudaGetSymbolAddress((void**)&qp_l, g_qp_l);
    cudaGetSymbolAddress((void**)&kp_h, g_kp_h); cudaGetSymbolAddress((void**)&kp_l, g_kp_l);
    cudaGetSymbolAddress((void**)&vp, g_vp);
    cudaGetSymbolAddress((void**)&qkbuf, g_qk);
    cudaGetSymbolAddress((void**)&E_h, g_E_h); cudaGetSymbolAddress((void**)&E_l, g_E_l);
    cudaGetSymbolAddress((void**)&rZ, g_rZ);
    cudaGetSymbolAddress((void**)&emg, g_emg);
    cudaGetSymbolAddress((void**)&vgt_h, g_vgt_h); cudaGetSymbolAddress((void**)&vgt_l, g_vgt_l);
    cudaGetSymbolAddress((void**)&aO_h, g_aO_h); cudaGetSymbolAddress((void**)&aO_l, g_aO_l);

    cudaFuncSetAttribute(gemm_qkv, cudaFuncAttributeMaxDynamicSharedMemorySize, GEMM_SMEM);
    cudaFuncSetAttribute(gemm_k<2>, cudaFuncAttributeMaxDynamicSharedMemorySize, GEMM_SMEM);
    cudaFuncSetAttribute(gemm_k<3>, cudaFuncAttributeMaxDynamicSharedMemorySize, GEMM_SMEM);
    cudaFuncSetAttribute(gemm_k<4>, cudaFuncAttributeMaxDynamicSharedMemorySize, GEMM_SMEM);

    // lazily-created side stream + fork/join events (created once; the
    // captured work is identical on every call)
    static cudaStream_t s2 = nullptr;
    static cudaEvent_t evFork = nullptr, evVg = nullptr, evJoin = nullptr;
    if (!s2) {
        cudaStreamCreateWithFlags(&s2, cudaStreamNonBlocking);
        cudaEventCreateWithFlags(&evFork, cudaEventDisableTiming);
        cudaEventCreateWithFlags(&evVg, cudaEventDisableTiming);
        cudaEventCreateWithFlags(&evJoin, cudaEventDisableTiming);
    }

    SplitArgs sa;
    sa.src[0] = query; sa.h[0] = qin_h; sa.l[0] = qin_l;
    sa.src[1] = key;   sa.h[1] = kin_h; sa.l[1] = kin_l;
    sa.src[2] = Wq;    sa.h[2] = wq_h;  sa.l[2] = wq_l;
    sa.src[3] = Wk;    sa.h[3] = wk_h;  sa.l[3] = wk_l;
    sa.src[4] = Wv;    sa.h[4] = wv_h;  sa.l[4] = wv_l;
    sa.src[5] = Wo;    sa.h[5] = wo_h;  sa.l[5] = wo_l;
    sa.end[0] = 524288; sa.end[1] = 1048576;
    sa.end[2] = 1310720; sa.end[3] = 1572864;
    sa.end[4] = 1835008; sa.end[5] = 2097152;
    split_all_kernel<<<2097152 / 256, 256>>>(sa);
    prep_em<<<32, 256>>>(gmask, kpm, emg);

    QKVArgs qa;
    qa.qh = qin_h; qa.ql = qin_l; qa.kh = kin_h; qa.kl = kin_l;
    qa.wqh = wq_h; qa.wql = wq_l; qa.wkh = wk_h; qa.wkl = wk_l;
    qa.wvh = wv_h; qa.wvl = wv_l;
    qa.bq = bq; qa.bk = bk; qa.bv = bv;
    qa.qph = qp_h; qa.qpl = qp_l; qa.kph = kp_h; qa.kpl = kp_l;
    qa.vp = vp;
    gemm_qkv<<<dim3(8, 16, 3), 256, GEMM_SMEM>>>(qa);

    // fork: half-1 chain on s2, half-0 chain on default stream
    cudaEventRecord(evFork, 0);
    cudaStreamWaitEvent(s2, evFork, 0);

    // s2: build_vg then half-1 chain
    build_vg<<<dim3(16, 32), 256, 0, s2>>>(vp, emg, vgt_h, vgt_l);
    cudaEventRecord(evVg, s2);
    gemm_k<2><<<dim3(8, 8, 16), 256, GEMM_SMEM, s2>>>(qp_h, qp_l, kp_h, kp_l,
        nullptr, nullptr, qkbuf, nullptr, nullptr, 2, 16);
    softmax_kernel<<<dim3(128, 16), 256, 0, s2>>>(qkbuf, emg, prob_out,
                                                  E_h, E_l, rZ, 16);
    gemm_k<3><<<dim3(2, 8, 16), 256, GEMM_SMEM, s2>>>(E_h, E_l, vgt_h, vgt_l,
        nullptr, rZ, nullptr, aO_h, aO_l, 32, 16);
    cudaEventRecord(evJoin, s2);

    // default stream: half-0 chain
    gemm_k<2><<<dim3(8, 8, 16), 256, GEMM_SMEM>>>(qp_h, qp_l, kp_h, kp_l,
        nullptr, nullptr, qkbuf, nullptr, nullptr, 2, 0);
    softmax_kernel<<<dim3(128, 16), 256>>>(qkbuf, emg, prob_out, E_h, E_l,
                                           rZ, 0);
    cudaStreamWaitEvent(0, evVg, 0);
    gemm_k<3><<<dim3(2, 8, 16), 256, GEMM_SMEM>>>(E_h, E_l, vgt_h, vgt_l,
        nullptr, rZ, nullptr, aO_h, aO_l, 32, 0);

    // join and final projection
    cudaStreamWaitEvent(0, evJoin, 0);
    gemm_k<4><<<dim3(8, 64, 1), 256, GEMM_SMEM>>>(aO_h, aO_l, wo_h, wo_l, bo,
        nullptr, out_proj, nullptr, nullptr, 32, 0);
}

// round 9
// speedup vs baseline: 3.4451x; 1.0627x over previous
#include <cuda_runtime.h>
#include <cuda_bf16.h>
#include <cstdint>

#define SCALING 0.125f

// ---------------------------------------------------------------------------
// helpers
// ---------------------------------------------------------------------------
__device__ __forceinline__ uint32_t s2u(const void* p) {
    uint32_t a;
    asm("{ .reg .u64 t; cvta.to.shared.u64 t, %1; cvt.u32.u64 %0, t; }"
        : "=r"(a) : "l"(p));
    return a;
}
__device__ __forceinline__ uint32_t pk2(float a, float b) {
    __nv_bfloat162 t = __floats2bfloat162_rn(a, b);
    return reinterpret_cast<uint32_t&>(t);
}
__device__ __forceinline__ float bhi(float x) {
    return __bfloat162float(__float2bfloat16(x));
}
__device__ __forceinline__ void ldsm4(uint32_t* r, uint32_t addr) {
    asm volatile("ldmatrix.sync.aligned.m8n8.x4.shared.b16 {%0,%1,%2,%3}, [%4];"
        : "=r"(r[0]), "=r"(r[1]), "=r"(r[2]), "=r"(r[3]) : "r"(addr));
}
__device__ __forceinline__ void mma_bf16(float* c, const uint32_t* a, const uint32_t* b) {
    asm volatile(
        "mma.sync.aligned.m16n8k16.row.col.f32.bf16.bf16.f32 "
        "{%0,%1,%2,%3}, {%4,%5,%6,%7}, {%8,%9}, {%0,%1,%2,%3};"
        : "+f"(c[0]), "+f"(c[1]), "+f"(c[2]), "+f"(c[3])
        : "r"(a[0]), "r"(a[1]), "r"(a[2]), "r"(a[3]), "r"(b[0]), "r"(b[1]));
}
#define SWZ(x) ((x) ^ (((x) >> 3) & 0x70))

#define CP_ASYNC16(dst, src) \
    asm volatile("cp.async.cg.shared.global [%0], [%1], 16;" :: "r"(dst), "l"(src))
#define CP_COMMIT() asm volatile("cp.async.commit_group;")
#define CP_WAIT0()  asm volatile("cp.async.wait_group 0;")
#define CP_WAIT1()  asm volatile("cp.async.wait_group 1;")
#define CP_WAIT2()  asm volatile("cp.async.wait_group 2;")

// ---------------------------------------------------------------------------
// Device scratch
// ---------------------------------------------------------------------------
__device__ __align__(16) __nv_bfloat16 g_qin_h[2048 * 1024], g_qin_l[2048 * 1024];
__device__ __align__(16) __nv_bfloat16 g_kin_h[2048 * 1024], g_kin_l[2048 * 1024];
__device__ __align__(16) __nv_bfloat16 g_wq_h[1024 * 1024], g_wq_l[1024 * 1024];
__device__ __align__(16) __nv_bfloat16 g_wk_h[1024 * 1024], g_wk_l[1024 * 1024];
__device__ __align__(16) __nv_bfloat16 g_wv_h[1024 * 1024], g_wv_l[1024 * 1024];
__device__ __align__(16) __nv_bfloat16 g_wo_h[1024 * 1024], g_wo_l[1024 * 1024];
__device__ __align__(16) __nv_bfloat16 g_qp_h[2048 * 1024], g_qp_l[2048 * 1024];
__device__ __align__(16) __nv_bfloat16 g_kp_h[2048 * 1024], g_kp_l[2048 * 1024];
__device__ __align__(16) float g_vp[2048 * 1024];
__device__ __align__(16) float g_qk[(size_t)32 * 1024 * 1024];
__device__ __align__(16) __nv_bfloat16 g_E_h[(size_t)32 * 1024 * 1024];
__device__ __align__(16) __nv_bfloat16 g_E_l[(size_t)32 * 1024 * 1024];
__device__ __align__(16) float g_rZ[32 * 4 * 1024];
__device__ __align__(16) float g_emg[2 * 4 * 1024];
__device__ __align__(16) __nv_bfloat16 g_vgt_h[32 * 256 * 1024], g_vgt_l[32 * 256 * 1024];
// attO layout: [b][g][t][d]  (b-half contiguous: 4096 rows each)
__device__ __align__(16) __nv_bfloat16 g_aO_h[8192 * 1024], g_aO_l[8192 * 1024];

// ---------------------------------------------------------------------------
// K0: fused fp32 -> bf16 hi/lo split over all 6 tensors in one launch
// ---------------------------------------------------------------------------
struct SplitArgs {
    const float* src[6];
    __nv_bfloat16* h[6];
    __nv_bfloat16* l[6];
    int end[6];
};

__global__ __launch_bounds__(256) void split_all_kernel(SplitArgs args)
{
    int i = blockIdx.x * 256 + threadIdx.x;
    int reg = 0;
#pragma unroll
    for (int r = 0; r < 5; r++) reg += (i >= args.end[r]) ? 1 : 0;
    int base = (reg == 0) ? 0 : args.end[reg - 1];
    int j = i - base;
    float4 v = ((const float4*)args.src[reg])[j];
    float h0 = bhi(v.x), h1 = bhi(v.y), h2 = bhi(v.z), h3 = bhi(v.w);
    ((uint2*)args.h[reg])[j] = make_uint2(pk2(h0, h1), pk2(h2, h3));
    ((uint2*)args.l[reg])[j] =
        make_uint2(pk2(v.x - h0, v.y - h1), pk2(v.z - h2, v.w - h3));
}

// ---------------------------------------------------------------------------
// prep: emg[b][g][s] = exp(gmask[b,g,s]) masked
// ---------------------------------------------------------------------------
__global__ __launch_bounds__(256) void prep_em(
    const float* __restrict__ gmask, const unsigned char* __restrict__ kpm,
    float* __restrict__ emg)
{
    int i = blockIdx.x * 256 + threadIdx.x;
    int b = i >> 12, s = i & 1023;
    float e = __expf(gmask[i]);
    if (kpm[b * 1024 + s]) e = 0.f;
    emg[i] = e;
}

// ---------------------------------------------------------------------------
// GEMM core: bf16x3 mma.sync, cp.async 3-stage, BK=32
// ---------------------------------------------------------------------------
#define GEMM_SMEM 98304

__device__ __forceinline__ void gemm_core(
    const __nv_bfloat16* __restrict__ Ah, const __nv_bfloat16* __restrict__ Al,
    const __nv_bfloat16* __restrict__ Bh, const __nv_bfloat16* __restrict__ Bl,
    size_t a_base, int a_str, size_t b_base, int b_str,
    int Kchunks, uint32_t sbase, int tid, int wm, int wn,
    float acc[4][4][4])
{
    const int lane = tid & 31;
    const int a_r  = lane & 15;
    const int a_kb = (lane >> 4) * 16;
    const int b_r  = (lane & 7) + ((lane >> 4) & 1) * 8;
    const int b_kb = ((lane >> 3) & 1) * 16;

#define ISSUE(kc, st) do {                                                     \
    const int _k0 = (kc) * 32;                                                 \
    _Pragma("unroll")                                                          \
    for (int it = 0; it < 8; it++) {                                           \
        int j = it * 256 + tid;                                                \
        int buf = j >> 10;                                                     \
        int r = (j >> 3) & 127;                                                \
        int ch = j & 7;                                                        \
        const __nv_bfloat16* src = buf ? (ch < 4 ? Bh : Bl)                    \
                                       : (ch < 4 ? Ah : Al);                   \
        size_t bs = buf ? b_base : a_base;                                     \
        int strd = buf ? b_str : a_str;                                        \
        uint32_t d = sbase + (st) * 32768 + buf * 16384 + SWZ(r * 128 + ch * 16);\
        CP_ASYNC16(d, src + bs + _k0 + (size_t)r * strd + (ch & 3) * 8);       \
    }                                                                          \
    CP_COMMIT();                                                               \
} while (0)

    ISSUE(0, 0);
    if (Kchunks > 1) ISSUE(1, 1);

    for (int kc = 0; kc < Kchunks; kc++) {
        const int st = kc % 3;
        if (kc + 2 < Kchunks) {
            ISSUE(kc + 2, (kc + 2) % 3);
            CP_WAIT2();
        } else if (kc + 1 < Kchunks) {
            CP_WAIT1();
        } else {
            CP_WAIT0();
        }
        __syncthreads();

        const uint32_t sA = sbase + st * 32768;
        const uint32_t sB = sA + 16384;

#pragma unroll
        for (int ks = 0; ks < 2; ks++) {
            const int kbb = ks * 32;
            uint32_t ah[4][4], bb[2][4];
#pragma unroll
            for (int mi = 0; mi < 4; mi++)
                ldsm4(ah[mi], sA + SWZ((wm + 16 * mi + a_r) * 128 + kbb + a_kb));
#pragma unroll
            for (int jj = 0; jj < 2; jj++)
                ldsm4(bb[jj], sB + SWZ((wn + 16 * jj + b_r) * 128 + kbb + b_kb));
#pragma unroll
            for (int mi = 0; mi < 4; mi++)
#pragma unroll
                for (int nj = 0; nj < 4; nj++)
                    mma_bf16(acc[mi][nj], ah[mi], &bb[nj >> 1][(nj & 1) * 2]);
#pragma unroll
            for (int mi = 0; mi < 4; mi++) {
                uint32_t al[4];
                ldsm4(al, sA + SWZ((wm + 16 * mi + a_r) * 128 + 64 + kbb + a_kb));
#pragma unroll
                for (int nj = 0; nj < 4; nj++)
                    mma_bf16(acc[mi][nj], al, &bb[nj >> 1][(nj & 1) * 2]);
            }
#pragma unroll
            for (int jj = 0; jj < 2; jj++)
                ldsm4(bb[jj], sB + SWZ((wn + 16 * jj + b_r) * 128 + 64 + kbb + b_kb));
#pragma unroll
            for (int mi = 0; mi < 4; mi++)
#pragma unroll
                for (int nj = 0; nj < 4; nj++)
                    mma_bf16(acc[mi][nj], ah[mi], &bb[nj >> 1][(nj & 1) * 2]);
        }
        __syncthreads();
    }
#undef ISSUE
}

// ---------------------------------------------------------------------------
// fused Q/K/V projection GEMM: z = 0:Q, 1:K, 2:V
// ---------------------------------------------------------------------------
struct QKVArgs {
    const __nv_bfloat16 *qh, *ql, *kh, *kl;
    const __nv_bfloat16 *wqh, *wql, *wkh, *wkl, *wvh, *wvl;
    const float *bq, *bk, *bv;
    __nv_bfloat16 *qph, *qpl, *kph, *kpl;
    float *vp;
};

__global__ __launch_bounds__(256, 2) void gemm_qkv(QKVArgs a)
{
    extern __shared__ __align__(1024) char smem[];
    const uint32_t sbase = s2u(smem);
    const int tid = threadIdx.x;
    const int wid = tid >> 5, lane = tid & 31;
    const int m0 = blockIdx.y * 128, n0 = blockIdx.x * 128;
    const int z = blockIdx.z;

    const __nv_bfloat16* Ah = (z == 0) ? a.qh : a.kh;
    const __nv_bfloat16* Al = (z == 0) ? a.ql : a.kl;
    const __nv_bfloat16* Bh = (z == 0) ? a.wqh : (z == 1) ? a.wkh : a.wvh;
    const __nv_bfloat16* Bl = (z == 0) ? a.wql : (z == 1) ? a.wkl : a.wvl;
    const float* bias = (z == 0) ? a.bq : (z == 1) ? a.bk : a.bv;
    const float scale = (z == 0) ? SCALING : 1.0f;

    const int wm = (wid >> 2) * 64, wn = (wid & 3) * 32;

    float acc[4][4][4];
#pragma unroll
    for (int i = 0; i < 4; i++)
#pragma unroll
        for (int j = 0; j < 4; j++)
#pragma unroll
            for (int e = 0; e < 4; e++) acc[i][j][e] = 0.f;

    gemm_core(Ah, Al, Bh, Bl, (size_t)m0 * 1024, 1024, (size_t)n0 * 1024, 1024,
              32, sbase, tid, wm, wn, acc);

    const int tr = lane >> 2, tc2 = (lane & 3) * 2;
#pragma unroll
    for (int mi = 0; mi < 4; mi++) {
#pragma unroll
        for (int nj = 0; nj < 4; nj++) {
            int n = n0 + wn + 8 * nj + tc2;
#pragma unroll
            for (int hr = 0; hr < 2; hr++) {
                int m = m0 + wm + 16 * mi + tr + hr * 8;
                float v0 = acc[mi][nj][hr * 2 + 0];
                float v1 = acc[mi][nj][hr * 2 + 1];
                if (z < 2) {
                    float y0 = (v0 + bias[n]) * scale, y1 = (v1 + bias[n + 1]) * scale;
                    float h0 = bhi(y0), h1 = bhi(y1);
                    size_t o = ((size_t)m * 1024 + n) >> 1;
                    __nv_bfloat16* Ch = (z == 0) ? a.qph : a.kph;
                    __nv_bfloat16* Cl = (z == 0) ? a.qpl : a.kpl;
                    ((uint32_t*)Ch)[o] = pk2(h0, h1);
                    ((uint32_t*)Cl)[o] = pk2(y0 - h0, y1 - h1);
                } else {
                    *(float2*)(a.vp + (size_t)m * 1024 + n) =
                        make_float2(v0 + bias[n], v1 + bias[n + 1]);
                }
            }
        }
    }
}

// ---------------------------------------------------------------------------
// generic GEMM: MODE 2 qk, 3 pv, 4 oproj
// MODE 2/3: zbase = bh offset.  MODE 4: zbase = b (half), M = 4096 rows.
// ---------------------------------------------------------------------------
template <int MODE>
__global__ __launch_bounds__(256, 2) void gemm_k(
    const __nv_bfloat16* __restrict__ Ah, const __nv_bfloat16* __restrict__ Al,
    const __nv_bfloat16* __restrict__ Bh, const __nv_bfloat16* __restrict__ Bl,
    const float* __restrict__ bias, const float* __restrict__ rZ,
    float* __restrict__ Cf, __nv_bfloat16* __restrict__ Ch,
    __nv_bfloat16* __restrict__ Cl, int Kchunks, int zbase)
{
    extern __shared__ __align__(1024) char smem[];
    const uint32_t sbase = s2u(smem);
    const int tid = threadIdx.x;
    const int wid = tid >> 5, lane = tid & 31;
    const int m0 = blockIdx.y * 128, n0 = blockIdx.x * 128;
    const int z = blockIdx.z + zbase;
    const int zb = z >> 4, zh = z & 15;

    size_t a_base, b_base;
    int a_str, b_str;
    if (MODE == 2) {
        a_base = (size_t)m0 * 2048 + zb * 1024 + zh * 64; a_str = 2048;
        b_base = (size_t)n0 * 2048 + zb * 1024 + zh * 64; b_str = 2048;
    } else if (MODE == 3) {
        a_base = ((size_t)z << 20) + (size_t)m0 * 1024; a_str = 1024;
        b_base = (size_t)z * 262144 + (size_t)n0 * 1024; b_str = 1024;
    } else {
        // A rows: [zbase*4096 + m0 ...], K = 1024
        a_base = ((size_t)zbase * 4096 + m0) * 1024; a_str = 1024;
        b_base = (size_t)n0 * 1024; b_str = 1024;
    }

    const int wm = (wid >> 2) * 64, wn = (wid & 3) * 32;

    float acc[4][4][4];
#pragma unroll
    for (int i = 0; i < 4; i++)
#pragma unroll
        for (int j = 0; j < 4; j++)
#pragma unroll
            for (int e = 0; e < 4; e++) acc[i][j][e] = 0.f;

    gemm_core(Ah, Al, Bh, Bl, a_base, a_str, b_base, b_str,
              Kchunks, sbase, tid, wm, wn, acc);

    const int tr = lane >> 2, tc2 = (lane & 3) * 2;
#pragma unroll
    for (int mi = 0; mi < 4; mi++) {
#pragma unroll
        for (int nj = 0; nj < 4; nj++) {
            int n = n0 + wn + 8 * nj + tc2;
#pragma unroll
            for (int hr = 0; hr < 2; hr++) {
                int m = m0 + wm + 16 * mi + tr + hr * 8;
                float v0 = acc[mi][nj][hr * 2 + 0];
                float v1 = acc[mi][nj][hr * 2 + 1];
                if (MODE == 2) {
                    *(float2*)(Cf + ((size_t)z << 20) + (size_t)m * 1024 + n) =
                        make_float2(v0, v1);
                } else if (MODE == 3) {
                    // attO[b][g][t][d]: row = zb*4096 + g*1024 + m
                    int g = n >> 6, d = n & 63;
                    float rz = rZ[z * 4096 + g * 1024 + m];
                    float y0 = v0 * rz, y1 = v1 * rz;
                    float h0 = bhi(y0), h1 = bhi(y1);
                    size_t o = ((((size_t)zb * 4096 + g * 1024 + m) << 10)
                                + zh * 64 + d) >> 1;
                    ((uint32_t*)Ch)[o] = pk2(h0, h1);
                    ((uint32_t*)Cl)[o] = pk2(y0 - h0, y1 - h1);
                } else {
                    // out row (G,T,B): 2*m + b
                    __stcs((float2*)(Cf + ((size_t)(2 * m + zbase) << 10) + n),
                           make_float2(v0 + bias[n], v1 + bias[n + 1]));
                }
            }
        }
    }
}

// ---------------------------------------------------------------------------
// K3: softmax — warp-per-row, row in registers; streaming hints
// ---------------------------------------------------------------------------
__global__ __launch_bounds__(256) void softmax_kernel(
    const float* __restrict__ qk, const float* __restrict__ emg,
    float* __restrict__ prob_out,
    __nv_bfloat16* __restrict__ Eh, __nv_bfloat16* __restrict__ El,
    float* __restrict__ rZg, int bh_base)
{
    __shared__ __align__(16) float em[4][1024];

    const int tid = threadIdx.x, wid = tid >> 5, lane = tid & 31;
    const int bh = blockIdx.y + bh_base, b = bh >> 4;
    const int t = blockIdx.x * 8 + wid;

    for (int i = tid; i < 1024; i += 256)
        ((float4*)&em[0][0])[i] = ((const float4*)(emg + b * 4096))[i];
    __syncthreads();

    const float* row = qk + ((size_t)bh << 20) + (size_t)t * 1024;
    float e[32];
#pragma unroll
    for (int j = 0; j < 8; j++) {
        float4 v = __ldcs((const float4*)(row + j * 128 + lane * 4));
        e[4 * j] = v.x; e[4 * j + 1] = v.y; e[4 * j + 2] = v.z; e[4 * j + 3] = v.w;
    }

    float mx = -1e30f;
#pragma unroll
    for (int i = 0; i < 32; i++) mx = fmaxf(mx, e[i]);
#pragma unroll
    for (int o = 16; o; o >>= 1) mx = fmaxf(mx, __shfl_xor_sync(0xffffffffu, mx, o));

#pragma unroll
    for (int i = 0; i < 32; i++) e[i] = __expf(e[i] - mx);

    float z[4] = {0.f, 0.f, 0.f, 0.f};
#pragma unroll
    for (int g = 0; g < 4; g++) {
#pragma unroll
        for (int j = 0; j < 8; j++) {
            float4 m = *(const float4*)&em[g][j * 128 + lane * 4];
            z[g] = fmaf(e[4 * j], m.x, z[g]);
            z[g] = fmaf(e[4 * j + 1], m.y, z[g]);
            z[g] = fmaf(e[4 * j + 2], m.z, z[g]);
            z[g] = fmaf(e[4 * j + 3], m.w, z[g]);
        }
    }
#pragma unroll
    for (int o = 16; o; o >>= 1) {
#pragma unroll
        for (int g = 0; g < 4; g++)
            z[g] += __shfl_xor_sync(0xffffffffu, z[g], o);
    }
    float rz[4];
#pragma unroll
    for (int g = 0; g < 4; g++) rz[g] = 1.f / z[g];
    if (lane < 4) rZg[bh * 4096 + lane * 1024 + t] = rz[lane];

    const size_t ebase = ((size_t)bh << 20) + (size_t)t * 1024;
#pragma unroll
    for (int j = 0; j < 8; j++) {
        float h0 = bhi(e[4 * j]), h1 = bhi(e[4 * j + 1]);
        float h2 = bhi(e[4 * j + 2]), h3 = bhi(e[4 * j + 3]);
        size_t o = (ebase + j * 128 + lane * 4) >> 2;
        ((uint2*)Eh)[o] = make_uint2(pk2(h0, h1), pk2(h2, h3));
        ((uint2*)El)[o] = make_uint2(pk2(e[4 * j] - h0, e[4 * j + 1] - h1),
                                     pk2(e[4 * j + 2] - h2, e[4 * j + 3] - h3));
    }

#pragma unroll
    for (int g = 0; g < 4; g++) {
        float* pout = prob_out + (((size_t)(bh * 4 + g) << 10) + t) * 1024;
        float rzg = rz[g];
#pragma unroll
        for (int j = 0; j < 8; j++) {
            float4 m = *(const float4*)&em[g][j * 128 + lane * 4];
            float4 o;
            o.x = e[4 * j] * m.x * rzg;
            o.y = e[4 * j + 1] * m.y * rzg;
            o.z = e[4 * j + 2] * m.z * rzg;
            o.w = e[4 * j + 3] * m.w * rzg;
            __stcs((float4*)(pout + j * 128 + lane * 4), o);
        }
    }
}

// ---------------------------------------------------------------------------
// K3b: vgt[bh][(g*64+d)][s] = emg[b,g,s] * V[s,b,h,d]   (hi/lo bf16)
// ---------------------------------------------------------------------------
__global__ __launch_bounds__(256) void build_vg(
    const float* __restrict__ vp, const float* __restrict__ emg,
    __nv_bfloat16* __restrict__ vgh, __nv_bfloat16* __restrict__ vgl)
{
    __shared__ float vsm[64][65];
    __shared__ float em[4][64];
    const int bh = blockIdx.y, b = bh >> 4, h = bh & 15;
    const int s0 = blockIdx.x * 64;
    const int tid = threadIdx.x;

#pragma unroll
    for (int it = 0; it < 4; it++) {
        int j = it * 256 + tid;
        int r = j >> 4, c4 = (j & 15) * 4;
        float4 v = *(const float4*)(vp + (size_t)((s0 + r) * 2 + b) * 1024 + h * 64 + c4);
        vsm[r][c4] = v.x; vsm[r][c4 + 1] = v.y; vsm[r][c4 + 2] = v.z; vsm[r][c4 + 3] = v.w;
    }
    {
        int g = tid >> 6, si = tid & 63;
        em[g][si] = emg[b * 4096 + g * 1024 + s0 + si];
    }
    __syncthreads();

    const int w = tid >> 5, lane = tid & 31;
#pragma unroll 4
    for (int rr = 0; rr < 32; rr++) {
        int gd = rr * 8 + w;
        int g = gd >> 6, d = gd & 63;
        float v0 = em[g][lane * 2] * vsm[lane * 2][d];
        float v1 = em[g][lane * 2 + 1] * vsm[lane * 2 + 1][d];
        float h0 = bhi(v0), h1 = bhi(v1);
        size_t o = ((size_t)bh * 262144 + (size_t)gd * 1024 + s0 + lane * 2) >> 1;
        ((uint32_t*)vgh)[o] = pk2(h0, h1);
        ((uint32_t*)vgl)[o] = pk2(v0 - h0, v1 - h1);
    }
}

// ---------------------------------------------------------------------------
extern "C" void kernel_launch(void* const* d_in, const int* in_sizes, int n_in,
                              void* d_out, int out_size)
{
    const float* query = (const float*)d_in[0];
    const float* key   = (const float*)d_in[1];
    const unsigned char* kpm = (const unsigned char*)d_in[2];
    const float* gmask = (const float*)d_in[3];
    const float* Wq = (const float*)d_in[4];
    const float* bq = (const float*)d_in[5];
    const float* Wk = (const float*)d_in[6];
    const float* bk = (const float*)d_in[7];
    const float* Wv = (const float*)d_in[8];
    const float* bv = (const float*)d_in[9];
    const float* Wo = (const float*)d_in[10];
    const float* bo = (const float*)d_in[11];

    float* out_proj = (float*)d_out;
    float* prob_out = (float*)d_out + (size_t)4 * 1024 * 2 * 1024;

    __nv_bfloat16 *qin_h, *qin_l, *kin_h, *kin_l;
    __nv_bfloat16 *wq_h, *wq_l, *wk_h, *wk_l, *wv_h, *wv_l, *wo_h, *wo_l;
    __nv_bfloat16 *qp_h, *qp_l, *kp_h, *kp_l, *E_h, *E_l, *vgt_h, *vgt_l, *aO_h, *aO_l;
    float *vp, *qkbuf, *rZ, *emg;
    cudaGetSymbolAddress((void**)&qin_h, g_qin_h); cudaGetSymbolAddress((void**)&qin_l, g_qin_l);
    cudaGetSymbolAddress((void**)&kin_h, g_kin_h); cudaGetSymbolAddress((void**)&kin_l, g_kin_l);
    cudaGetSymbolAddress((void**)&wq_h, g_wq_h); cudaGetSymbolAddress((void**)&wq_l, g_wq_l);
    cudaGetSymbolAddress((void**)&wk_h, g_wk_h); cudaGetSymbolAddress((void**)&wk_l, g_wk_l);
    cudaGetSymbolAddress((void**)&wv_h, g_wv_h); cudaGetSymbolAddress((void**)&wv_l, g_wv_l);
    cudaGetSymbolAddress((void**)&wo_h, g_wo_h); cudaGetSymbolAddress((void**)&wo_l, g_wo_l);
    cudaGetSymbolAddress((void**)&qp_h, g_qp_h); cudaGetSymbolAddress((void**)&qp_l, g_qp_l);
    cudaGetSymbolAddress((void**)&kp_h, g_kp_h); cudaGetSymbolAddress((void**)&kp_l, g_kp_l);
    cudaGetSymbolAddress((void**)&vp, g_vp);
    cudaGetSymbolAddress((void**)&qkbuf, g_qk);
    cudaGetSymbolAddress((void**)&E_h, g_E_h); cudaGetSymbolAddress((void**)&E_l, g_E_l);
    cudaGetSymbolAddress((void**)&rZ, g_rZ);
    cudaGetSymbolAddress((void**)&emg, g_emg);
    cudaGetSymbolAddress((void**)&vgt_h, g_vgt_h); cudaGetSymbolAddress((void**)&vgt_l, g_vgt_l);
    cudaGetSymbolAddress((void**)&aO_h, g_aO_h); cudaGetSymbolAddress((void**)&aO_l, g_aO_l);

    cudaFuncSetAttribute(gemm_qkv, cudaFuncAttributeMaxDynamicSharedMemorySize, GEMM_SMEM);
    cudaFuncSetAttribute(gemm_k<2>, cudaFuncAttributeMaxDynamicSharedMemorySize, GEMM_SMEM);
    cudaFuncSetAttribute(gemm_k<3>, cudaFuncAttributeMaxDynamicSharedMemorySize, GEMM_SMEM);
    cudaFuncSetAttribute(gemm_k<4>, cudaFuncAttributeMaxDynamicSharedMemorySize, GEMM_SMEM);

    static cudaStream_t s2 = nullptr;
    static cudaEvent_t evFork = nullptr, evVg = nullptr, evJoin = nullptr;
    if (!s2) {
        cudaStreamCreateWithFlags(&s2, cudaStreamNonBlocking);
        cudaEventCreateWithFlags(&evFork, cudaEventDisableTiming);
        cudaEventCreateWithFlags(&evVg, cudaEventDisableTiming);
        cudaEventCreateWithFlags(&evJoin, cudaEventDisableTiming);
    }

    SplitArgs sa;
    sa.src[0] = query; sa.h[0] = qin_h; sa.l[0] = qin_l;
    sa.src[1] = key;   sa.h[1] = kin_h; sa.l[1] = kin_l;
    sa.src[2] = Wq;    sa.h[2] = wq_h;  sa.l[2] = wq_l;
    sa.src[3] = Wk;    sa.h[3] = wk_h;  sa.l[3] = wk_l;
    sa.src[4] = Wv;    sa.h[4] = wv_h;  sa.l[4] = wv_l;
    sa.src[5] = Wo;    sa.h[5] = wo_h;  sa.l[5] = wo_l;
    sa.end[0] = 524288; sa.end[1] = 1048576;
    sa.end[2] = 1310720; sa.end[3] = 1572864;
    sa.end[4] = 1835008; sa.end[5] = 2097152;
    split_all_kernel<<<2097152 / 256, 256>>>(sa);
    prep_em<<<32, 256>>>(gmask, kpm, emg);

    QKVArgs qa;
    qa.qh = qin_h; qa.ql = qin_l; qa.kh = kin_h; qa.kl = kin_l;
    qa.wqh = wq_h; qa.wql = wq_l; qa.wkh = wk_h; qa.wkl = wk_l;
    qa.wvh = wv_h; qa.wvl = wv_l;
    qa.bq = bq; qa.bk = bk; qa.bv = bv;
    qa.qph = qp_h; qa.qpl = qp_l; qa.kph = kp_h; qa.kpl = kp_l;
    qa.vp = vp;
    gemm_qkv<<<dim3(8, 16, 3), 256, GEMM_SMEM>>>(qa);

    // fork
    cudaEventRecord(evFork, 0);
    cudaStreamWaitEvent(s2, evFork, 0);

    // s2: build_vg then half-1 chain (b=1, bh 16..31) + oproj(b=1)
    build_vg<<<dim3(16, 32), 256, 0, s2>>>(vp, emg, vgt_h, vgt_l);
    cudaEventRecord(evVg, s2);
    gemm_k<2><<<dim3(8, 8, 16), 256, GEMM_SMEM, s2>>>(qp_h, qp_l, kp_h, kp_l,
        nullptr, nullptr, qkbuf, nullptr, nullptr, 2, 16);
    softmax_kernel<<<dim3(128, 16), 256, 0, s2>>>(qkbuf, emg, prob_out,
                                                  E_h, E_l, rZ, 16);
    gemm_k<3><<<dim3(2, 8, 16), 256, GEMM_SMEM, s2>>>(E_h, E_l, vgt_h, vgt_l,
        nullptr, rZ, nullptr, aO_h, aO_l, 32, 16);
    gemm_k<4><<<dim3(8, 32, 1), 256, GEMM_SMEM, s2>>>(aO_h, aO_l, wo_h, wo_l,
        bo, nullptr, out_proj, nullptr, nullptr, 32, 1);
    cudaEventRecord(evJoin, s2);

    // default stream: half-0 chain (b=0, bh 0..15) + oproj(b=0)
    gemm_k<2><<<dim3(8, 8, 16), 256, GEMM_SMEM>>>(qp_h, qp_l, kp_h, kp_l,
        nullptr, nullptr, qkbuf, nullptr, nullptr, 2, 0);
    softmax_kernel<<<dim3(128, 16), 256>>>(qkbuf, emg, prob_out, E_h, E_l,
                                           rZ, 0);
    cudaStreamWaitEvent(0, evVg, 0);
    gemm_k<3><<<dim3(2, 8, 16), 256, GEMM_SMEM>>>(E_h, E_l, vgt_h, vgt_l,
        nullptr, rZ, nullptr, aO_h, aO_l, 32, 0);
    gemm_k<4><<<dim3(8, 32, 1), 256, GEMM_SMEM>>>(aO_h, aO_l, wo_h, wo_l,
        bo, nullptr, out_proj, nullptr, nullptr, 32, 0);

    // join
    cudaStreamWaitEvent(0, evJoin, 0);
}